// round 7
// baseline (speedup 1.0000x reference)
#include <cuda_runtime.h>
#include <cuda_fp16.h>
#include <cstdint>
#include <cstddef>

#define BATCH 4
#define NQ    2048
#define NK    2048
#define EMB   512
#define NH    8
#define HD    64
#define NTOK  (BATCH * NQ)
#define BHN   (BATCH * NH)

// ---------------- device-global scratch (halves) ------------------------------
__device__ __half g_qn [NTOK * EMB];
__device__ __half g_kvn[NTOK * EMB];
__device__ __half g_q  [NTOK * EMB];          // pre-scaled by 0.125
__device__ __half g_k  [NTOK * EMB];
__device__ __half g_vt [BHN * HD * NK];       // V^T per (b,h): [d][key]
__device__ __half g_ctx[NTOK * EMB];
__device__ __half g_wt [4 * EMB * EMB];       // W^T, k-major rows
__device__ unsigned long long g_mbits[(size_t)BATCH * NQ * (NK / 64)];
__device__ int g_is_byte[2];

// ---------------- PTX helpers --------------------------------------------------
__device__ __forceinline__ uint32_t sptr(const void* p) {
    uint32_t a;
    asm("{ .reg .u64 t; cvta.to.shared.u64 t, %1; cvt.u32.u64 %0, t; }"
        : "=r"(a) : "l"(p));
    return a;
}

#define MMA_F16(C, A, B) \
    asm volatile( \
        "mma.sync.aligned.m16n8k16.row.col.f32.f16.f16.f32 " \
        "{%0,%1,%2,%3}, {%4,%5,%6,%7}, {%8,%9}, {%0,%1,%2,%3};" \
        : "+f"((C)[0]), "+f"((C)[1]), "+f"((C)[2]), "+f"((C)[3]) \
        : "r"((A)[0]), "r"((A)[1]), "r"((A)[2]), "r"((A)[3]), \
          "r"((B)[0]), "r"((B)[1]))

#define LDSM4(R0, R1, R2, R3, ADDR) \
    asm volatile("ldmatrix.sync.aligned.m8n8.x4.shared.b16 {%0,%1,%2,%3}, [%4];" \
        : "=r"(R0), "=r"(R1), "=r"(R2), "=r"(R3) : "r"(ADDR))

#define CP16(DST, SRC) \
    asm volatile("cp.async.cg.shared.global [%0], [%1], 16;" \
        :: "r"(DST), "l"(SRC))
#define CP_COMMIT() asm volatile("cp.async.commit_group;" ::: "memory")
#define CP_WAIT0()  asm volatile("cp.async.wait_group 0;" ::: "memory")

// ---------------- fp16 GEMM mainloop: C[128x128] = A[128,512] @ B[128,512]^T ---
// 256 threads, 8 warps (4M x 2N); warp tile 32x64; BK=32 (2 k16 steps/chunk).
// Fragment loads via ldmatrix.x4 (row strides 80B: 8 rows hit 8 distinct 16B banks).
__device__ __forceinline__ void gemm16_mainloop(
        const __half* __restrict__ A, const __half* __restrict__ B,
        float (&c)[2][8][4]) {
    __shared__ __align__(16) __half As[128][40];
    __shared__ __align__(16) __half Bs[128][40];
    const int tid = threadIdx.x;
    const int lane = tid & 31, wid = tid >> 5;
    const int wm = wid & 3, wn = wid >> 2;

    #pragma unroll
    for (int mt = 0; mt < 2; mt++)
        #pragma unroll
        for (int nt = 0; nt < 8; nt++)
            #pragma unroll
            for (int j = 0; j < 4; j++) c[mt][nt][j] = 0.0f;

    // ldmatrix lane-base addresses
    const uint32_t a_base = sptr(&As[wm * 32 + ((lane & 8) ? 8 : 0) + (lane & 7)]
                                    [(lane & 16) ? 8 : 0]);
    const uint32_t b_base = sptr(&Bs[wn * 64 + ((lane & 16) ? 8 : 0) + (lane & 7)]
                                    [(lane & 8) ? 8 : 0]);

    uint4 pa[2], pb[2];
    #pragma unroll
    for (int i = 0; i < 2; i++) {
        int s = tid + i * 256, r = s >> 2, f = s & 3;
        pa[i] = *(const uint4*)(A + (size_t)r * EMB + f * 8);
        pb[i] = *(const uint4*)(B + (size_t)r * EMB + f * 8);
    }

    for (int ch = 0; ch < 16; ch++) {
        #pragma unroll
        for (int i = 0; i < 2; i++) {
            int s = tid + i * 256, r = s >> 2, f = s & 3;
            *(uint4*)&As[r][f * 8] = pa[i];
            *(uint4*)&Bs[r][f * 8] = pb[i];
        }
        __syncthreads();
        if (ch + 1 < 16) {
            int co = (ch + 1) * 32;
            #pragma unroll
            for (int i = 0; i < 2; i++) {
                int s = tid + i * 256, r = s >> 2, f = s & 3;
                pa[i] = *(const uint4*)(A + (size_t)r * EMB + co + f * 8);
                pb[i] = *(const uint4*)(B + (size_t)r * EMB + co + f * 8);
            }
        }
        #pragma unroll
        for (int ks = 0; ks < 2; ks++) {
            uint32_t a[2][4], b[8][2];
            #pragma unroll
            for (int mt = 0; mt < 2; mt++)
                LDSM4(a[mt][0], a[mt][1], a[mt][2], a[mt][3],
                      a_base + mt * 1280 + ks * 32);
            #pragma unroll
            for (int p = 0; p < 4; p++)
                LDSM4(b[2*p][0], b[2*p][1], b[2*p+1][0], b[2*p+1][1],
                      b_base + p * 1280 + ks * 32);
            #pragma unroll
            for (int mt = 0; mt < 2; mt++)
                #pragma unroll
                for (int nt = 0; nt < 8; nt++)
                    MMA_F16(c[mt][nt], a[mt], b[nt]);
        }
        __syncthreads();
    }
}

// Q/K/V projections in one launch. z=0: Q (scaled 0.125), z=1: K, z=2: V^T.
__global__ void __launch_bounds__(256, 2) proj_qkv_kernel(
        const __half* __restrict__ qn, const __half* __restrict__ kvn,
        const __half* __restrict__ wt,
        const float* __restrict__ bq, const float* __restrict__ bk,
        const float* __restrict__ bv,
        __half* __restrict__ q, __half* __restrict__ k,
        __half* __restrict__ vt) {
    const int z = blockIdx.z;
    const size_t bm = (size_t)blockIdx.y * 128, bn = (size_t)blockIdx.x * 128;
    const __half* A = (z == 0 ? qn : kvn) + bm * EMB;
    const __half* B = wt + (size_t)z * EMB * EMB + bn * EMB;
    float c[2][8][4];
    gemm16_mainloop(A, B, c);

    const int tid = threadIdx.x, lane = tid & 31, wid = tid >> 5;
    const int wm = wid & 3, wn = wid >> 2, g = lane >> 2, t = lane & 3;
    const float* bias = (z == 0) ? bq : (z == 1) ? bk : bv;
    const float scale = (z == 0) ? 0.125f : 1.0f;

    #pragma unroll
    for (int mt = 0; mt < 2; mt++) {
        #pragma unroll
        for (int nt = 0; nt < 8; nt++) {
            int m   = (int)bm + wm * 32 + mt * 16 + g;
            int col = (int)bn + wn * 64 + nt * 8 + 2 * t;
            float b0 = bias[col], b1 = bias[col + 1];
            float v0 = (c[mt][nt][0] + b0) * scale;
            float v1 = (c[mt][nt][1] + b1) * scale;
            float v2 = (c[mt][nt][2] + b0) * scale;
            float v3 = (c[mt][nt][3] + b1) * scale;
            if (z < 2) {
                __half* dst = (z == 0) ? q : k;
                *(half2*)(dst + (size_t)m * EMB + col) = __floats2half2_rn(v0, v1);
                *(half2*)(dst + (size_t)(m + 8) * EMB + col) = __floats2half2_rn(v2, v3);
            } else {
                int h = col >> 6, d = col & 63;
                int b_ = m >> 11;
                size_t base = ((size_t)(b_ * NH + h) * HD);
                int tok = m & 2047;
                vt[(base + d) * NK + tok]           = __float2half_rn(v0);
                vt[(base + d + 1) * NK + tok]       = __float2half_rn(v1);
                vt[(base + d) * NK + tok + 8]       = __float2half_rn(v2);
                vt[(base + d + 1) * NK + tok + 8]   = __float2half_rn(v3);
            }
        }
    }
}

// Output projection: fp32 result + bias into d_out.
__global__ void __launch_bounds__(256, 2) proj_o_kernel(
        const __half* __restrict__ ctx, const __half* __restrict__ wt,
        const float* __restrict__ bo, float* __restrict__ out) {
    const size_t bm = (size_t)blockIdx.y * 128, bn = (size_t)blockIdx.x * 128;
    float c[2][8][4];
    gemm16_mainloop(ctx + bm * EMB, wt + 3ull * EMB * EMB + bn * EMB, c);

    const int tid = threadIdx.x, lane = tid & 31, wid = tid >> 5;
    const int wm = wid & 3, wn = wid >> 2, g = lane >> 2, t = lane & 3;
    #pragma unroll
    for (int mt = 0; mt < 2; mt++) {
        #pragma unroll
        for (int nt = 0; nt < 8; nt++) {
            int m   = (int)bm + wm * 32 + mt * 16 + g;
            int col = (int)bn + wn * 64 + nt * 8 + 2 * t;
            float b0 = bo[col], b1 = bo[col + 1];
            *(float2*)(out + (size_t)m * EMB + col) =
                make_float2(c[mt][nt][0] + b0, c[mt][nt][1] + b1);
            *(float2*)(out + (size_t)(m + 8) * EMB + col) =
                make_float2(c[mt][nt][2] + b0, c[mt][nt][3] + b1);
        }
    }
}

// ---------------- fused flash attention (fp16 MMA + ldmatrix) ------------------
// Block (qt, bh): 256 threads, 8 warps; warp w owns q-rows [w*16, w*16+16).
__global__ void __launch_bounds__(256, 2) fattn_kernel(
        const __half* __restrict__ Qp, const __half* __restrict__ Kp,
        const __half* __restrict__ Vtp,
        const unsigned long long* __restrict__ mbits,
        __half* __restrict__ ctx) {
    __shared__ __align__(16) __half Ks [64][72];    // [key][d]
    __shared__ __align__(16) __half Vst[64][72];    // [d][key]
    __shared__ __align__(16) __half Ps [128][72];   // [qrow][key]

    const int tid = threadIdx.x;
    const int lane = tid & 31, w = tid >> 5;
    const int g = lane >> 2, t = lane & 3;
    const int qt = blockIdx.x, bh = blockIdx.y;
    const int b = bh >> 3, h = bh & 7;
    const int row0 = w * 16 + g, row1 = row0 + 8;

    // ldmatrix lane-base addresses (row stride 144B: 8 rows -> 8 distinct banks)
    const uint32_t k_base = sptr(&Ks[((lane & 16) ? 8 : 0) + (lane & 7)]
                                    [(lane & 8) ? 8 : 0]);
    const uint32_t v_base = sptr(&Vst[((lane & 16) ? 8 : 0) + (lane & 7)]
                                     [(lane & 8) ? 8 : 0]);
    const uint32_t p_base = sptr(&Ps[w * 16 + ((lane & 8) ? 8 : 0) + (lane & 7)]
                                    [(lane & 16) ? 8 : 0]);

    // Q fragments (already scaled by 0.125, fp16)
    uint32_t qa[4][4];
    {
        const __half* q0 = Qp + (size_t)(b * NQ + qt * 128 + row0) * EMB + h * HD;
        const __half* q1 = Qp + (size_t)(b * NQ + qt * 128 + row1) * EMB + h * HD;
        #pragma unroll
        for (int ks = 0; ks < 4; ks++) {
            qa[ks][0] = *(const uint32_t*)(q0 + ks * 16 + 2 * t);
            qa[ks][1] = *(const uint32_t*)(q1 + ks * 16 + 2 * t);
            qa[ks][2] = *(const uint32_t*)(q0 + ks * 16 + 2 * t + 8);
            qa[ks][3] = *(const uint32_t*)(q1 + ks * 16 + 2 * t + 8);
        }
    }

    float m0 = -1e30f, m1 = -1e30f, l0 = 0.0f, l1 = 0.0f;
    float acc[8][4];
    #pragma unroll
    for (int nt = 0; nt < 8; nt++)
        #pragma unroll
        for (int j = 0; j < 4; j++) acc[nt][j] = 0.0f;

    const unsigned long long* mb0 =
        mbits + ((size_t)b * NQ + qt * 128 + row0) * (NK / 64);
    const unsigned long long* mb1 =
        mbits + ((size_t)b * NQ + qt * 128 + row1) * (NK / 64);

    const __half* Kbase  = Kp + ((size_t)b * NK) * EMB + h * HD;
    const __half* Vtbase = Vtp + (size_t)bh * HD * NK;

    for (int kt = 0; kt < NK / 64; kt++) {
        int k0 = kt * 64;
        __syncthreads();
        // stage K [key][d], V^T [d][key] via cp.async (16B each)
        #pragma unroll
        for (int i = 0; i < 2; i++) {
            int s = tid + i * 256;
            int r = s >> 3, f = s & 7;
            CP16(sptr(&Ks[r][f * 8]),
                 Kbase + (size_t)(k0 + r) * EMB + f * 8);
            CP16(sptr(&Vst[r][f * 8]),
                 Vtbase + (size_t)r * NK + k0 + f * 8);
        }
        CP_COMMIT();
        CP_WAIT0();
        __syncthreads();

        // S = Q @ K^T
        float sc[8][4];
        #pragma unroll
        for (int nt = 0; nt < 8; nt++)
            #pragma unroll
            for (int j = 0; j < 4; j++) sc[nt][j] = 0.0f;
        #pragma unroll
        for (int ks = 0; ks < 4; ks++) {
            uint32_t bf[8][2];
            #pragma unroll
            for (int p = 0; p < 4; p++)
                LDSM4(bf[2*p][0], bf[2*p][1], bf[2*p+1][0], bf[2*p+1][1],
                      k_base + p * 16 * 144 + ks * 32);
            #pragma unroll
            for (int nt = 0; nt < 8; nt++)
                MMA_F16(sc[nt], qa[ks], bf[nt]);
        }

        // mask + tile max
        unsigned long long w0 = mb0[kt], w1 = mb1[kt];
        float tm0 = -1e30f, tm1 = -1e30f;
        #pragma unroll
        for (int nt = 0; nt < 8; nt++) {
            int c0 = nt * 8 + 2 * t;
            sc[nt][0] = ((w0 >> c0) & 1)       ? sc[nt][0] : -1e30f;
            sc[nt][1] = ((w0 >> (c0 + 1)) & 1) ? sc[nt][1] : -1e30f;
            sc[nt][2] = ((w1 >> c0) & 1)       ? sc[nt][2] : -1e30f;
            sc[nt][3] = ((w1 >> (c0 + 1)) & 1) ? sc[nt][3] : -1e30f;
            tm0 = fmaxf(tm0, fmaxf(sc[nt][0], sc[nt][1]));
            tm1 = fmaxf(tm1, fmaxf(sc[nt][2], sc[nt][3]));
        }
        tm0 = fmaxf(tm0, __shfl_xor_sync(0xffffffffu, tm0, 1));
        tm0 = fmaxf(tm0, __shfl_xor_sync(0xffffffffu, tm0, 2));
        tm1 = fmaxf(tm1, __shfl_xor_sync(0xffffffffu, tm1, 1));
        tm1 = fmaxf(tm1, __shfl_xor_sync(0xffffffffu, tm1, 2));

        float mn0 = fmaxf(m0, tm0), mn1 = fmaxf(m1, tm1);
        float corr0 = __expf(m0 - mn0), corr1 = __expf(m1 - mn1);

        __syncwarp();
        float ps0 = 0.0f, ps1 = 0.0f;
        #pragma unroll
        for (int nt = 0; nt < 8; nt++) {
            int c0 = nt * 8 + 2 * t;
            float p00 = (sc[nt][0] > -1e29f) ? __expf(sc[nt][0] - mn0) : 0.0f;
            float p01 = (sc[nt][1] > -1e29f) ? __expf(sc[nt][1] - mn0) : 0.0f;
            float p10 = (sc[nt][2] > -1e29f) ? __expf(sc[nt][2] - mn1) : 0.0f;
            float p11 = (sc[nt][3] > -1e29f) ? __expf(sc[nt][3] - mn1) : 0.0f;
            ps0 += p00 + p01;
            ps1 += p10 + p11;
            *(half2*)&Ps[row0][c0] = __floats2half2_rn(p00, p01);
            *(half2*)&Ps[row1][c0] = __floats2half2_rn(p10, p11);
        }
        ps0 += __shfl_xor_sync(0xffffffffu, ps0, 1);
        ps0 += __shfl_xor_sync(0xffffffffu, ps0, 2);
        ps1 += __shfl_xor_sync(0xffffffffu, ps1, 1);
        ps1 += __shfl_xor_sync(0xffffffffu, ps1, 2);
        l0 = l0 * corr0 + ps0;  m0 = mn0;
        l1 = l1 * corr1 + ps1;  m1 = mn1;
        #pragma unroll
        for (int nt = 0; nt < 8; nt++) {
            acc[nt][0] *= corr0; acc[nt][1] *= corr0;
            acc[nt][2] *= corr1; acc[nt][3] *= corr1;
        }
        __syncwarp();

        // O += P @ V   (A from Ps, B from V^T [d][key])
        #pragma unroll
        for (int ks = 0; ks < 4; ks++) {
            uint32_t pa[4], bv[8][2];
            LDSM4(pa[0], pa[1], pa[2], pa[3], p_base + ks * 32);
            #pragma unroll
            for (int p = 0; p < 4; p++)
                LDSM4(bv[2*p][0], bv[2*p][1], bv[2*p+1][0], bv[2*p+1][1],
                      v_base + p * 16 * 144 + ks * 32);
            #pragma unroll
            for (int nt = 0; nt < 8; nt++)
                MMA_F16(acc[nt], pa, bv[nt]);
        }
    }

    float inv0 = (l0 > 0.0f) ? (1.0f / l0) : 0.0f;
    float inv1 = (l1 > 0.0f) ? (1.0f / l1) : 0.0f;
    __half* o0 = ctx + (size_t)(b * NQ + qt * 128 + row0) * EMB + h * HD;
    __half* o1 = ctx + (size_t)(b * NQ + qt * 128 + row1) * EMB + h * HD;
    #pragma unroll
    for (int nt = 0; nt < 8; nt++) {
        int c0 = nt * 8 + 2 * t;
        *(half2*)(o0 + c0) = __floats2half2_rn(acc[nt][0] * inv0, acc[nt][1] * inv0);
        *(half2*)(o1 + c0) = __floats2half2_rn(acc[nt][2] * inv1, acc[nt][3] * inv1);
    }
}

// ---------------- masks -------------------------------------------------------
__global__ void detect_mask_kernel(const unsigned char* kvm_raw,
                                   const unsigned char* spm_raw) {
    __shared__ int found[2];
    if (threadIdx.x == 0) { found[0] = 0; found[1] = 0; }
    __syncthreads();
    for (int i = threadIdx.x; i < 8192; i += blockDim.x) {
        if ((i & 3) != 0) {
            if (kvm_raw[i]) atomicOr(&found[0], 1);
            if (spm_raw[i]) atomicOr(&found[1], 1);
        }
    }
    __syncthreads();
    if (threadIdx.x == 0) { g_is_byte[0] = found[0]; g_is_byte[1] = found[1]; }
}

__global__ void mask_bits_kernel(const void* kvm_raw, const void* spm_raw) {
    int idx = blockIdx.x * blockDim.x + threadIdx.x;   // 262144 words
    int bq = idx >> 5, wk = idx & 31;
    int b = bq >> 11;
    int kbase = wk * 64;
    bool kb = g_is_byte[0] != 0, sb = g_is_byte[1] != 0;
    const unsigned char* kvc = (const unsigned char*)kvm_raw + b * NK + kbase;
    const int*           kvi = (const int*)kvm_raw + b * NK + kbase;
    const unsigned char* spc = (const unsigned char*)spm_raw + (size_t)bq * NK + kbase;
    const int*           spi = (const int*)spm_raw + (size_t)bq * NK + kbase;
    unsigned long long bits = 0;
    #pragma unroll 8
    for (int j = 0; j < 64; j++) {
        bool kv = kb ? (kvc[j] != 0) : (kvi[j] != 0);
        bool sp = sb ? (spc[j] != 0) : (spi[j] != 0);
        if (kv && sp) bits |= 1ULL << j;
    }
    g_mbits[idx] = bits;
}

// ---------------- LayerNorm (both tensors, half output) -----------------------
__global__ void lnorm_kernel(const float* __restrict__ xq,
                             const float* __restrict__ xkv,
                             const float* __restrict__ gq,
                             const float* __restrict__ bq,
                             const float* __restrict__ gkv,
                             const float* __restrict__ bkv,
                             __half* __restrict__ yq,
                             __half* __restrict__ ykv) {
    __shared__ float red[8];
    int row = blockIdx.x, t = threadIdx.x;
    const float* x = blockIdx.y ? xkv : xq;
    const float* g = blockIdx.y ? gkv : gq;
    const float* b = blockIdx.y ? bkv : bq;
    __half* y      = blockIdx.y ? ykv : yq;

    float4 v = ((const float4*)(x + (size_t)row * EMB))[t];
    float s  = v.x + v.y + v.z + v.w;
    float s2 = v.x*v.x + v.y*v.y + v.z*v.z + v.w*v.w;
    #pragma unroll
    for (int o = 16; o > 0; o >>= 1) {
        s  += __shfl_xor_sync(0xffffffffu, s,  o);
        s2 += __shfl_xor_sync(0xffffffffu, s2, o);
    }
    if ((t & 31) == 0) { red[t >> 5] = s; red[4 + (t >> 5)] = s2; }
    __syncthreads();
    float tot  = red[0] + red[1] + red[2] + red[3];
    float tot2 = red[4] + red[5] + red[6] + red[7];
    float mu  = tot * (1.0f / EMB);
    float var = tot2 * (1.0f / EMB) - mu * mu;
    float inv = rsqrtf(var + 1e-5f);
    float4 gg = ((const float4*)g)[t];
    float4 bb = ((const float4*)b)[t];
    float o0 = (v.x - mu) * inv * gg.x + bb.x;
    float o1 = (v.y - mu) * inv * gg.y + bb.y;
    float o2 = (v.z - mu) * inv * gg.z + bb.z;
    float o3 = (v.w - mu) * inv * gg.w + bb.w;
    __half* yr = y + (size_t)row * EMB + t * 4;
    *(half2*)(yr)     = __floats2half2_rn(o0, o1);
    *(half2*)(yr + 2) = __floats2half2_rn(o2, o3);
}

// ---------------- weight transpose (all 4, half output) -----------------------
__global__ void wt_kernel(const float* __restrict__ Wq,
                          const float* __restrict__ Wk,
                          const float* __restrict__ Wv,
                          const float* __restrict__ Wo,
                          __half* __restrict__ Wt) {
    __shared__ float tile[32][33];
    int z = blockIdx.z;
    const float* W = (z == 0) ? Wq : (z == 1) ? Wk : (z == 2) ? Wv : Wo;
    __half* dst = Wt + (size_t)z * EMB * EMB;
    int bx = blockIdx.x * 32, by = blockIdx.y * 32;
    int tx = threadIdx.x, ty = threadIdx.y;
    #pragma unroll
    for (int i = 0; i < 4; i++)
        tile[ty + i * 8][tx] = W[(size_t)(by + ty + i * 8) * EMB + bx + tx];
    __syncthreads();
    #pragma unroll
    for (int i = 0; i < 4; i++)
        dst[(size_t)(bx + ty + i * 8) * EMB + by + tx] =
            __float2half_rn(tile[tx][ty + i * 8]);
}

// ---------------- launch ------------------------------------------------------
extern "C" void kernel_launch(void* const* d_in, const int* in_sizes, int n_in,
                              void* d_out, int out_size) {
    const float* query     = (const float*)d_in[0];
    const float* key_value = (const float*)d_in[1];
    const void*  kvm_raw   = d_in[2];
    const void*  spm_raw   = d_in[3];
    const float* ln_q_g  = (const float*)d_in[4];
    const float* ln_q_b  = (const float*)d_in[5];
    const float* ln_kv_g = (const float*)d_in[6];
    const float* ln_kv_b = (const float*)d_in[7];
    const float* Wq = (const float*)d_in[8];
    const float* bq = (const float*)d_in[9];
    const float* Wk = (const float*)d_in[10];
    const float* bk = (const float*)d_in[11];
    const float* Wv = (const float*)d_in[12];
    const float* bv = (const float*)d_in[13];
    const float* Wo = (const float*)d_in[14];
    const float* bo = (const float*)d_in[15];
    float* out = (float*)d_out;

    void *p_qn, *p_kvn, *p_q, *p_k, *p_vt, *p_ctx, *p_wt, *p_mb;
    cudaGetSymbolAddress(&p_qn,  g_qn);
    cudaGetSymbolAddress(&p_kvn, g_kvn);
    cudaGetSymbolAddress(&p_q,   g_q);
    cudaGetSymbolAddress(&p_k,   g_k);
    cudaGetSymbolAddress(&p_vt,  g_vt);
    cudaGetSymbolAddress(&p_ctx, g_ctx);
    cudaGetSymbolAddress(&p_wt,  g_wt);
    cudaGetSymbolAddress(&p_mb,  g_mbits);

    detect_mask_kernel<<<1, 256>>>((const unsigned char*)kvm_raw,
                                   (const unsigned char*)spm_raw);
    mask_bits_kernel<<<(BATCH * NQ * (NK / 64)) / 256, 256>>>(kvm_raw, spm_raw);

    dim3 lg(NTOK, 2);
    lnorm_kernel<<<lg, 128>>>(query, key_value, ln_q_g, ln_q_b,
                              ln_kv_g, ln_kv_b,
                              (__half*)p_qn, (__half*)p_kvn);

    dim3 tb(32, 8), tg(16, 16, 4);
    wt_kernel<<<tg, tb>>>(Wq, Wk, Wv, Wo, (__half*)p_wt);

    dim3 pg(EMB / 128, NTOK / 128, 3);
    proj_qkv_kernel<<<pg, 256>>>((const __half*)p_qn, (const __half*)p_kvn,
                                 (const __half*)p_wt, bq, bk, bv,
                                 (__half*)p_q, (__half*)p_k, (__half*)p_vt);

    dim3 fg(NQ / 128, BHN);
    fattn_kernel<<<fg, 256>>>((const __half*)p_q, (const __half*)p_k,
                              (const __half*)p_vt,
                              (const unsigned long long*)p_mb,
                              (__half*)p_ctx);

    dim3 og(EMB / 128, NTOK / 128);
    proj_o_kernel<<<og, 256>>>((const __half*)p_ctx, (const __half*)p_wt,
                               bo, out);
}

// round 8
// speedup vs baseline: 1.1283x; 1.1283x over previous
#include <cuda_runtime.h>
#include <cuda_fp16.h>
#include <cstdint>
#include <cstddef>

#define BATCH 4
#define NQ    2048
#define NK    2048
#define EMB   512
#define NH    8
#define HD    64
#define NTOK  (BATCH * NQ)
#define BHN   (BATCH * NH)

// ---------------- device-global scratch ---------------------------------------
__device__ __half g_qn [NTOK * EMB];
__device__ __half g_kvn[NTOK * EMB];
__device__ __half g_q  [NTOK * EMB];          // pre-scaled by 0.125
__device__ __half g_k  [NTOK * EMB];          // COMPACTED rows per batch
__device__ __half g_vt [BHN * HD * NK];       // V^T per (b,h): [d][compacted key]
__device__ __half g_ctx[NTOK * EMB];
__device__ __half g_wt [4 * EMB * EMB];       // W^T, k-major rows
__device__ unsigned long long g_mbits[(size_t)BATCH * NQ * (NK / 64)]; // compacted cols
__device__ int g_kidx[BATCH * NK];            // compacted -> original key
__device__ int g_nvalid[BATCH];
__device__ int g_nkt[BATCH];                  // ceil(nvalid/64)
__device__ int g_is_byte[2];

// ---------------- PTX helpers --------------------------------------------------
__device__ __forceinline__ uint32_t sptr(const void* p) {
    uint32_t a;
    asm("{ .reg .u64 t; cvta.to.shared.u64 t, %1; cvt.u32.u64 %0, t; }"
        : "=r"(a) : "l"(p));
    return a;
}

#define MMA_F16(C, A, B) \
    asm volatile( \
        "mma.sync.aligned.m16n8k16.row.col.f32.f16.f16.f32 " \
        "{%0,%1,%2,%3}, {%4,%5,%6,%7}, {%8,%9}, {%0,%1,%2,%3};" \
        : "+f"((C)[0]), "+f"((C)[1]), "+f"((C)[2]), "+f"((C)[3]) \
        : "r"((A)[0]), "r"((A)[1]), "r"((A)[2]), "r"((A)[3]), \
          "r"((B)[0]), "r"((B)[1]))

#define LDSM4(R0, R1, R2, R3, ADDR) \
    asm volatile("ldmatrix.sync.aligned.m8n8.x4.shared.b16 {%0,%1,%2,%3}, [%4];" \
        : "=r"(R0), "=r"(R1), "=r"(R2), "=r"(R3) : "r"(ADDR))

#define CP16(DST, SRC) \
    asm volatile("cp.async.cg.shared.global [%0], [%1], 16;" \
        :: "r"(DST), "l"(SRC))
#define CP_COMMIT() asm volatile("cp.async.commit_group;" ::: "memory")
#define CP_WAIT0()  asm volatile("cp.async.wait_group 0;" ::: "memory")

// ---------------- fp16 GEMM mainloop: C[128x128] = A[128,512] @ B[128,512]^T ---
// ridx != nullptr: A rows gathered (batch-local token indices).
__device__ __forceinline__ void gemm16_mainloop(
        const __half* __restrict__ A, const int* __restrict__ ridx,
        const __half* __restrict__ B, float (&c)[2][8][4]) {
    __shared__ __align__(16) __half As[128][40];
    __shared__ __align__(16) __half Bs[128][40];
    const int tid = threadIdx.x;
    const int lane = tid & 31, wid = tid >> 5;
    const int wm = wid & 3, wn = wid >> 2;

    #pragma unroll
    for (int mt = 0; mt < 2; mt++)
        #pragma unroll
        for (int nt = 0; nt < 8; nt++)
            #pragma unroll
            for (int j = 0; j < 4; j++) c[mt][nt][j] = 0.0f;

    const uint32_t a_base = sptr(&As[wm * 32 + ((lane & 8) ? 8 : 0) + (lane & 7)]
                                    [(lane & 16) ? 8 : 0]);
    const uint32_t b_base = sptr(&Bs[wn * 64 + ((lane & 16) ? 8 : 0) + (lane & 7)]
                                    [(lane & 8) ? 8 : 0]);

    const int r0 = tid >> 2, r1 = r0 + 64;
    const int f0 = (tid & 3) * 8;
    const __half* A0 = A + (size_t)(ridx ? ridx[r0] : r0) * EMB + f0;
    const __half* A1 = A + (size_t)(ridx ? ridx[r1] : r1) * EMB + f0;
    const __half* B0 = B + (size_t)r0 * EMB + f0;
    const __half* B1 = B + (size_t)r1 * EMB + f0;
    __half* sA0 = &As[r0][f0];
    __half* sA1 = &As[r1][f0];
    __half* sB0 = &Bs[r0][f0];
    __half* sB1 = &Bs[r1][f0];

    uint4 pa0 = *(const uint4*)A0, pa1 = *(const uint4*)A1;
    uint4 pb0 = *(const uint4*)B0, pb1 = *(const uint4*)B1;

    for (int ch = 0; ch < 16; ch++) {
        *(uint4*)sA0 = pa0;  *(uint4*)sA1 = pa1;
        *(uint4*)sB0 = pb0;  *(uint4*)sB1 = pb1;
        __syncthreads();
        if (ch + 1 < 16) {
            int co = (ch + 1) * 32;
            pa0 = *(const uint4*)(A0 + co);
            pa1 = *(const uint4*)(A1 + co);
            pb0 = *(const uint4*)(B0 + co);
            pb1 = *(const uint4*)(B1 + co);
        }
        #pragma unroll
        for (int ks = 0; ks < 2; ks++) {
            uint32_t a[2][4], b[8][2];
            #pragma unroll
            for (int mt = 0; mt < 2; mt++)
                LDSM4(a[mt][0], a[mt][1], a[mt][2], a[mt][3],
                      a_base + mt * 1280 + ks * 32);
            #pragma unroll
            for (int p = 0; p < 4; p++)
                LDSM4(b[2*p][0], b[2*p][1], b[2*p+1][0], b[2*p+1][1],
                      b_base + p * 1280 + ks * 32);
            #pragma unroll
            for (int mt = 0; mt < 2; mt++)
                #pragma unroll
                for (int nt = 0; nt < 8; nt++)
                    MMA_F16(c[mt][nt], a[mt], b[nt]);
        }
        __syncthreads();
    }
}

// Q/K/V projections. z=0: Q (scaled 0.125), z=1: K (gathered), z=2: V^T (gathered).
__global__ void __launch_bounds__(256, 2) proj_qkv_kernel(
        const __half* __restrict__ qn, const __half* __restrict__ kvn,
        const __half* __restrict__ wt,
        const float* __restrict__ bq, const float* __restrict__ bk,
        const float* __restrict__ bv,
        __half* __restrict__ q, __half* __restrict__ k,
        __half* __restrict__ vt) {
    const int z = blockIdx.z;
    const size_t bm = (size_t)blockIdx.y * 128, bn = (size_t)blockIdx.x * 128;
    const int bb = (int)(bm >> 11);           // batch
    const int rloc = (int)(bm & 2047);        // row within batch

    const int* ridx = nullptr;
    const __half* A;
    if (z == 0) {
        A = qn + bm * EMB;
    } else {
        if (rloc >= g_nkt[bb] * 64) return;   // compacted tail: no work
        A = kvn + (size_t)bb * 2048 * EMB;
        ridx = g_kidx + bb * NK + rloc;
    }
    const __half* B = wt + (size_t)z * EMB * EMB + bn * EMB;
    float c[2][8][4];
    gemm16_mainloop(A, ridx, B, c);

    const int tid = threadIdx.x, lane = tid & 31, wid = tid >> 5;
    const int wm = wid & 3, wn = wid >> 2, g = lane >> 2, t = lane & 3;
    const float* bias = (z == 0) ? bq : (z == 1) ? bk : bv;
    const float scale = (z == 0) ? 0.125f : 1.0f;

    #pragma unroll
    for (int mt = 0; mt < 2; mt++) {
        #pragma unroll
        for (int nt = 0; nt < 8; nt++) {
            int m   = (int)bm + wm * 32 + mt * 16 + g;
            int col = (int)bn + wn * 64 + nt * 8 + 2 * t;
            float b0 = bias[col], b1 = bias[col + 1];
            float v0 = (c[mt][nt][0] + b0) * scale;
            float v1 = (c[mt][nt][1] + b1) * scale;
            float v2 = (c[mt][nt][2] + b0) * scale;
            float v3 = (c[mt][nt][3] + b1) * scale;
            if (z < 2) {
                __half* dst = (z == 0) ? q : k;
                *(half2*)(dst + (size_t)m * EMB + col) = __floats2half2_rn(v0, v1);
                *(half2*)(dst + (size_t)(m + 8) * EMB + col) = __floats2half2_rn(v2, v3);
            } else {
                int h = col >> 6, d = col & 63;
                int b_ = m >> 11;
                size_t base = ((size_t)(b_ * NH + h) * HD);
                int tok = m & 2047;            // compacted key index
                vt[(base + d) * NK + tok]         = __float2half_rn(v0);
                vt[(base + d + 1) * NK + tok]     = __float2half_rn(v1);
                vt[(base + d) * NK + tok + 8]     = __float2half_rn(v2);
                vt[(base + d + 1) * NK + tok + 8] = __float2half_rn(v3);
            }
        }
    }
}

// Output projection: fp32 result + bias into d_out.
__global__ void __launch_bounds__(256, 2) proj_o_kernel(
        const __half* __restrict__ ctx, const __half* __restrict__ wt,
        const float* __restrict__ bo, float* __restrict__ out) {
    const size_t bm = (size_t)blockIdx.y * 128, bn = (size_t)blockIdx.x * 128;
    float c[2][8][4];
    gemm16_mainloop(ctx + bm * EMB, nullptr,
                    wt + 3ull * EMB * EMB + bn * EMB, c);

    const int tid = threadIdx.x, lane = tid & 31, wid = tid >> 5;
    const int wm = wid & 3, wn = wid >> 2, g = lane >> 2, t = lane & 3;
    #pragma unroll
    for (int mt = 0; mt < 2; mt++) {
        #pragma unroll
        for (int nt = 0; nt < 8; nt++) {
            int m   = (int)bm + wm * 32 + mt * 16 + g;
            int col = (int)bn + wn * 64 + nt * 8 + 2 * t;
            float b0 = bo[col], b1 = bo[col + 1];
            *(float2*)(out + (size_t)m * EMB + col) =
                make_float2(c[mt][nt][0] + b0, c[mt][nt][1] + b1);
            *(float2*)(out + (size_t)(m + 8) * EMB + col) =
                make_float2(c[mt][nt][2] + b0, c[mt][nt][3] + b1);
        }
    }
}

// ---------------- fused flash attention (fp16 MMA, compacted keys) -------------
__global__ void __launch_bounds__(256, 2) fattn_kernel(
        const __half* __restrict__ Qp, const __half* __restrict__ Kp,
        const __half* __restrict__ Vtp,
        const unsigned long long* __restrict__ mbits,
        __half* __restrict__ ctx) {
    __shared__ __align__(16) __half Ks [64][72];
    __shared__ __align__(16) __half Vst[64][72];
    __shared__ __align__(16) __half Ps [128][72];

    const int tid = threadIdx.x;
    const int lane = tid & 31, w = tid >> 5;
    const int g = lane >> 2, t = lane & 3;
    const int qt = blockIdx.x, bh = blockIdx.y;
    const int b = bh >> 3, h = bh & 7;
    const int row0 = w * 16 + g, row1 = row0 + 8;
    const int nkt = g_nkt[b];

    const uint32_t k_base = sptr(&Ks[((lane & 16) ? 8 : 0) + (lane & 7)]
                                    [(lane & 8) ? 8 : 0]);
    const uint32_t v_base = sptr(&Vst[((lane & 16) ? 8 : 0) + (lane & 7)]
                                     [(lane & 8) ? 8 : 0]);
    const uint32_t p_base = sptr(&Ps[w * 16 + ((lane & 8) ? 8 : 0) + (lane & 7)]
                                    [(lane & 16) ? 8 : 0]);

    uint32_t qa[4][4];
    {
        const __half* q0 = Qp + (size_t)(b * NQ + qt * 128 + row0) * EMB + h * HD;
        const __half* q1 = Qp + (size_t)(b * NQ + qt * 128 + row1) * EMB + h * HD;
        #pragma unroll
        for (int ks = 0; ks < 4; ks++) {
            qa[ks][0] = *(const uint32_t*)(q0 + ks * 16 + 2 * t);
            qa[ks][1] = *(const uint32_t*)(q1 + ks * 16 + 2 * t);
            qa[ks][2] = *(const uint32_t*)(q0 + ks * 16 + 2 * t + 8);
            qa[ks][3] = *(const uint32_t*)(q1 + ks * 16 + 2 * t + 8);
        }
    }

    float m0 = -1e30f, m1 = -1e30f, l0 = 0.0f, l1 = 0.0f;
    float acc[8][4];
    #pragma unroll
    for (int nt = 0; nt < 8; nt++)
        #pragma unroll
        for (int j = 0; j < 4; j++) acc[nt][j] = 0.0f;

    const unsigned long long* mb0 =
        mbits + ((size_t)b * NQ + qt * 128 + row0) * (NK / 64);
    const unsigned long long* mb1 =
        mbits + ((size_t)b * NQ + qt * 128 + row1) * (NK / 64);

    const __half* Kbase  = Kp + ((size_t)b * NK) * EMB + h * HD;
    const __half* Vtbase = Vtp + (size_t)bh * HD * NK;

    for (int kt = 0; kt < nkt; kt++) {
        int k0 = kt * 64;
        __syncthreads();
        #pragma unroll
        for (int i = 0; i < 2; i++) {
            int s = tid + i * 256;
            int r = s >> 3, f = s & 7;
            CP16(sptr(&Ks[r][f * 8]),
                 Kbase + (size_t)(k0 + r) * EMB + f * 8);
            CP16(sptr(&Vst[r][f * 8]),
                 Vtbase + (size_t)r * NK + k0 + f * 8);
        }
        CP_COMMIT();
        CP_WAIT0();
        __syncthreads();

        float sc[8][4];
        #pragma unroll
        for (int nt = 0; nt < 8; nt++)
            #pragma unroll
            for (int j = 0; j < 4; j++) sc[nt][j] = 0.0f;
        #pragma unroll
        for (int ks = 0; ks < 4; ks++) {
            uint32_t bf[8][2];
            #pragma unroll
            for (int p = 0; p < 4; p++)
                LDSM4(bf[2*p][0], bf[2*p][1], bf[2*p+1][0], bf[2*p+1][1],
                      k_base + p * 16 * 144 + ks * 32);
            #pragma unroll
            for (int nt = 0; nt < 8; nt++)
                MMA_F16(sc[nt], qa[ks], bf[nt]);
        }

        unsigned long long w0 = mb0[kt], w1 = mb1[kt];
        float tm0 = -1e30f, tm1 = -1e30f;
        #pragma unroll
        for (int nt = 0; nt < 8; nt++) {
            int c0 = nt * 8 + 2 * t;
            sc[nt][0] = ((w0 >> c0) & 1)       ? sc[nt][0] : -1e30f;
            sc[nt][1] = ((w0 >> (c0 + 1)) & 1) ? sc[nt][1] : -1e30f;
            sc[nt][2] = ((w1 >> c0) & 1)       ? sc[nt][2] : -1e30f;
            sc[nt][3] = ((w1 >> (c0 + 1)) & 1) ? sc[nt][3] : -1e30f;
            tm0 = fmaxf(tm0, fmaxf(sc[nt][0], sc[nt][1]));
            tm1 = fmaxf(tm1, fmaxf(sc[nt][2], sc[nt][3]));
        }
        tm0 = fmaxf(tm0, __shfl_xor_sync(0xffffffffu, tm0, 1));
        tm0 = fmaxf(tm0, __shfl_xor_sync(0xffffffffu, tm0, 2));
        tm1 = fmaxf(tm1, __shfl_xor_sync(0xffffffffu, tm1, 1));
        tm1 = fmaxf(tm1, __shfl_xor_sync(0xffffffffu, tm1, 2));

        float mn0 = fmaxf(m0, tm0), mn1 = fmaxf(m1, tm1);
        float corr0 = __expf(m0 - mn0), corr1 = __expf(m1 - mn1);

        __syncwarp();
        float ps0 = 0.0f, ps1 = 0.0f;
        #pragma unroll
        for (int nt = 0; nt < 8; nt++) {
            int c0 = nt * 8 + 2 * t;
            float p00 = (sc[nt][0] > -1e29f) ? __expf(sc[nt][0] - mn0) : 0.0f;
            float p01 = (sc[nt][1] > -1e29f) ? __expf(sc[nt][1] - mn0) : 0.0f;
            float p10 = (sc[nt][2] > -1e29f) ? __expf(sc[nt][2] - mn1) : 0.0f;
            float p11 = (sc[nt][3] > -1e29f) ? __expf(sc[nt][3] - mn1) : 0.0f;
            ps0 += p00 + p01;
            ps1 += p10 + p11;
            *(half2*)&Ps[row0][c0] = __floats2half2_rn(p00, p01);
            *(half2*)&Ps[row1][c0] = __floats2half2_rn(p10, p11);
        }
        ps0 += __shfl_xor_sync(0xffffffffu, ps0, 1);
        ps0 += __shfl_xor_sync(0xffffffffu, ps0, 2);
        ps1 += __shfl_xor_sync(0xffffffffu, ps1, 1);
        ps1 += __shfl_xor_sync(0xffffffffu, ps1, 2);
        l0 = l0 * corr0 + ps0;  m0 = mn0;
        l1 = l1 * corr1 + ps1;  m1 = mn1;
        #pragma unroll
        for (int nt = 0; nt < 8; nt++) {
            acc[nt][0] *= corr0; acc[nt][1] *= corr0;
            acc[nt][2] *= corr1; acc[nt][3] *= corr1;
        }
        __syncwarp();

        #pragma unroll
        for (int ks = 0; ks < 4; ks++) {
            uint32_t pa[4], bv[8][2];
            LDSM4(pa[0], pa[1], pa[2], pa[3], p_base + ks * 32);
            #pragma unroll
            for (int p = 0; p < 4; p++)
                LDSM4(bv[2*p][0], bv[2*p][1], bv[2*p+1][0], bv[2*p+1][1],
                      v_base + p * 16 * 144 + ks * 32);
            #pragma unroll
            for (int nt = 0; nt < 8; nt++)
                MMA_F16(acc[nt], pa, bv[nt]);
        }
    }

    float inv0 = (l0 > 0.0f) ? (1.0f / l0) : 0.0f;
    float inv1 = (l1 > 0.0f) ? (1.0f / l1) : 0.0f;
    __half* o0 = ctx + (size_t)(b * NQ + qt * 128 + row0) * EMB + h * HD;
    __half* o1 = ctx + (size_t)(b * NQ + qt * 128 + row1) * EMB + h * HD;
    #pragma unroll
    for (int nt = 0; nt < 8; nt++) {
        int c0 = nt * 8 + 2 * t;
        *(half2*)(o0 + c0) = __floats2half2_rn(acc[nt][0] * inv0, acc[nt][1] * inv0);
        *(half2*)(o1 + c0) = __floats2half2_rn(acc[nt][2] * inv1, acc[nt][3] * inv1);
    }
}

// ---------------- mask dtype sniff ---------------------------------------------
__global__ void detect_mask_kernel(const unsigned char* kvm_raw,
                                   const unsigned char* spm_raw) {
    __shared__ int found[2];
    if (threadIdx.x == 0) { found[0] = 0; found[1] = 0; }
    __syncthreads();
    for (int i = threadIdx.x; i < 8192; i += blockDim.x) {
        if ((i & 3) != 0) {
            if (kvm_raw[i]) atomicOr(&found[0], 1);
            if (spm_raw[i]) atomicOr(&found[1], 1);
        }
    }
    __syncthreads();
    if (threadIdx.x == 0) { g_is_byte[0] = found[0]; g_is_byte[1] = found[1]; }
}

// ---------------- kv_mask stream compaction (order-preserving) ------------------
__global__ void compact_idx_kernel(const void* kvm_raw) {
    const int b = blockIdx.x;
    const int tid = threadIdx.x;                 // 256
    const int lane = tid & 31, w = tid >> 5;
    __shared__ int base;
    __shared__ int wstart[8];
    if (tid == 0) base = 0;
    __syncthreads();
    const bool kb = g_is_byte[0] != 0;
    for (int c0 = 0; c0 < NK; c0 += 256) {
        int kk = c0 + tid;
        bool v = kb ? (((const unsigned char*)kvm_raw)[b * NK + kk] != 0)
                    : (((const int*)kvm_raw)[b * NK + kk] != 0);
        unsigned bal = __ballot_sync(0xffffffffu, v);
        __shared__ int wcnt[8];
        if (lane == 0) wcnt[w] = __popc(bal);
        __syncthreads();
        if (tid == 0) {
            int s = base;
            #pragma unroll
            for (int i = 0; i < 8; i++) { wstart[i] = s; s += wcnt[i]; }
            base = s;
        }
        __syncthreads();
        if (v)
            g_kidx[b * NK + wstart[w] + __popc(bal & ((1u << lane) - 1))] = kk;
        __syncthreads();
    }
    int nv = base;
    for (int c = nv + tid; c < NK; c += 256) g_kidx[b * NK + c] = 0;
    if (tid == 0) {
        g_nvalid[b] = nv;
        g_nkt[b] = (nv + 63) >> 6;
    }
}

// ---------------- sparse-mask bits over compacted columns -----------------------
__global__ void mask_bits_kernel(const void* spm_raw) {
    int idx = blockIdx.x * blockDim.x + threadIdx.x;   // B*NQ*32
    int ct = idx & 31;
    int bq = idx >> 5;
    int b = bq >> 11;
    int nv = g_nvalid[b];
    int cbase = ct * 64;
    int lim = nv - cbase;
    if (lim > 64) lim = 64;
    unsigned long long bits = 0;
    if (lim > 0) {
        const int* kidx = g_kidx + b * NK + cbase;
        if (g_is_byte[1]) {
            const unsigned char* sp = (const unsigned char*)spm_raw + (size_t)bq * NK;
            for (int j = 0; j < lim; j++)
                if (sp[kidx[j]]) bits |= 1ULL << j;
        } else {
            const int* sp = (const int*)spm_raw + (size_t)bq * NK;
            for (int j = 0; j < lim; j++)
                if (sp[kidx[j]]) bits |= 1ULL << j;
        }
    }
    g_mbits[idx] = bits;
}

// ---------------- LayerNorm (both tensors, half output) ------------------------
__global__ void lnorm_kernel(const float* __restrict__ xq,
                             const float* __restrict__ xkv,
                             const float* __restrict__ gq,
                             const float* __restrict__ bq,
                             const float* __restrict__ gkv,
                             const float* __restrict__ bkv,
                             __half* __restrict__ yq,
                             __half* __restrict__ ykv) {
    __shared__ float red[8];
    int row = blockIdx.x, t = threadIdx.x;
    const float* x = blockIdx.y ? xkv : xq;
    const float* g = blockIdx.y ? gkv : gq;
    const float* b = blockIdx.y ? bkv : bq;
    __half* y      = blockIdx.y ? ykv : yq;

    float4 v = ((const float4*)(x + (size_t)row * EMB))[t];
    float s  = v.x + v.y + v.z + v.w;
    float s2 = v.x*v.x + v.y*v.y + v.z*v.z + v.w*v.w;
    #pragma unroll
    for (int o = 16; o > 0; o >>= 1) {
        s  += __shfl_xor_sync(0xffffffffu, s,  o);
        s2 += __shfl_xor_sync(0xffffffffu, s2, o);
    }
    if ((t & 31) == 0) { red[t >> 5] = s; red[4 + (t >> 5)] = s2; }
    __syncthreads();
    float tot  = red[0] + red[1] + red[2] + red[3];
    float tot2 = red[4] + red[5] + red[6] + red[7];
    float mu  = tot * (1.0f / EMB);
    float var = tot2 * (1.0f / EMB) - mu * mu;
    float inv = rsqrtf(var + 1e-5f);
    float4 gg = ((const float4*)g)[t];
    float4 bb = ((const float4*)b)[t];
    float o0 = (v.x - mu) * inv * gg.x + bb.x;
    float o1 = (v.y - mu) * inv * gg.y + bb.y;
    float o2 = (v.z - mu) * inv * gg.z + bb.z;
    float o3 = (v.w - mu) * inv * gg.w + bb.w;
    __half* yr = y + (size_t)row * EMB + t * 4;
    *(half2*)(yr)     = __floats2half2_rn(o0, o1);
    *(half2*)(yr + 2) = __floats2half2_rn(o2, o3);
}

// ---------------- weight transpose (all 4, half output) ------------------------
__global__ void wt_kernel(const float* __restrict__ Wq,
                          const float* __restrict__ Wk,
                          const float* __restrict__ Wv,
                          const float* __restrict__ Wo,
                          __half* __restrict__ Wt) {
    __shared__ float tile[32][33];
    int z = blockIdx.z;
    const float* W = (z == 0) ? Wq : (z == 1) ? Wk : (z == 2) ? Wv : Wo;
    __half* dst = Wt + (size_t)z * EMB * EMB;
    int bx = blockIdx.x * 32, by = blockIdx.y * 32;
    int tx = threadIdx.x, ty = threadIdx.y;
    #pragma unroll
    for (int i = 0; i < 4; i++)
        tile[ty + i * 8][tx] = W[(size_t)(by + ty + i * 8) * EMB + bx + tx];
    __syncthreads();
    #pragma unroll
    for (int i = 0; i < 4; i++)
        dst[(size_t)(bx + ty + i * 8) * EMB + by + tx] =
            __float2half_rn(tile[tx][ty + i * 8]);
}

// ---------------- launch --------------------------------------------------------
extern "C" void kernel_launch(void* const* d_in, const int* in_sizes, int n_in,
                              void* d_out, int out_size) {
    const float* query     = (const float*)d_in[0];
    const float* key_value = (const float*)d_in[1];
    const void*  kvm_raw   = d_in[2];
    const void*  spm_raw   = d_in[3];
    const float* ln_q_g  = (const float*)d_in[4];
    const float* ln_q_b  = (const float*)d_in[5];
    const float* ln_kv_g = (const float*)d_in[6];
    const float* ln_kv_b = (const float*)d_in[7];
    const float* Wq = (const float*)d_in[8];
    const float* bq = (const float*)d_in[9];
    const float* Wk = (const float*)d_in[10];
    const float* bk = (const float*)d_in[11];
    const float* Wv = (const float*)d_in[12];
    const float* bv = (const float*)d_in[13];
    const float* Wo = (const float*)d_in[14];
    const float* bo = (const float*)d_in[15];
    float* out = (float*)d_out;

    void *p_qn, *p_kvn, *p_q, *p_k, *p_vt, *p_ctx, *p_wt, *p_mb;
    cudaGetSymbolAddress(&p_qn,  g_qn);
    cudaGetSymbolAddress(&p_kvn, g_kvn);
    cudaGetSymbolAddress(&p_q,   g_q);
    cudaGetSymbolAddress(&p_k,   g_k);
    cudaGetSymbolAddress(&p_vt,  g_vt);
    cudaGetSymbolAddress(&p_ctx, g_ctx);
    cudaGetSymbolAddress(&p_wt,  g_wt);
    cudaGetSymbolAddress(&p_mb,  g_mbits);

    detect_mask_kernel<<<1, 256>>>((const unsigned char*)kvm_raw,
                                   (const unsigned char*)spm_raw);
    compact_idx_kernel<<<BATCH, 256>>>(kvm_raw);
    mask_bits_kernel<<<(BATCH * NQ * (NK / 64)) / 256, 256>>>(spm_raw);

    dim3 lg(NTOK, 2);
    lnorm_kernel<<<lg, 128>>>(query, key_value, ln_q_g, ln_q_b,
                              ln_kv_g, ln_kv_b,
                              (__half*)p_qn, (__half*)p_kvn);

    dim3 tb(32, 8), tg(16, 16, 4);
    wt_kernel<<<tg, tb>>>(Wq, Wk, Wv, Wo, (__half*)p_wt);

    dim3 pg(EMB / 128, NTOK / 128, 3);
    proj_qkv_kernel<<<pg, 256>>>((const __half*)p_qn, (const __half*)p_kvn,
                                 (const __half*)p_wt, bq, bk, bv,
                                 (__half*)p_q, (__half*)p_k, (__half*)p_vt);

    dim3 fg(NQ / 128, BHN);
    fattn_kernel<<<fg, 256>>>((const __half*)p_q, (const __half*)p_k,
                              (const __half*)p_vt,
                              (const unsigned long long*)p_mb,
                              (__half*)p_ctx);

    dim3 og(EMB / 128, NTOK / 128);
    proj_o_kernel<<<og, 256>>>((const __half*)p_ctx, (const __half*)p_wt,
                               bo, out);
}

// round 9
// speedup vs baseline: 1.8998x; 1.6837x over previous
#include <cuda_runtime.h>
#include <cuda_fp16.h>
#include <cstdint>
#include <cstddef>

#define BATCH 4
#define NQ    2048
#define NK    2048
#define EMB   512
#define NH    8
#define HD    64
#define NTOK  (BATCH * NQ)
#define BHN   (BATCH * NH)

// ---------------- device-global scratch ---------------------------------------
__device__ __half g_qn [NTOK * EMB];
__device__ __half g_kvn[NTOK * EMB];
__device__ __half g_q  [NTOK * EMB];          // pre-scaled by 0.125
__device__ __half g_k  [NTOK * EMB];          // COMPACTED rows per batch
__device__ __half g_vt [BHN * HD * NK];       // V^T per (b,h): [d][compacted key]
__device__ __half g_ctx[NTOK * EMB];
__device__ __half g_wt [4 * EMB * EMB];       // W^T, k-major rows
__device__ unsigned long long g_mbits[(size_t)BATCH * NQ * (NK / 64)];
__device__ int g_kidx[BATCH * NK];
__device__ int g_nvalid[BATCH];
__device__ int g_nkt[BATCH];
__device__ int g_is_byte[2];

// ---------------- PTX helpers --------------------------------------------------
__device__ __forceinline__ uint32_t sptr(const void* p) {
    uint32_t a;
    asm("{ .reg .u64 t; cvta.to.shared.u64 t, %1; cvt.u32.u64 %0, t; }"
        : "=r"(a) : "l"(p));
    return a;
}
__device__ __forceinline__ uint32_t h2ex2(uint32_t x) {
    uint32_t r;
    asm("ex2.approx.f16x2 %0, %1;" : "=r"(r) : "r"(x));
    return r;
}

#define MMA_F16(C, A, B) \
    asm volatile( \
        "mma.sync.aligned.m16n8k16.row.col.f32.f16.f16.f32 " \
        "{%0,%1,%2,%3}, {%4,%5,%6,%7}, {%8,%9}, {%0,%1,%2,%3};" \
        : "+f"((C)[0]), "+f"((C)[1]), "+f"((C)[2]), "+f"((C)[3]) \
        : "r"((A)[0]), "r"((A)[1]), "r"((A)[2]), "r"((A)[3]), \
          "r"((B)[0]), "r"((B)[1]))

#define LDSM4(R0, R1, R2, R3, ADDR) \
    asm volatile("ldmatrix.sync.aligned.m8n8.x4.shared.b16 {%0,%1,%2,%3}, [%4];" \
        : "=r"(R0), "=r"(R1), "=r"(R2), "=r"(R3) : "r"(ADDR))

#define CP16(DST, SRC) \
    asm volatile("cp.async.cg.shared.global [%0], [%1], 16;" \
        :: "r"(DST), "l"(SRC))
#define CP_COMMIT() asm volatile("cp.async.commit_group;" ::: "memory")
#define CP_WAIT0()  asm volatile("cp.async.wait_group 0;" ::: "memory")

// ---------------- fp16 GEMM mainloop (double-buffered, 1 sync/chunk) -----------
__device__ __forceinline__ void gemm16_mainloop(
        const __half* __restrict__ A, const int* __restrict__ ridx,
        const __half* __restrict__ B, float (&c)[2][8][4]) {
    __shared__ __align__(16) __half As[2][128][40];
    __shared__ __align__(16) __half Bs[2][128][40];
    const int tid = threadIdx.x;
    const int lane = tid & 31, wid = tid >> 5;
    const int wm = wid & 3, wn = wid >> 2;

    #pragma unroll
    for (int mt = 0; mt < 2; mt++)
        #pragma unroll
        for (int nt = 0; nt < 8; nt++)
            #pragma unroll
            for (int j = 0; j < 4; j++) c[mt][nt][j] = 0.0f;

    const uint32_t a_base = sptr(&As[0][wm * 32 + ((lane & 8) ? 8 : 0) + (lane & 7)]
                                      [(lane & 16) ? 8 : 0]);
    const uint32_t b_base = sptr(&Bs[0][wn * 64 + ((lane & 16) ? 8 : 0) + (lane & 7)]
                                      [(lane & 8) ? 8 : 0]);
    const uint32_t BUFB = 128 * 40 * 2;   // byte stride between buffers

    const int r0 = tid >> 2, r1 = r0 + 64;
    const int f0 = (tid & 3) * 8;
    const __half* A0 = A + (size_t)(ridx ? ridx[r0] : r0) * EMB + f0;
    const __half* A1 = A + (size_t)(ridx ? ridx[r1] : r1) * EMB + f0;
    const __half* B0 = B + (size_t)r0 * EMB + f0;
    const __half* B1 = B + (size_t)r1 * EMB + f0;

    uint4 pa0 = *(const uint4*)A0, pa1 = *(const uint4*)A1;
    uint4 pb0 = *(const uint4*)B0, pb1 = *(const uint4*)B1;

    for (int ch = 0; ch < 16; ch++) {
        const int buf = ch & 1;
        *(uint4*)&As[buf][r0][f0] = pa0;  *(uint4*)&As[buf][r1][f0] = pa1;
        *(uint4*)&Bs[buf][r0][f0] = pb0;  *(uint4*)&Bs[buf][r1][f0] = pb1;
        if (ch + 1 < 16) {
            int co = (ch + 1) * 32;
            pa0 = *(const uint4*)(A0 + co);
            pa1 = *(const uint4*)(A1 + co);
            pb0 = *(const uint4*)(B0 + co);
            pb1 = *(const uint4*)(B1 + co);
        }
        __syncthreads();
        const uint32_t ab = a_base + buf * BUFB;
        const uint32_t bb = b_base + buf * BUFB;
        #pragma unroll
        for (int ks = 0; ks < 2; ks++) {
            uint32_t a[2][4], b[8][2];
            #pragma unroll
            for (int mt = 0; mt < 2; mt++)
                LDSM4(a[mt][0], a[mt][1], a[mt][2], a[mt][3],
                      ab + mt * 1280 + ks * 32);
            #pragma unroll
            for (int p = 0; p < 4; p++)
                LDSM4(b[2*p][0], b[2*p][1], b[2*p+1][0], b[2*p+1][1],
                      bb + p * 1280 + ks * 32);
            #pragma unroll
            for (int mt = 0; mt < 2; mt++)
                #pragma unroll
                for (int nt = 0; nt < 8; nt++)
                    MMA_F16(c[mt][nt], a[mt], b[nt]);
        }
    }
}

// Q/K/V projections. z=0: Q (scaled 0.125), z=1: K (gathered), z=2: V^T (gathered).
__global__ void __launch_bounds__(256, 2) proj_qkv_kernel(
        const __half* __restrict__ qn, const __half* __restrict__ kvn,
        const __half* __restrict__ wt,
        const float* __restrict__ bq, const float* __restrict__ bk,
        const float* __restrict__ bv,
        __half* __restrict__ q, __half* __restrict__ k,
        __half* __restrict__ vt) {
    const int z = blockIdx.z;
    const size_t bm = (size_t)blockIdx.y * 128, bn = (size_t)blockIdx.x * 128;
    const int bb = (int)(bm >> 11);
    const int rloc = (int)(bm & 2047);

    const int* ridx = nullptr;
    const __half* A;
    if (z == 0) {
        A = qn + bm * EMB;
    } else {
        if (rloc >= g_nkt[bb] * 64) return;
        A = kvn + (size_t)bb * 2048 * EMB;
        ridx = g_kidx + bb * NK + rloc;
    }
    const __half* B = wt + (size_t)z * EMB * EMB + bn * EMB;
    float c[2][8][4];
    gemm16_mainloop(A, ridx, B, c);

    const int tid = threadIdx.x, lane = tid & 31, wid = tid >> 5;
    const int wm = wid & 3, wn = wid >> 2, g = lane >> 2, t = lane & 3;
    const float* bias = (z == 0) ? bq : (z == 1) ? bk : bv;
    const float scale = (z == 0) ? 0.125f : 1.0f;

    #pragma unroll
    for (int mt = 0; mt < 2; mt++) {
        #pragma unroll
        for (int nt = 0; nt < 8; nt++) {
            int m   = (int)bm + wm * 32 + mt * 16 + g;
            int col = (int)bn + wn * 64 + nt * 8 + 2 * t;
            float b0 = bias[col], b1 = bias[col + 1];
            float v0 = (c[mt][nt][0] + b0) * scale;
            float v1 = (c[mt][nt][1] + b1) * scale;
            float v2 = (c[mt][nt][2] + b0) * scale;
            float v3 = (c[mt][nt][3] + b1) * scale;
            if (z < 2) {
                __half* dst = (z == 0) ? q : k;
                *(half2*)(dst + (size_t)m * EMB + col) = __floats2half2_rn(v0, v1);
                *(half2*)(dst + (size_t)(m + 8) * EMB + col) = __floats2half2_rn(v2, v3);
            } else {
                int h = col >> 6, d = col & 63;
                int b_ = m >> 11;
                size_t base = ((size_t)(b_ * NH + h) * HD);
                int tok = m & 2047;
                vt[(base + d) * NK + tok]         = __float2half_rn(v0);
                vt[(base + d + 1) * NK + tok]     = __float2half_rn(v1);
                vt[(base + d) * NK + tok + 8]     = __float2half_rn(v2);
                vt[(base + d + 1) * NK + tok + 8] = __float2half_rn(v3);
            }
        }
    }
}

__global__ void __launch_bounds__(256, 2) proj_o_kernel(
        const __half* __restrict__ ctx, const __half* __restrict__ wt,
        const float* __restrict__ bo, float* __restrict__ out) {
    const size_t bm = (size_t)blockIdx.y * 128, bn = (size_t)blockIdx.x * 128;
    float c[2][8][4];
    gemm16_mainloop(ctx + bm * EMB, nullptr,
                    wt + 3ull * EMB * EMB + bn * EMB, c);

    const int tid = threadIdx.x, lane = tid & 31, wid = tid >> 5;
    const int wm = wid & 3, wn = wid >> 2, g = lane >> 2, t = lane & 3;
    #pragma unroll
    for (int mt = 0; mt < 2; mt++) {
        #pragma unroll
        for (int nt = 0; nt < 8; nt++) {
            int m   = (int)bm + wm * 32 + mt * 16 + g;
            int col = (int)bn + wn * 64 + nt * 8 + 2 * t;
            float b0 = bo[col], b1 = bo[col + 1];
            *(float2*)(out + (size_t)m * EMB + col) =
                make_float2(c[mt][nt][0] + b0, c[mt][nt][1] + b1);
            *(float2*)(out + (size_t)(m + 8) * EMB + col) =
                make_float2(c[mt][nt][2] + b0, c[mt][nt][3] + b1);
        }
    }
}

// ---------------- fused flash attention -----------------------------------------
// Dynamic smem layout (halves):
//   Ks : [2][64][72]  at 0        (buf byte-stride  9216)
//   Vst: [2][80][72]  at 9216h    (buf byte-stride 11520; rows 64..79 = ones/zeros)
//   Ps : [128][72]    at 20736h
#define FATTN_SMEM 59904
__global__ void __launch_bounds__(256, 2) fattn_kernel(
        const __half* __restrict__ Qp, const __half* __restrict__ Kp,
        const __half* __restrict__ Vtp,
        const unsigned long long* __restrict__ mbits,
        __half* __restrict__ ctx) {
    extern __shared__ __align__(16) __half smd[];
    __half* KsB = smd;
    __half* VsB = smd + 9216;
    __half (*Ps)[72] = (__half(*)[72])(smd + 20736);

    const int tid = threadIdx.x;
    const int lane = tid & 31, w = tid >> 5;
    const int g = lane >> 2, t = lane & 3;
    const int qt = blockIdx.x, bh = blockIdx.y;
    const int b = bh >> 3, h = bh & 7;
    const int row0 = w * 16 + g, row1 = row0 + 8;
    const int nkt = g_nkt[b];

    const uint32_t ks_smem = sptr(KsB);
    const uint32_t vs_smem = sptr(VsB);
    const uint32_t lrow = ((lane & 16) ? 8 : 0) + (lane & 7);
    const uint32_t k_base = ks_smem + lrow * 144 + ((lane & 8) ? 16 : 0);
    const uint32_t v_base = vs_smem + lrow * 144 + ((lane & 8) ? 16 : 0);
    const uint32_t p_base = sptr(&Ps[w * 16 + ((lane & 8) ? 8 : 0) + (lane & 7)]
                                    [(lane & 16) ? 8 : 0]);

    // init ones/zeros rows 64..79 of both V buffers (row 64 = 1, rest 0)
    for (int idx = tid; idx < 2 * 16 * 72; idx += 256) {
        int bufr = idx / 72, col = idx % 72;
        int buf = bufr >> 4, row = 64 + (bufr & 15);
        VsB[buf * 5760 + row * 72 + col] =
            (row == 64) ? __float2half(1.0f) : __float2half(0.0f);
    }

    // Q fragments (pre-scaled fp16)
    uint32_t qa[4][4];
    {
        const __half* q0 = Qp + (size_t)(b * NQ + qt * 128 + row0) * EMB + h * HD;
        const __half* q1 = Qp + (size_t)(b * NQ + qt * 128 + row1) * EMB + h * HD;
        #pragma unroll
        for (int ks = 0; ks < 4; ks++) {
            qa[ks][0] = *(const uint32_t*)(q0 + ks * 16 + 2 * t);
            qa[ks][1] = *(const uint32_t*)(q1 + ks * 16 + 2 * t);
            qa[ks][2] = *(const uint32_t*)(q0 + ks * 16 + 2 * t + 8);
            qa[ks][3] = *(const uint32_t*)(q1 + ks * 16 + 2 * t + 8);
        }
    }

    float m0 = -40.0f, m1 = -40.0f;
    float acc[9][4];
    #pragma unroll
    for (int nt = 0; nt < 9; nt++)
        #pragma unroll
        for (int j = 0; j < 4; j++) acc[nt][j] = 0.0f;

    const unsigned long long* mb0 =
        mbits + ((size_t)b * NQ + qt * 128 + row0) * (NK / 64);
    const unsigned long long* mb1 =
        mbits + ((size_t)b * NQ + qt * 128 + row1) * (NK / 64);

    const __half* Kbase  = Kp + ((size_t)b * NK) * EMB + h * HD;
    const __half* Vtbase = Vtp + (size_t)bh * HD * NK;

    const int sr = tid >> 2;             // 0..63 staging row (tid + 256 -> same r+32? no: use two slots)
    // staging helper indices: slot i covers r = (tid + i*256)>>3, f = (tid+i*256)&7
    const float L2E = 1.4426950408889634f;

    // prologue: stage tile 0 into buf 0
    if (nkt > 0) {
        #pragma unroll
        for (int i = 0; i < 2; i++) {
            int s = tid + i * 256;
            int r = s >> 3, f = s & 7;
            CP16(ks_smem + r * 144 + f * 16,
                 Kbase + (size_t)r * EMB + f * 8);
            CP16(vs_smem + r * 144 + f * 16,
                 Vtbase + (size_t)r * NK + f * 8);
        }
        CP_COMMIT();
    }

    for (int kt = 0; kt < nkt; kt++) {
        const int buf = kt & 1;
        CP_WAIT0();
        __syncthreads();                   // data ready + all warps done with other buf

        if (kt + 1 < nkt) {                // stage next tile into other buffer
            int k0n = (kt + 1) * 64;
            int nbuf = buf ^ 1;
            #pragma unroll
            for (int i = 0; i < 2; i++) {
                int s = tid + i * 256;
                int r = s >> 3, f = s & 7;
                CP16(ks_smem + nbuf * 9216 + r * 144 + f * 16,
                     Kbase + (size_t)(k0n + r) * EMB + f * 8);
                CP16(vs_smem + nbuf * 11520 + r * 144 + f * 16,
                     Vtbase + (size_t)r * NK + k0n + f * 8);
            }
            CP_COMMIT();
        }

        // S = Q @ K^T
        float sc[8][4];
        #pragma unroll
        for (int nt = 0; nt < 8; nt++)
            #pragma unroll
            for (int j = 0; j < 4; j++) sc[nt][j] = 0.0f;
        const uint32_t kb = k_base + buf * 9216;
        #pragma unroll
        for (int ks = 0; ks < 4; ks++) {
            uint32_t bf[8][2];
            #pragma unroll
            for (int p = 0; p < 4; p++)
                LDSM4(bf[2*p][0], bf[2*p][1], bf[2*p+1][0], bf[2*p+1][1],
                      kb + p * 16 * 144 + ks * 32);
            #pragma unroll
            for (int nt = 0; nt < 8; nt++)
                MMA_F16(sc[nt], qa[ks], bf[nt]);
        }

        // mask + tile max
        unsigned long long w0 = mb0[kt], w1 = mb1[kt];
        float tm0 = -1e30f, tm1 = -1e30f;
        #pragma unroll
        for (int nt = 0; nt < 8; nt++) {
            int c0 = nt * 8 + 2 * t;
            sc[nt][0] = ((w0 >> c0) & 1)       ? sc[nt][0] : -1e30f;
            sc[nt][1] = ((w0 >> (c0 + 1)) & 1) ? sc[nt][1] : -1e30f;
            sc[nt][2] = ((w1 >> c0) & 1)       ? sc[nt][2] : -1e30f;
            sc[nt][3] = ((w1 >> (c0 + 1)) & 1) ? sc[nt][3] : -1e30f;
            tm0 = fmaxf(tm0, fmaxf(sc[nt][0], sc[nt][1]));
            tm1 = fmaxf(tm1, fmaxf(sc[nt][2], sc[nt][3]));
        }
        tm0 = fmaxf(tm0, __shfl_xor_sync(0xffffffffu, tm0, 1));
        tm0 = fmaxf(tm0, __shfl_xor_sync(0xffffffffu, tm0, 2));
        tm1 = fmaxf(tm1, __shfl_xor_sync(0xffffffffu, tm1, 1));
        tm1 = fmaxf(tm1, __shfl_xor_sync(0xffffffffu, tm1, 2));

        float mn0 = fmaxf(m0, tm0), mn1 = fmaxf(m1, tm1);  // >= -40 always
        float corr0 = exp2f((m0 - mn0) * L2E);
        float corr1 = exp2f((m1 - mn1) * L2E);
        float mnl0 = mn0 * L2E, mnl1 = mn1 * L2E;

        __syncwarp();                     // prev PV reads of Ps done
        #pragma unroll
        for (int nt = 0; nt < 8; nt++) {
            int c0 = nt * 8 + 2 * t;
            // (s - mn)*log2e <= 0; masked -> -inf -> ex2 -> 0
            half2 h0 = __floats2half2_rn(fmaf(sc[nt][0], L2E, -mnl0),
                                         fmaf(sc[nt][1], L2E, -mnl0));
            half2 h1 = __floats2half2_rn(fmaf(sc[nt][2], L2E, -mnl1),
                                         fmaf(sc[nt][3], L2E, -mnl1));
            *(uint32_t*)&Ps[row0][c0] = h2ex2(*(uint32_t*)&h0);
            *(uint32_t*)&Ps[row1][c0] = h2ex2(*(uint32_t*)&h1);
        }
        m0 = mn0;  m1 = mn1;
        #pragma unroll
        for (int nt = 0; nt < 9; nt++) {
            acc[nt][0] *= corr0; acc[nt][1] *= corr0;
            acc[nt][2] *= corr1; acc[nt][3] *= corr1;
        }
        __syncwarp();                     // Ps visible to warp

        // O += P @ V  (tile nt=8 is the ones-column -> running row sum l)
        const uint32_t vb = v_base + buf * 11520;
        #pragma unroll
        for (int ks = 0; ks < 4; ks++) {
            uint32_t pa[4], bv[10][2];
            LDSM4(pa[0], pa[1], pa[2], pa[3], p_base + ks * 32);
            #pragma unroll
            for (int p = 0; p < 5; p++)
                LDSM4(bv[2*p][0], bv[2*p][1], bv[2*p+1][0], bv[2*p+1][1],
                      vb + p * 16 * 144 + ks * 32);
            #pragma unroll
            for (int nt = 0; nt < 9; nt++)
                MMA_F16(acc[nt], pa, bv[nt]);
        }
        __syncthreads();                  // all warps done reading buf before reuse
    }

    // l for row0/row1 lives in acc[8][0]/acc[8][2] of the t==0 lane of each quad
    float l0 = __shfl_sync(0xffffffffu, acc[8][0], lane & 28);
    float l1 = __shfl_sync(0xffffffffu, acc[8][2], lane & 28);
    float inv0 = (l0 > 0.0f) ? (1.0f / l0) : 0.0f;
    float inv1 = (l1 > 0.0f) ? (1.0f / l1) : 0.0f;
    __half* o0 = ctx + (size_t)(b * NQ + qt * 128 + row0) * EMB + h * HD;
    __half* o1 = ctx + (size_t)(b * NQ + qt * 128 + row1) * EMB + h * HD;
    #pragma unroll
    for (int nt = 0; nt < 8; nt++) {
        int c0 = nt * 8 + 2 * t;
        *(half2*)(o0 + c0) = __floats2half2_rn(acc[nt][0] * inv0, acc[nt][1] * inv0);
        *(half2*)(o1 + c0) = __floats2half2_rn(acc[nt][2] * inv1, acc[nt][3] * inv1);
    }
}

// ---------------- mask dtype sniff ---------------------------------------------
__global__ void detect_mask_kernel(const unsigned char* kvm_raw,
                                   const unsigned char* spm_raw) {
    __shared__ int found[2];
    if (threadIdx.x == 0) { found[0] = 0; found[1] = 0; }
    __syncthreads();
    for (int i = threadIdx.x; i < 8192; i += blockDim.x) {
        if ((i & 3) != 0) {
            if (kvm_raw[i]) atomicOr(&found[0], 1);
            if (spm_raw[i]) atomicOr(&found[1], 1);
        }
    }
    __syncthreads();
    if (threadIdx.x == 0) { g_is_byte[0] = found[0]; g_is_byte[1] = found[1]; }
}

// ---------------- kv_mask stream compaction -------------------------------------
__global__ void compact_idx_kernel(const void* kvm_raw) {
    const int b = blockIdx.x;
    const int tid = threadIdx.x;
    const int lane = tid & 31, w = tid >> 5;
    __shared__ int base;
    __shared__ int wstart[8];
    __shared__ int wcnt[8];
    if (tid == 0) base = 0;
    __syncthreads();
    const bool kb = g_is_byte[0] != 0;
    for (int c0 = 0; c0 < NK; c0 += 256) {
        int kk = c0 + tid;
        bool v = kb ? (((const unsigned char*)kvm_raw)[b * NK + kk] != 0)
                    : (((const int*)kvm_raw)[b * NK + kk] != 0);
        unsigned bal = __ballot_sync(0xffffffffu, v);
        if (lane == 0) wcnt[w] = __popc(bal);
        __syncthreads();
        if (tid == 0) {
            int s = base;
            #pragma unroll
            for (int i = 0; i < 8; i++) { wstart[i] = s; s += wcnt[i]; }
            base = s;
        }
        __syncthreads();
        if (v)
            g_kidx[b * NK + wstart[w] + __popc(bal & ((1u << lane) - 1))] = kk;
        __syncthreads();
    }
    int nv = base;
    for (int c = nv + tid; c < NK; c += 256) g_kidx[b * NK + c] = 0;
    if (tid == 0) {
        g_nvalid[b] = nv;
        g_nkt[b] = (nv + 63) >> 6;
    }
}

// ---------------- sparse-mask bits over compacted columns -----------------------
__global__ void mask_bits_kernel(const void* spm_raw) {
    int idx = blockIdx.x * blockDim.x + threadIdx.x;
    int ct = idx & 31;
    int bq = idx >> 5;
    int b = bq >> 11;
    int nv = g_nvalid[b];
    int cbase = ct * 64;
    int lim = nv - cbase;
    if (lim > 64) lim = 64;
    unsigned long long bits = 0;
    if (lim > 0) {
        const int* kidx = g_kidx + b * NK + cbase;
        if (g_is_byte[1]) {
            const unsigned char* sp = (const unsigned char*)spm_raw + (size_t)bq * NK;
            for (int j = 0; j < lim; j++)
                if (sp[kidx[j]]) bits |= 1ULL << j;
        } else {
            const int* sp = (const int*)spm_raw + (size_t)bq * NK;
            for (int j = 0; j < lim; j++)
                if (sp[kidx[j]]) bits |= 1ULL << j;
        }
    }
    g_mbits[idx] = bits;
}

// ---------------- LayerNorm ------------------------------------------------------
__global__ void lnorm_kernel(const float* __restrict__ xq,
                             const float* __restrict__ xkv,
                             const float* __restrict__ gq,
                             const float* __restrict__ bq,
                             const float* __restrict__ gkv,
                             const float* __restrict__ bkv,
                             __half* __restrict__ yq,
                             __half* __restrict__ ykv) {
    __shared__ float red[8];
    int row = blockIdx.x, t = threadIdx.x;
    const float* x = blockIdx.y ? xkv : xq;
    const float* g = blockIdx.y ? gkv : gq;
    const float* b = blockIdx.y ? bkv : bq;
    __half* y      = blockIdx.y ? ykv : yq;

    float4 v = ((const float4*)(x + (size_t)row * EMB))[t];
    float s  = v.x + v.y + v.z + v.w;
    float s2 = v.x*v.x + v.y*v.y + v.z*v.z + v.w*v.w;
    #pragma unroll
    for (int o = 16; o > 0; o >>= 1) {
        s  += __shfl_xor_sync(0xffffffffu, s,  o);
        s2 += __shfl_xor_sync(0xffffffffu, s2, o);
    }
    if ((t & 31) == 0) { red[t >> 5] = s; red[4 + (t >> 5)] = s2; }
    __syncthreads();
    float tot  = red[0] + red[1] + red[2] + red[3];
    float tot2 = red[4] + red[5] + red[6] + red[7];
    float mu  = tot * (1.0f / EMB);
    float var = tot2 * (1.0f / EMB) - mu * mu;
    float inv = rsqrtf(var + 1e-5f);
    float4 gg = ((const float4*)g)[t];
    float4 bb = ((const float4*)b)[t];
    float o0 = (v.x - mu) * inv * gg.x + bb.x;
    float o1 = (v.y - mu) * inv * gg.y + bb.y;
    float o2 = (v.z - mu) * inv * gg.z + bb.z;
    float o3 = (v.w - mu) * inv * gg.w + bb.w;
    __half* yr = y + (size_t)row * EMB + t * 4;
    *(half2*)(yr)     = __floats2half2_rn(o0, o1);
    *(half2*)(yr + 2) = __floats2half2_rn(o2, o3);
}

// ---------------- weight transpose ------------------------------------------------
__global__ void wt_kernel(const float* __restrict__ Wq,
                          const float* __restrict__ Wk,
                          const float* __restrict__ Wv,
                          const float* __restrict__ Wo,
                          __half* __restrict__ Wt) {
    __shared__ float tile[32][33];
    int z = blockIdx.z;
    const float* W = (z == 0) ? Wq : (z == 1) ? Wk : (z == 2) ? Wv : Wo;
    __half* dst = Wt + (size_t)z * EMB * EMB;
    int bx = blockIdx.x * 32, by = blockIdx.y * 32;
    int tx = threadIdx.x, ty = threadIdx.y;
    #pragma unroll
    for (int i = 0; i < 4; i++)
        tile[ty + i * 8][tx] = W[(size_t)(by + ty + i * 8) * EMB + bx + tx];
    __syncthreads();
    #pragma unroll
    for (int i = 0; i < 4; i++)
        dst[(size_t)(bx + ty + i * 8) * EMB + by + tx] =
            __float2half_rn(tile[tx][ty + i * 8]);
}

// ---------------- launch ----------------------------------------------------------
extern "C" void kernel_launch(void* const* d_in, const int* in_sizes, int n_in,
                              void* d_out, int out_size) {
    const float* query     = (const float*)d_in[0];
    const float* key_value = (const float*)d_in[1];
    const void*  kvm_raw   = d_in[2];
    const void*  spm_raw   = d_in[3];
    const float* ln_q_g  = (const float*)d_in[4];
    const float* ln_q_b  = (const float*)d_in[5];
    const float* ln_kv_g = (const float*)d_in[6];
    const float* ln_kv_b = (const float*)d_in[7];
    const float* Wq = (const float*)d_in[8];
    const float* bq = (const float*)d_in[9];
    const float* Wk = (const float*)d_in[10];
    const float* bk = (const float*)d_in[11];
    const float* Wv = (const float*)d_in[12];
    const float* bv = (const float*)d_in[13];
    const float* Wo = (const float*)d_in[14];
    const float* bo = (const float*)d_in[15];
    float* out = (float*)d_out;

    void *p_qn, *p_kvn, *p_q, *p_k, *p_vt, *p_ctx, *p_wt, *p_mb;
    cudaGetSymbolAddress(&p_qn,  g_qn);
    cudaGetSymbolAddress(&p_kvn, g_kvn);
    cudaGetSymbolAddress(&p_q,   g_q);
    cudaGetSymbolAddress(&p_k,   g_k);
    cudaGetSymbolAddress(&p_vt,  g_vt);
    cudaGetSymbolAddress(&p_ctx, g_ctx);
    cudaGetSymbolAddress(&p_wt,  g_wt);
    cudaGetSymbolAddress(&p_mb,  g_mbits);

    detect_mask_kernel<<<1, 256>>>((const unsigned char*)kvm_raw,
                                   (const unsigned char*)spm_raw);
    compact_idx_kernel<<<BATCH, 256>>>(kvm_raw);
    mask_bits_kernel<<<(BATCH * NQ * (NK / 64)) / 256, 256>>>(spm_raw);

    dim3 lg(NTOK, 2);
    lnorm_kernel<<<lg, 128>>>(query, key_value, ln_q_g, ln_q_b,
                              ln_kv_g, ln_kv_b,
                              (__half*)p_qn, (__half*)p_kvn);

    dim3 tb(32, 8), tg(16, 16, 4);
    wt_kernel<<<tg, tb>>>(Wq, Wk, Wv, Wo, (__half*)p_wt);

    dim3 pg(EMB / 128, NTOK / 128, 3);
    proj_qkv_kernel<<<pg, 256>>>((const __half*)p_qn, (const __half*)p_kvn,
                                 (const __half*)p_wt, bq, bk, bv,
                                 (__half*)p_q, (__half*)p_k, (__half*)p_vt);

    cudaFuncSetAttribute(fattn_kernel,
        cudaFuncAttributeMaxDynamicSharedMemorySize, FATTN_SMEM);
    dim3 fg(NQ / 128, BHN);
    fattn_kernel<<<fg, 256, FATTN_SMEM>>>((const __half*)p_q, (const __half*)p_k,
                              (const __half*)p_vt,
                              (const unsigned long long*)p_mb,
                              (__half*)p_ctx);

    dim3 og(EMB / 128, NTOK / 128);
    proj_o_kernel<<<og, 256>>>((const __half*)p_ctx, (const __half*)p_wt,
                               bo, out);
}

// round 10
// speedup vs baseline: 1.9285x; 1.0151x over previous
#include <cuda_runtime.h>
#include <cuda_fp16.h>
#include <cstdint>
#include <cstddef>

#define BATCH 4
#define NQ    2048
#define NK    2048
#define EMB   512
#define NH    8
#define HD    64
#define NTOK  (BATCH * NQ)
#define BHN   (BATCH * NH)

// ---------------- device-global scratch ---------------------------------------
__device__ __half g_qn [NTOK * EMB];
__device__ __half g_kvn[NTOK * EMB];
__device__ __half g_q  [NTOK * EMB];          // pre-scaled by 0.125*log2(e)
__device__ __half g_k  [NTOK * EMB];          // COMPACTED rows per batch
__device__ __half g_vt [BHN * HD * NK];       // V^T per (b,h): [d][compacted key]
__device__ __half g_ctx[NTOK * EMB];
__device__ __half g_wt [4 * EMB * EMB];       // W^T, k-major rows
__device__ unsigned long long g_mbits[(size_t)BATCH * NQ * (NK / 64)];
__device__ int g_kidx[BATCH * NK];
__device__ int g_nvalid[BATCH];
__device__ int g_nkt[BATCH];
__device__ int g_is_byte[2];

// ---------------- PTX helpers --------------------------------------------------
__device__ __forceinline__ uint32_t sptr(const void* p) {
    uint32_t a;
    asm("{ .reg .u64 t; cvta.to.shared.u64 t, %1; cvt.u32.u64 %0, t; }"
        : "=r"(a) : "l"(p));
    return a;
}
__device__ __forceinline__ uint32_t h2ex2(uint32_t x) {
    uint32_t r;
    asm("ex2.approx.f16x2 %0, %1;" : "=r"(r) : "r"(x));
    return r;
}

#define MMA_F16(C, A, B) \
    asm volatile( \
        "mma.sync.aligned.m16n8k16.row.col.f32.f16.f16.f32 " \
        "{%0,%1,%2,%3}, {%4,%5,%6,%7}, {%8,%9}, {%0,%1,%2,%3};" \
        : "+f"((C)[0]), "+f"((C)[1]), "+f"((C)[2]), "+f"((C)[3]) \
        : "r"((A)[0]), "r"((A)[1]), "r"((A)[2]), "r"((A)[3]), \
          "r"((B)[0]), "r"((B)[1]))

#define LDSM4(R0, R1, R2, R3, ADDR) \
    asm volatile("ldmatrix.sync.aligned.m8n8.x4.shared.b16 {%0,%1,%2,%3}, [%4];" \
        : "=r"(R0), "=r"(R1), "=r"(R2), "=r"(R3) : "r"(ADDR))

#define CP16(DST, SRC) \
    asm volatile("cp.async.cg.shared.global [%0], [%1], 16;" \
        :: "r"(DST), "l"(SRC))
#define CP_COMMIT() asm volatile("cp.async.commit_group;" ::: "memory")
#define CP_WAIT0()  asm volatile("cp.async.wait_group 0;" ::: "memory")

// ---------------- fp16 GEMM mainloop (double-buffered, 1 sync/chunk) -----------
__device__ __forceinline__ void gemm16_mainloop(
        const __half* __restrict__ A, const int* __restrict__ ridx,
        const __half* __restrict__ B, float (&c)[2][8][4]) {
    __shared__ __align__(16) __half As[2][128][40];
    __shared__ __align__(16) __half Bs[2][128][40];
    const int tid = threadIdx.x;
    const int lane = tid & 31, wid = tid >> 5;
    const int wm = wid & 3, wn = wid >> 2;

    #pragma unroll
    for (int mt = 0; mt < 2; mt++)
        #pragma unroll
        for (int nt = 0; nt < 8; nt++)
            #pragma unroll
            for (int j = 0; j < 4; j++) c[mt][nt][j] = 0.0f;

    const uint32_t a_base = sptr(&As[0][wm * 32 + ((lane & 8) ? 8 : 0) + (lane & 7)]
                                      [(lane & 16) ? 8 : 0]);
    const uint32_t b_base = sptr(&Bs[0][wn * 64 + ((lane & 16) ? 8 : 0) + (lane & 7)]
                                      [(lane & 8) ? 8 : 0]);
    const uint32_t BUFB = 128 * 40 * 2;

    const int r0 = tid >> 2, r1 = r0 + 64;
    const int f0 = (tid & 3) * 8;
    const __half* A0 = A + (size_t)(ridx ? ridx[r0] : r0) * EMB + f0;
    const __half* A1 = A + (size_t)(ridx ? ridx[r1] : r1) * EMB + f0;
    const __half* B0 = B + (size_t)r0 * EMB + f0;
    const __half* B1 = B + (size_t)r1 * EMB + f0;

    uint4 pa0 = *(const uint4*)A0, pa1 = *(const uint4*)A1;
    uint4 pb0 = *(const uint4*)B0, pb1 = *(const uint4*)B1;

    for (int ch = 0; ch < 16; ch++) {
        const int buf = ch & 1;
        *(uint4*)&As[buf][r0][f0] = pa0;  *(uint4*)&As[buf][r1][f0] = pa1;
        *(uint4*)&Bs[buf][r0][f0] = pb0;  *(uint4*)&Bs[buf][r1][f0] = pb1;
        if (ch + 1 < 16) {
            int co = (ch + 1) * 32;
            pa0 = *(const uint4*)(A0 + co);
            pa1 = *(const uint4*)(A1 + co);
            pb0 = *(const uint4*)(B0 + co);
            pb1 = *(const uint4*)(B1 + co);
        }
        __syncthreads();
        const uint32_t ab = a_base + buf * BUFB;
        const uint32_t bb = b_base + buf * BUFB;
        #pragma unroll
        for (int ks = 0; ks < 2; ks++) {
            uint32_t a[2][4], b[8][2];
            #pragma unroll
            for (int mt = 0; mt < 2; mt++)
                LDSM4(a[mt][0], a[mt][1], a[mt][2], a[mt][3],
                      ab + mt * 1280 + ks * 32);
            #pragma unroll
            for (int p = 0; p < 4; p++)
                LDSM4(b[2*p][0], b[2*p][1], b[2*p+1][0], b[2*p+1][1],
                      bb + p * 1280 + ks * 32);
            #pragma unroll
            for (int mt = 0; mt < 2; mt++)
                #pragma unroll
                for (int nt = 0; nt < 8; nt++)
                    MMA_F16(c[mt][nt], a[mt], b[nt]);
        }
    }
}

// Q/K/V projections. z=0: Q (scaled 0.125*log2e), z=1: K (gathered), z=2: V^T.
__global__ void __launch_bounds__(256, 2) proj_qkv_kernel(
        const __half* __restrict__ qn, const __half* __restrict__ kvn,
        const __half* __restrict__ wt,
        const float* __restrict__ bq, const float* __restrict__ bk,
        const float* __restrict__ bv,
        __half* __restrict__ q, __half* __restrict__ k,
        __half* __restrict__ vt) {
    const int z = blockIdx.z;
    const size_t bm = (size_t)blockIdx.y * 128, bn = (size_t)blockIdx.x * 128;
    const int bb = (int)(bm >> 11);
    const int rloc = (int)(bm & 2047);

    const int* ridx = nullptr;
    const __half* A;
    if (z == 0) {
        A = qn + bm * EMB;
    } else {
        if (rloc >= g_nkt[bb] * 64) return;
        A = kvn + (size_t)bb * 2048 * EMB;
        ridx = g_kidx + bb * NK + rloc;
    }
    const __half* B = wt + (size_t)z * EMB * EMB + bn * EMB;
    float c[2][8][4];
    gemm16_mainloop(A, ridx, B, c);

    const int tid = threadIdx.x, lane = tid & 31, wid = tid >> 5;
    const int wm = wid & 3, wn = wid >> 2, g = lane >> 2, t = lane & 3;
    const float* bias = (z == 0) ? bq : (z == 1) ? bk : bv;
    const float scale = (z == 0) ? 0.1803368801111244f : 1.0f;  // 0.125*log2(e)

    #pragma unroll
    for (int mt = 0; mt < 2; mt++) {
        #pragma unroll
        for (int nt = 0; nt < 8; nt++) {
            int m   = (int)bm + wm * 32 + mt * 16 + g;
            int col = (int)bn + wn * 64 + nt * 8 + 2 * t;
            float b0 = bias[col], b1 = bias[col + 1];
            float v0 = (c[mt][nt][0] + b0) * scale;
            float v1 = (c[mt][nt][1] + b1) * scale;
            float v2 = (c[mt][nt][2] + b0) * scale;
            float v3 = (c[mt][nt][3] + b1) * scale;
            if (z < 2) {
                __half* dst = (z == 0) ? q : k;
                *(half2*)(dst + (size_t)m * EMB + col) = __floats2half2_rn(v0, v1);
                *(half2*)(dst + (size_t)(m + 8) * EMB + col) = __floats2half2_rn(v2, v3);
            } else {
                int h = col >> 6, d = col & 63;
                int b_ = m >> 11;
                size_t base = ((size_t)(b_ * NH + h) * HD);
                int tok = m & 2047;
                vt[(base + d) * NK + tok]         = __float2half_rn(v0);
                vt[(base + d + 1) * NK + tok]     = __float2half_rn(v1);
                vt[(base + d) * NK + tok + 8]     = __float2half_rn(v2);
                vt[(base + d + 1) * NK + tok + 8] = __float2half_rn(v3);
            }
        }
    }
}

__global__ void __launch_bounds__(256, 2) proj_o_kernel(
        const __half* __restrict__ ctx, const __half* __restrict__ wt,
        const float* __restrict__ bo, float* __restrict__ out) {
    const size_t bm = (size_t)blockIdx.y * 128, bn = (size_t)blockIdx.x * 128;
    float c[2][8][4];
    gemm16_mainloop(ctx + bm * EMB, nullptr,
                    wt + 3ull * EMB * EMB + bn * EMB, c);

    const int tid = threadIdx.x, lane = tid & 31, wid = tid >> 5;
    const int wm = wid & 3, wn = wid >> 2, g = lane >> 2, t = lane & 3;
    #pragma unroll
    for (int mt = 0; mt < 2; mt++) {
        #pragma unroll
        for (int nt = 0; nt < 8; nt++) {
            int m   = (int)bm + wm * 32 + mt * 16 + g;
            int col = (int)bn + wn * 64 + nt * 8 + 2 * t;
            float b0 = bo[col], b1 = bo[col + 1];
            *(float2*)(out + (size_t)m * EMB + col) =
                make_float2(c[mt][nt][0] + b0, c[mt][nt][1] + b1);
            *(float2*)(out + (size_t)(m + 8) * EMB + col) =
                make_float2(c[mt][nt][2] + b0, c[mt][nt][3] + b1);
        }
    }
}

// ---------------- fused flash attention (log2-domain softmax) -------------------
// Dynamic smem layout (halves):
//   Ks : [2][64][72]  at 0        (buf byte-stride  9216)
//   Vst: [2][80][72]  at 9216h    (buf byte-stride 11520; rows 64..79 = ones/zeros)
//   Ps : [128][72]    at 20736h
#define FATTN_SMEM 59904
__global__ void __launch_bounds__(256, 2) fattn_kernel(
        const __half* __restrict__ Qp, const __half* __restrict__ Kp,
        const __half* __restrict__ Vtp,
        const unsigned long long* __restrict__ mbits,
        __half* __restrict__ ctx) {
    extern __shared__ __align__(16) __half smd[];
    __half* KsB = smd;
    __half* VsB = smd + 9216;
    __half (*Ps)[72] = (__half(*)[72])(smd + 20736);

    const int tid = threadIdx.x;
    const int lane = tid & 31, w = tid >> 5;
    const int g = lane >> 2, t = lane & 3;
    const int qt = blockIdx.x, bh = blockIdx.y;
    const int b = bh >> 3, h = bh & 7;
    const int row0 = w * 16 + g, row1 = row0 + 8;
    const int nkt = g_nkt[b];

    const uint32_t ks_smem = sptr(KsB);
    const uint32_t vs_smem = sptr(VsB);
    const uint32_t lrow = ((lane & 16) ? 8 : 0) + (lane & 7);
    const uint32_t k_base = ks_smem + lrow * 144 + ((lane & 8) ? 16 : 0);
    const uint32_t v_base = vs_smem + lrow * 144 + ((lane & 8) ? 16 : 0);
    const uint32_t p_base = sptr(&Ps[w * 16 + ((lane & 8) ? 8 : 0) + (lane & 7)]
                                    [(lane & 16) ? 8 : 0]);

    // init ones/zeros rows 64..79 of both V buffers (row 64 = 1, rest 0)
    for (int idx = tid; idx < 2 * 16 * 72; idx += 256) {
        int bufr = idx / 72, col = idx % 72;
        int buf = bufr >> 4, row = 64 + (bufr & 15);
        VsB[buf * 5760 + row * 72 + col] =
            (row == 64) ? __float2half(1.0f) : __float2half(0.0f);
    }

    // Q fragments (pre-scaled by 0.125*log2e, fp16)
    uint32_t qa[4][4];
    {
        const __half* q0 = Qp + (size_t)(b * NQ + qt * 128 + row0) * EMB + h * HD;
        const __half* q1 = Qp + (size_t)(b * NQ + qt * 128 + row1) * EMB + h * HD;
        #pragma unroll
        for (int ks = 0; ks < 4; ks++) {
            qa[ks][0] = *(const uint32_t*)(q0 + ks * 16 + 2 * t);
            qa[ks][1] = *(const uint32_t*)(q1 + ks * 16 + 2 * t);
            qa[ks][2] = *(const uint32_t*)(q0 + ks * 16 + 2 * t + 8);
            qa[ks][3] = *(const uint32_t*)(q1 + ks * 16 + 2 * t + 8);
        }
    }

    float m0 = -40.0f, m1 = -40.0f;          // log2-domain running max
    float acc[9][4];
    #pragma unroll
    for (int nt = 0; nt < 9; nt++)
        #pragma unroll
        for (int j = 0; j < 4; j++) acc[nt][j] = 0.0f;

    const unsigned long long* mb0 =
        mbits + ((size_t)b * NQ + qt * 128 + row0) * (NK / 64);
    const unsigned long long* mb1 =
        mbits + ((size_t)b * NQ + qt * 128 + row1) * (NK / 64);

    const __half* Kbase  = Kp + ((size_t)b * NK) * EMB + h * HD;
    const __half* Vtbase = Vtp + (size_t)bh * HD * NK;

    // prologue: stage tile 0 into buf 0
    if (nkt > 0) {
        #pragma unroll
        for (int i = 0; i < 2; i++) {
            int s = tid + i * 256;
            int r = s >> 3, f = s & 7;
            CP16(ks_smem + r * 144 + f * 16,
                 Kbase + (size_t)r * EMB + f * 8);
            CP16(vs_smem + r * 144 + f * 16,
                 Vtbase + (size_t)r * NK + f * 8);
        }
        CP_COMMIT();
    }

    for (int kt = 0; kt < nkt; kt++) {
        const int buf = kt & 1;
        CP_WAIT0();
        __syncthreads();

        if (kt + 1 < nkt) {
            int k0n = (kt + 1) * 64;
            int nbuf = buf ^ 1;
            #pragma unroll
            for (int i = 0; i < 2; i++) {
                int s = tid + i * 256;
                int r = s >> 3, f = s & 7;
                CP16(ks_smem + nbuf * 9216 + r * 144 + f * 16,
                     Kbase + (size_t)(k0n + r) * EMB + f * 8);
                CP16(vs_smem + nbuf * 11520 + r * 144 + f * 16,
                     Vtbase + (size_t)r * NK + k0n + f * 8);
            }
            CP_COMMIT();
        }

        // S = Q @ K^T  (scores already in log2 units)
        float sc[8][4];
        #pragma unroll
        for (int nt = 0; nt < 8; nt++)
            #pragma unroll
            for (int j = 0; j < 4; j++) sc[nt][j] = 0.0f;
        const uint32_t kb = k_base + buf * 9216;
        #pragma unroll
        for (int ks = 0; ks < 4; ks++) {
            uint32_t bf[8][2];
            #pragma unroll
            for (int p = 0; p < 4; p++)
                LDSM4(bf[2*p][0], bf[2*p][1], bf[2*p+1][0], bf[2*p+1][1],
                      kb + p * 16 * 144 + ks * 32);
            #pragma unroll
            for (int nt = 0; nt < 8; nt++)
                MMA_F16(sc[nt], qa[ks], bf[nt]);
        }

        // mask + tile max
        unsigned long long w0 = mb0[kt], w1 = mb1[kt];
        float tm0 = -1e30f, tm1 = -1e30f;
        #pragma unroll
        for (int nt = 0; nt < 8; nt++) {
            int c0 = nt * 8 + 2 * t;
            sc[nt][0] = ((w0 >> c0) & 1)       ? sc[nt][0] : -1e30f;
            sc[nt][1] = ((w0 >> (c0 + 1)) & 1) ? sc[nt][1] : -1e30f;
            sc[nt][2] = ((w1 >> c0) & 1)       ? sc[nt][2] : -1e30f;
            sc[nt][3] = ((w1 >> (c0 + 1)) & 1) ? sc[nt][3] : -1e30f;
            tm0 = fmaxf(tm0, fmaxf(sc[nt][0], sc[nt][1]));
            tm1 = fmaxf(tm1, fmaxf(sc[nt][2], sc[nt][3]));
        }
        tm0 = fmaxf(tm0, __shfl_xor_sync(0xffffffffu, tm0, 1));
        tm0 = fmaxf(tm0, __shfl_xor_sync(0xffffffffu, tm0, 2));
        tm1 = fmaxf(tm1, __shfl_xor_sync(0xffffffffu, tm1, 1));
        tm1 = fmaxf(tm1, __shfl_xor_sync(0xffffffffu, tm1, 2));

        float mn0 = fmaxf(m0, tm0), mn1 = fmaxf(m1, tm1);  // >= -40 always
        // warp-uniform skip: rescale only if any lane's max advanced
        if (__any_sync(0xffffffffu, (mn0 > m0) | (mn1 > m1))) {
            float corr0 = exp2f(m0 - mn0);
            float corr1 = exp2f(m1 - mn1);
            #pragma unroll
            for (int nt = 0; nt < 9; nt++) {
                acc[nt][0] *= corr0; acc[nt][1] *= corr0;
                acc[nt][2] *= corr1; acc[nt][3] *= corr1;
            }
            m0 = mn0;  m1 = mn1;
        }

        __syncwarp();                     // prev PV reads of Ps done
        #pragma unroll
        for (int nt = 0; nt < 8; nt++) {
            int c0 = nt * 8 + 2 * t;
            // (s - m) <= 0 in log2 units; masked -> -inf -> ex2 -> 0
            half2 h0 = __floats2half2_rn(sc[nt][0] - m0, sc[nt][1] - m0);
            half2 h1 = __floats2half2_rn(sc[nt][2] - m1, sc[nt][3] - m1);
            *(uint32_t*)&Ps[row0][c0] = h2ex2(*(uint32_t*)&h0);
            *(uint32_t*)&Ps[row1][c0] = h2ex2(*(uint32_t*)&h1);
        }
        __syncwarp();                     // Ps visible to warp

        // O += P @ V  (tile nt=8 is the ones-column -> running row sum l)
        const uint32_t vb = v_base + buf * 11520;
        #pragma unroll
        for (int ks = 0; ks < 4; ks++) {
            uint32_t pa[4], bv[10][2];
            LDSM4(pa[0], pa[1], pa[2], pa[3], p_base + ks * 32);
            #pragma unroll
            for (int p = 0; p < 5; p++)
                LDSM4(bv[2*p][0], bv[2*p][1], bv[2*p+1][0], bv[2*p+1][1],
                      vb + p * 16 * 144 + ks * 32);
            #pragma unroll
            for (int nt = 0; nt < 9; nt++)
                MMA_F16(acc[nt], pa, bv[nt]);
        }
        __syncthreads();                  // all warps done reading buf before reuse
    }

    float l0 = __shfl_sync(0xffffffffu, acc[8][0], lane & 28);
    float l1 = __shfl_sync(0xffffffffu, acc[8][2], lane & 28);
    float inv0 = (l0 > 0.0f) ? (1.0f / l0) : 0.0f;
    float inv1 = (l1 > 0.0f) ? (1.0f / l1) : 0.0f;
    __half* o0 = ctx + (size_t)(b * NQ + qt * 128 + row0) * EMB + h * HD;
    __half* o1 = ctx + (size_t)(b * NQ + qt * 128 + row1) * EMB + h * HD;
    #pragma unroll
    for (int nt = 0; nt < 8; nt++) {
        int c0 = nt * 8 + 2 * t;
        *(half2*)(o0 + c0) = __floats2half2_rn(acc[nt][0] * inv0, acc[nt][1] * inv0);
        *(half2*)(o1 + c0) = __floats2half2_rn(acc[nt][2] * inv1, acc[nt][3] * inv1);
    }
}

// ---------------- mask dtype sniff ---------------------------------------------
__global__ void detect_mask_kernel(const unsigned char* kvm_raw,
                                   const unsigned char* spm_raw) {
    __shared__ int found[2];
    if (threadIdx.x == 0) { found[0] = 0; found[1] = 0; }
    __syncthreads();
    for (int i = threadIdx.x; i < 8192; i += blockDim.x) {
        if ((i & 3) != 0) {
            if (kvm_raw[i]) atomicOr(&found[0], 1);
            if (spm_raw[i]) atomicOr(&found[1], 1);
        }
    }
    __syncthreads();
    if (threadIdx.x == 0) { g_is_byte[0] = found[0]; g_is_byte[1] = found[1]; }
}

// ---------------- kv_mask stream compaction -------------------------------------
__global__ void compact_idx_kernel(const void* kvm_raw) {
    const int b = blockIdx.x;
    const int tid = threadIdx.x;
    const int lane = tid & 31, w = tid >> 5;
    __shared__ int base;
    __shared__ int wstart[8];
    __shared__ int wcnt[8];
    if (tid == 0) base = 0;
    __syncthreads();
    const bool kb = g_is_byte[0] != 0;
    for (int c0 = 0; c0 < NK; c0 += 256) {
        int kk = c0 + tid;
        bool v = kb ? (((const unsigned char*)kvm_raw)[b * NK + kk] != 0)
                    : (((const int*)kvm_raw)[b * NK + kk] != 0);
        unsigned bal = __ballot_sync(0xffffffffu, v);
        if (lane == 0) wcnt[w] = __popc(bal);
        __syncthreads();
        if (tid == 0) {
            int s = base;
            #pragma unroll
            for (int i = 0; i < 8; i++) { wstart[i] = s; s += wcnt[i]; }
            base = s;
        }
        __syncthreads();
        if (v)
            g_kidx[b * NK + wstart[w] + __popc(bal & ((1u << lane) - 1))] = kk;
        __syncthreads();
    }
    int nv = base;
    for (int c = nv + tid; c < NK; c += 256) g_kidx[b * NK + c] = 0;
    if (tid == 0) {
        g_nvalid[b] = nv;
        g_nkt[b] = (nv + 63) >> 6;
    }
}

// ---------------- sparse-mask bits (coalesced via smem) --------------------------
// One block per (b,q) row: stage the 2048-entry row in smem, gather locally,
// assemble 64-bit words via ballots.
__global__ void __launch_bounds__(256) mask_bits_kernel(const void* spm_raw) {
    __shared__ unsigned char sp_sm[2048];
    __shared__ uint32_t wb[64];     // [iter 0..7][warp 0..7]
    const int bq = blockIdx.x;      // 0..8191
    const int b = bq >> 11;
    const int tid = threadIdx.x;

    if (g_is_byte[1]) {
        const uint32_t* sp = (const uint32_t*)
            ((const unsigned char*)spm_raw + (size_t)bq * NK);
        for (int i = tid; i < 512; i += 256) {
            uint32_t v = sp[i];
            sp_sm[i * 4 + 0] = (v & 0x000000ffu) ? 1 : 0;
            sp_sm[i * 4 + 1] = (v & 0x0000ff00u) ? 1 : 0;
            sp_sm[i * 4 + 2] = (v & 0x00ff0000u) ? 1 : 0;
            sp_sm[i * 4 + 3] = (v & 0xff000000u) ? 1 : 0;
        }
    } else {
        const int* sp = (const int*)spm_raw + (size_t)bq * NK;
        for (int i = tid; i < 2048; i += 256)
            sp_sm[i] = sp[i] ? 1 : 0;
    }
    __syncthreads();

    const int nv = g_nvalid[b];
    const int* kidx = g_kidx + b * NK;
    #pragma unroll
    for (int i = 0; i < 8; i++) {
        int c = i * 256 + tid;                     // compacted key index
        bool bit = (c < nv) && (sp_sm[kidx[c]] != 0);
        unsigned bal = __ballot_sync(0xffffffffu, bit);
        if ((tid & 31) == 0) wb[i * 8 + (tid >> 5)] = bal;
    }
    __syncthreads();
    if (tid < 32) {
        int i = tid >> 2, wp = (tid & 3) * 2;
        uint64_t wv = (uint64_t)wb[i * 8 + wp] |
                      ((uint64_t)wb[i * 8 + wp + 1] << 32);
        g_mbits[(size_t)bq * 32 + tid] = wv;
    }
}

// ---------------- LayerNorm ------------------------------------------------------
__global__ void lnorm_kernel(const float* __restrict__ xq,
                             const float* __restrict__ xkv,
                             const float* __restrict__ gq,
                             const float* __restrict__ bq,
                             const float* __restrict__ gkv,
                             const float* __restrict__ bkv,
                             __half* __restrict__ yq,
                             __half* __restrict__ ykv) {
    __shared__ float red[8];
    int row = blockIdx.x, t = threadIdx.x;
    const float* x = blockIdx.y ? xkv : xq;
    const float* g = blockIdx.y ? gkv : gq;
    const float* b = blockIdx.y ? bkv : bq;
    __half* y      = blockIdx.y ? ykv : yq;

    float4 v = ((const float4*)(x + (size_t)row * EMB))[t];
    float s  = v.x + v.y + v.z + v.w;
    float s2 = v.x*v.x + v.y*v.y + v.z*v.z + v.w*v.w;
    #pragma unroll
    for (int o = 16; o > 0; o >>= 1) {
        s  += __shfl_xor_sync(0xffffffffu, s,  o);
        s2 += __shfl_xor_sync(0xffffffffu, s2, o);
    }
    if ((t & 31) == 0) { red[t >> 5] = s; red[4 + (t >> 5)] = s2; }
    __syncthreads();
    float tot  = red[0] + red[1] + red[2] + red[3];
    float tot2 = red[4] + red[5] + red[6] + red[7];
    float mu  = tot * (1.0f / EMB);
    float var = tot2 * (1.0f / EMB) - mu * mu;
    float inv = rsqrtf(var + 1e-5f);
    float4 gg = ((const float4*)g)[t];
    float4 bb = ((const float4*)b)[t];
    float o0 = (v.x - mu) * inv * gg.x + bb.x;
    float o1 = (v.y - mu) * inv * gg.y + bb.y;
    float o2 = (v.z - mu) * inv * gg.z + bb.z;
    float o3 = (v.w - mu) * inv * gg.w + bb.w;
    __half* yr = y + (size_t)row * EMB + t * 4;
    *(half2*)(yr)     = __floats2half2_rn(o0, o1);
    *(half2*)(yr + 2) = __floats2half2_rn(o2, o3);
}

// ---------------- weight transpose ------------------------------------------------
__global__ void wt_kernel(const float* __restrict__ Wq,
                          const float* __restrict__ Wk,
                          const float* __restrict__ Wv,
                          const float* __restrict__ Wo,
                          __half* __restrict__ Wt) {
    __shared__ float tile[32][33];
    int z = blockIdx.z;
    const float* W = (z == 0) ? Wq : (z == 1) ? Wk : (z == 2) ? Wv : Wo;
    __half* dst = Wt + (size_t)z * EMB * EMB;
    int bx = blockIdx.x * 32, by = blockIdx.y * 32;
    int tx = threadIdx.x, ty = threadIdx.y;
    #pragma unroll
    for (int i = 0; i < 4; i++)
        tile[ty + i * 8][tx] = W[(size_t)(by + ty + i * 8) * EMB + bx + tx];
    __syncthreads();
    #pragma unroll
    for (int i = 0; i < 4; i++)
        dst[(size_t)(bx + ty + i * 8) * EMB + by + tx] =
            __float2half_rn(tile[tx][ty + i * 8]);
}

// ---------------- launch ----------------------------------------------------------
extern "C" void kernel_launch(void* const* d_in, const int* in_sizes, int n_in,
                              void* d_out, int out_size) {
    const float* query     = (const float*)d_in[0];
    const float* key_value = (const float*)d_in[1];
    const void*  kvm_raw   = d_in[2];
    const void*  spm_raw   = d_in[3];
    const float* ln_q_g  = (const float*)d_in[4];
    const float* ln_q_b  = (const float*)d_in[5];
    const float* ln_kv_g = (const float*)d_in[6];
    const float* ln_kv_b = (const float*)d_in[7];
    const float* Wq = (const float*)d_in[8];
    const float* bq = (const float*)d_in[9];
    const float* Wk = (const float*)d_in[10];
    const float* bk = (const float*)d_in[11];
    const float* Wv = (const float*)d_in[12];
    const float* bv = (const float*)d_in[13];
    const float* Wo = (const float*)d_in[14];
    const float* bo = (const float*)d_in[15];
    float* out = (float*)d_out;

    void *p_qn, *p_kvn, *p_q, *p_k, *p_vt, *p_ctx, *p_wt, *p_mb;
    cudaGetSymbolAddress(&p_qn,  g_qn);
    cudaGetSymbolAddress(&p_kvn, g_kvn);
    cudaGetSymbolAddress(&p_q,   g_q);
    cudaGetSymbolAddress(&p_k,   g_k);
    cudaGetSymbolAddress(&p_vt,  g_vt);
    cudaGetSymbolAddress(&p_ctx, g_ctx);
    cudaGetSymbolAddress(&p_wt,  g_wt);
    cudaGetSymbolAddress(&p_mb,  g_mbits);

    detect_mask_kernel<<<1, 256>>>((const unsigned char*)kvm_raw,
                                   (const unsigned char*)spm_raw);
    compact_idx_kernel<<<BATCH, 256>>>(kvm_raw);
    mask_bits_kernel<<<BATCH * NQ, 256>>>(spm_raw);

    dim3 lg(NTOK, 2);
    lnorm_kernel<<<lg, 128>>>(query, key_value, ln_q_g, ln_q_b,
                              ln_kv_g, ln_kv_b,
                              (__half*)p_qn, (__half*)p_kvn);

    dim3 tb(32, 8), tg(16, 16, 4);
    wt_kernel<<<tg, tb>>>(Wq, Wk, Wv, Wo, (__half*)p_wt);

    dim3 pg(EMB / 128, NTOK / 128, 3);
    proj_qkv_kernel<<<pg, 256>>>((const __half*)p_qn, (const __half*)p_kvn,
                                 (const __half*)p_wt, bq, bk, bv,
                                 (__half*)p_q, (__half*)p_k, (__half*)p_vt);

    cudaFuncSetAttribute(fattn_kernel,
        cudaFuncAttributeMaxDynamicSharedMemorySize, FATTN_SMEM);
    dim3 fg(NQ / 128, BHN);
    fattn_kernel<<<fg, 256, FATTN_SMEM>>>((const __half*)p_q, (const __half*)p_k,
                              (const __half*)p_vt,
                              (const unsigned long long*)p_mb,
                              (__half*)p_ctx);

    dim3 og(EMB / 128, NTOK / 128);
    proj_o_kernel<<<og, 256>>>((const __half*)p_ctx, (const __half*)p_wt,
                               bo, out);
}

// round 11
// speedup vs baseline: 1.9870x; 1.0303x over previous
#include <cuda_runtime.h>
#include <cuda_fp16.h>
#include <cstdint>
#include <cstddef>

#define BATCH 4
#define NQ    2048
#define NK    2048
#define EMB   512
#define NH    8
#define HD    64
#define NTOK  (BATCH * NQ)
#define BHN   (BATCH * NH)

// ---------------- device-global scratch ---------------------------------------
__device__ __half g_qn [NTOK * EMB];
__device__ __half g_kvn[NTOK * EMB];
__device__ __half g_q  [NTOK * EMB];          // pre-scaled by 0.125*log2(e)
__device__ __half g_k  [NTOK * EMB];          // COMPACTED rows per batch
__device__ __half g_vt [BHN * HD * NK];       // V^T per (b,h): [d][compacted key]
__device__ __half g_ctx[NTOK * EMB];
__device__ __half g_wt [4 * EMB * EMB];       // W^T, k-major rows
__device__ unsigned long long g_mbits[(size_t)BATCH * NQ * (NK / 64)];
__device__ int g_kidx[BATCH * NK];
__device__ int g_nvalid[BATCH];
__device__ int g_nkt[BATCH];
__device__ int g_is_byte[2];

// ---------------- PTX helpers --------------------------------------------------
__device__ __forceinline__ uint32_t sptr(const void* p) {
    uint32_t a;
    asm("{ .reg .u64 t; cvta.to.shared.u64 t, %1; cvt.u32.u64 %0, t; }"
        : "=r"(a) : "l"(p));
    return a;
}
__device__ __forceinline__ uint32_t h2ex2(uint32_t x) {
    uint32_t r;
    asm("ex2.approx.f16x2 %0, %1;" : "=r"(r) : "r"(x));
    return r;
}

#define MMA_F16(C, A, B) \
    asm volatile( \
        "mma.sync.aligned.m16n8k16.row.col.f32.f16.f16.f32 " \
        "{%0,%1,%2,%3}, {%4,%5,%6,%7}, {%8,%9}, {%0,%1,%2,%3};" \
        : "+f"((C)[0]), "+f"((C)[1]), "+f"((C)[2]), "+f"((C)[3]) \
        : "r"((A)[0]), "r"((A)[1]), "r"((A)[2]), "r"((A)[3]), \
          "r"((B)[0]), "r"((B)[1]))

#define LDSM4(R0, R1, R2, R3, ADDR) \
    asm volatile("ldmatrix.sync.aligned.m8n8.x4.shared.b16 {%0,%1,%2,%3}, [%4];" \
        : "=r"(R0), "=r"(R1), "=r"(R2), "=r"(R3) : "r"(ADDR))

#define CP16(DST, SRC) \
    asm volatile("cp.async.cg.shared.global [%0], [%1], 16;" \
        :: "r"(DST), "l"(SRC))
#define CP_COMMIT() asm volatile("cp.async.commit_group;" ::: "memory")
#define CP_WAIT0()  asm volatile("cp.async.wait_group 0;" ::: "memory")

// ---------------- fp16 GEMM mainloop (double-buffered, 1 sync/chunk) -----------
__device__ __forceinline__ void gemm16_mainloop(
        const __half* __restrict__ A, const int* __restrict__ ridx,
        const __half* __restrict__ B, float (&c)[2][8][4]) {
    __shared__ __align__(16) __half As[2][128][40];
    __shared__ __align__(16) __half Bs[2][128][40];
    const int tid = threadIdx.x;
    const int lane = tid & 31, wid = tid >> 5;
    const int wm = wid & 3, wn = wid >> 2;

    #pragma unroll
    for (int mt = 0; mt < 2; mt++)
        #pragma unroll
        for (int nt = 0; nt < 8; nt++)
            #pragma unroll
            for (int j = 0; j < 4; j++) c[mt][nt][j] = 0.0f;

    const uint32_t a_base = sptr(&As[0][wm * 32 + ((lane & 8) ? 8 : 0) + (lane & 7)]
                                      [(lane & 16) ? 8 : 0]);
    const uint32_t b_base = sptr(&Bs[0][wn * 64 + ((lane & 16) ? 8 : 0) + (lane & 7)]
                                      [(lane & 8) ? 8 : 0]);
    const uint32_t BUFB = 128 * 40 * 2;

    const int r0 = tid >> 2, r1 = r0 + 64;
    const int f0 = (tid & 3) * 8;
    const __half* A0 = A + (size_t)(ridx ? ridx[r0] : r0) * EMB + f0;
    const __half* A1 = A + (size_t)(ridx ? ridx[r1] : r1) * EMB + f0;
    const __half* B0 = B + (size_t)r0 * EMB + f0;
    const __half* B1 = B + (size_t)r1 * EMB + f0;

    uint4 pa0 = *(const uint4*)A0, pa1 = *(const uint4*)A1;
    uint4 pb0 = *(const uint4*)B0, pb1 = *(const uint4*)B1;

    for (int ch = 0; ch < 16; ch++) {
        const int buf = ch & 1;
        *(uint4*)&As[buf][r0][f0] = pa0;  *(uint4*)&As[buf][r1][f0] = pa1;
        *(uint4*)&Bs[buf][r0][f0] = pb0;  *(uint4*)&Bs[buf][r1][f0] = pb1;
        if (ch + 1 < 16) {
            int co = (ch + 1) * 32;
            pa0 = *(const uint4*)(A0 + co);
            pa1 = *(const uint4*)(A1 + co);
            pb0 = *(const uint4*)(B0 + co);
            pb1 = *(const uint4*)(B1 + co);
        }
        __syncthreads();
        const uint32_t ab = a_base + buf * BUFB;
        const uint32_t bb = b_base + buf * BUFB;
        #pragma unroll
        for (int ks = 0; ks < 2; ks++) {
            uint32_t a[2][4], b[8][2];
            #pragma unroll
            for (int mt = 0; mt < 2; mt++)
                LDSM4(a[mt][0], a[mt][1], a[mt][2], a[mt][3],
                      ab + mt * 1280 + ks * 32);
            #pragma unroll
            for (int p = 0; p < 4; p++)
                LDSM4(b[2*p][0], b[2*p][1], b[2*p+1][0], b[2*p+1][1],
                      bb + p * 1280 + ks * 32);
            #pragma unroll
            for (int mt = 0; mt < 2; mt++)
                #pragma unroll
                for (int nt = 0; nt < 8; nt++)
                    MMA_F16(c[mt][nt], a[mt], b[nt]);
        }
    }
}

// Q/K/V projections. z=0: Q (scaled 0.125*log2e), z=1: K (gathered), z=2: V^T.
__global__ void __launch_bounds__(256, 2) proj_qkv_kernel(
        const __half* __restrict__ qn, const __half* __restrict__ kvn,
        const __half* __restrict__ wt,
        const float* __restrict__ bq, const float* __restrict__ bk,
        const float* __restrict__ bv,
        __half* __restrict__ q, __half* __restrict__ k,
        __half* __restrict__ vt) {
    const int z = blockIdx.z;
    const size_t bm = (size_t)blockIdx.y * 128, bn = (size_t)blockIdx.x * 128;
    const int bb = (int)(bm >> 11);
    const int rloc = (int)(bm & 2047);

    const int* ridx = nullptr;
    const __half* A;
    if (z == 0) {
        A = qn + bm * EMB;
    } else {
        if (rloc >= g_nkt[bb] * 64) return;
        A = kvn + (size_t)bb * 2048 * EMB;
        ridx = g_kidx + bb * NK + rloc;
    }
    const __half* B = wt + (size_t)z * EMB * EMB + bn * EMB;
    float c[2][8][4];
    gemm16_mainloop(A, ridx, B, c);

    const int tid = threadIdx.x, lane = tid & 31, wid = tid >> 5;
    const int wm = wid & 3, wn = wid >> 2, g = lane >> 2, t = lane & 3;
    const float* bias = (z == 0) ? bq : (z == 1) ? bk : bv;
    const float scale = (z == 0) ? 0.1803368801111244f : 1.0f;  // 0.125*log2(e)

    #pragma unroll
    for (int mt = 0; mt < 2; mt++) {
        #pragma unroll
        for (int nt = 0; nt < 8; nt++) {
            int m   = (int)bm + wm * 32 + mt * 16 + g;
            int col = (int)bn + wn * 64 + nt * 8 + 2 * t;
            float b0 = bias[col], b1 = bias[col + 1];
            float v0 = (c[mt][nt][0] + b0) * scale;
            float v1 = (c[mt][nt][1] + b1) * scale;
            float v2 = (c[mt][nt][2] + b0) * scale;
            float v3 = (c[mt][nt][3] + b1) * scale;
            if (z < 2) {
                __half* dst = (z == 0) ? q : k;
                *(half2*)(dst + (size_t)m * EMB + col) = __floats2half2_rn(v0, v1);
                *(half2*)(dst + (size_t)(m + 8) * EMB + col) = __floats2half2_rn(v2, v3);
            } else {
                int h = col >> 6, d = col & 63;
                int b_ = m >> 11;
                size_t base = ((size_t)(b_ * NH + h) * HD);
                int tok = m & 2047;
                vt[(base + d) * NK + tok]         = __float2half_rn(v0);
                vt[(base + d + 1) * NK + tok]     = __float2half_rn(v1);
                vt[(base + d) * NK + tok + 8]     = __float2half_rn(v2);
                vt[(base + d + 1) * NK + tok + 8] = __float2half_rn(v3);
            }
        }
    }
}

__global__ void __launch_bounds__(256, 2) proj_o_kernel(
        const __half* __restrict__ ctx, const __half* __restrict__ wt,
        const float* __restrict__ bo, float* __restrict__ out) {
    const size_t bm = (size_t)blockIdx.y * 128, bn = (size_t)blockIdx.x * 128;
    float c[2][8][4];
    gemm16_mainloop(ctx + bm * EMB, nullptr,
                    wt + 3ull * EMB * EMB + bn * EMB, c);

    const int tid = threadIdx.x, lane = tid & 31, wid = tid >> 5;
    const int wm = wid & 3, wn = wid >> 2, g = lane >> 2, t = lane & 3;
    #pragma unroll
    for (int mt = 0; mt < 2; mt++) {
        #pragma unroll
        for (int nt = 0; nt < 8; nt++) {
            int m   = (int)bm + wm * 32 + mt * 16 + g;
            int col = (int)bn + wn * 64 + nt * 8 + 2 * t;
            float b0 = bo[col], b1 = bo[col + 1];
            *(float2*)(out + (size_t)m * EMB + col) =
                make_float2(c[mt][nt][0] + b0, c[mt][nt][1] + b1);
            *(float2*)(out + (size_t)(m + 8) * EMB + col) =
                make_float2(c[mt][nt][2] + b0, c[mt][nt][3] + b1);
        }
    }
}

// ---------------- fused flash attention (register-resident P) -------------------
// Dynamic smem layout (halves):
//   Ks : [2][64][72]  at 0        (buf byte-stride  9216)
//   Vst: [2][80][72]  at 9216h    (buf byte-stride 11520; rows 64..79 = ones/zeros)
#define FATTN_SMEM 41472
__global__ void __launch_bounds__(256, 2) fattn_kernel(
        const __half* __restrict__ Qp, const __half* __restrict__ Kp,
        const __half* __restrict__ Vtp,
        const unsigned long long* __restrict__ mbits,
        __half* __restrict__ ctx) {
    extern __shared__ __align__(16) __half smd[];
    __half* KsB = smd;
    __half* VsB = smd + 9216;

    const int tid = threadIdx.x;
    const int lane = tid & 31, w = tid >> 5;
    const int g = lane >> 2, t = lane & 3;
    const int qt = blockIdx.x, bh = blockIdx.y;
    const int b = bh >> 3, h = bh & 7;
    const int row0 = w * 16 + g, row1 = row0 + 8;
    const int nkt = g_nkt[b];

    const uint32_t ks_smem = sptr(KsB);
    const uint32_t vs_smem = sptr(VsB);
    const uint32_t lrow = ((lane & 16) ? 8 : 0) + (lane & 7);
    const uint32_t k_base = ks_smem + lrow * 144 + ((lane & 8) ? 16 : 0);
    const uint32_t v_base = vs_smem + lrow * 144 + ((lane & 8) ? 16 : 0);

    // init ones/zeros rows 64..79 of both V buffers (row 64 = 1, rest 0)
    for (int idx = tid; idx < 2 * 16 * 72; idx += 256) {
        int bufr = idx / 72, col = idx % 72;
        int buf = bufr >> 4, row = 64 + (bufr & 15);
        VsB[buf * 5760 + row * 72 + col] =
            (row == 64) ? __float2half(1.0f) : __float2half(0.0f);
    }

    // Q fragments (pre-scaled by 0.125*log2e, fp16)
    uint32_t qa[4][4];
    {
        const __half* q0 = Qp + (size_t)(b * NQ + qt * 128 + row0) * EMB + h * HD;
        const __half* q1 = Qp + (size_t)(b * NQ + qt * 128 + row1) * EMB + h * HD;
        #pragma unroll
        for (int ks = 0; ks < 4; ks++) {
            qa[ks][0] = *(const uint32_t*)(q0 + ks * 16 + 2 * t);
            qa[ks][1] = *(const uint32_t*)(q1 + ks * 16 + 2 * t);
            qa[ks][2] = *(const uint32_t*)(q0 + ks * 16 + 2 * t + 8);
            qa[ks][3] = *(const uint32_t*)(q1 + ks * 16 + 2 * t + 8);
        }
    }

    float m0 = -40.0f, m1 = -40.0f;          // log2-domain running max
    float acc[9][4];
    #pragma unroll
    for (int nt = 0; nt < 9; nt++)
        #pragma unroll
        for (int j = 0; j < 4; j++) acc[nt][j] = 0.0f;

    const unsigned long long* mb0 =
        mbits + ((size_t)b * NQ + qt * 128 + row0) * (NK / 64);
    const unsigned long long* mb1 =
        mbits + ((size_t)b * NQ + qt * 128 + row1) * (NK / 64);

    const __half* Kbase  = Kp + ((size_t)b * NK) * EMB + h * HD;
    const __half* Vtbase = Vtp + (size_t)bh * HD * NK;

    // prologue: stage tile 0 into buf 0
    if (nkt > 0) {
        #pragma unroll
        for (int i = 0; i < 2; i++) {
            int s = tid + i * 256;
            int r = s >> 3, f = s & 7;
            CP16(ks_smem + r * 144 + f * 16,
                 Kbase + (size_t)r * EMB + f * 8);
            CP16(vs_smem + r * 144 + f * 16,
                 Vtbase + (size_t)r * NK + f * 8);
        }
        CP_COMMIT();
    }

    for (int kt = 0; kt < nkt; kt++) {
        const int buf = kt & 1;
        CP_WAIT0();
        __syncthreads();

        if (kt + 1 < nkt) {
            int k0n = (kt + 1) * 64;
            int nbuf = buf ^ 1;
            #pragma unroll
            for (int i = 0; i < 2; i++) {
                int s = tid + i * 256;
                int r = s >> 3, f = s & 7;
                CP16(ks_smem + nbuf * 9216 + r * 144 + f * 16,
                     Kbase + (size_t)(k0n + r) * EMB + f * 8);
                CP16(vs_smem + nbuf * 11520 + r * 144 + f * 16,
                     Vtbase + (size_t)r * NK + k0n + f * 8);
            }
            CP_COMMIT();
        }

        // S = Q @ K^T  (scores already in log2 units)
        float sc[8][4];
        #pragma unroll
        for (int nt = 0; nt < 8; nt++)
            #pragma unroll
            for (int j = 0; j < 4; j++) sc[nt][j] = 0.0f;
        const uint32_t kb = k_base + buf * 9216;
        #pragma unroll
        for (int ks = 0; ks < 4; ks++) {
            uint32_t bf[8][2];
            #pragma unroll
            for (int p = 0; p < 4; p++)
                LDSM4(bf[2*p][0], bf[2*p][1], bf[2*p+1][0], bf[2*p+1][1],
                      kb + p * 16 * 144 + ks * 32);
            #pragma unroll
            for (int nt = 0; nt < 8; nt++)
                MMA_F16(sc[nt], qa[ks], bf[nt]);
        }

        // mask + tile max
        unsigned long long w0 = mb0[kt], w1 = mb1[kt];
        float tm0 = -1e30f, tm1 = -1e30f;
        #pragma unroll
        for (int nt = 0; nt < 8; nt++) {
            int c0 = nt * 8 + 2 * t;
            sc[nt][0] = ((w0 >> c0) & 1)       ? sc[nt][0] : -1e30f;
            sc[nt][1] = ((w0 >> (c0 + 1)) & 1) ? sc[nt][1] : -1e30f;
            sc[nt][2] = ((w1 >> c0) & 1)       ? sc[nt][2] : -1e30f;
            sc[nt][3] = ((w1 >> (c0 + 1)) & 1) ? sc[nt][3] : -1e30f;
            tm0 = fmaxf(tm0, fmaxf(sc[nt][0], sc[nt][1]));
            tm1 = fmaxf(tm1, fmaxf(sc[nt][2], sc[nt][3]));
        }
        tm0 = fmaxf(tm0, __shfl_xor_sync(0xffffffffu, tm0, 1));
        tm0 = fmaxf(tm0, __shfl_xor_sync(0xffffffffu, tm0, 2));
        tm1 = fmaxf(tm1, __shfl_xor_sync(0xffffffffu, tm1, 1));
        tm1 = fmaxf(tm1, __shfl_xor_sync(0xffffffffu, tm1, 2));

        float mn0 = fmaxf(m0, tm0), mn1 = fmaxf(m1, tm1);  // >= -40 always
        if (__any_sync(0xffffffffu, (mn0 > m0) | (mn1 > m1))) {
            float corr0 = exp2f(m0 - mn0);
            float corr1 = exp2f(m1 - mn1);
            #pragma unroll
            for (int nt = 0; nt < 9; nt++) {
                acc[nt][0] *= corr0; acc[nt][1] *= corr0;
                acc[nt][2] *= corr1; acc[nt][3] *= corr1;
            }
            m0 = mn0;  m1 = mn1;
        }

        // P in registers: S C-fragment == PV A-fragment (FA-2 layout identity)
        // pa[ks] covers keys 16ks..16ks+15: a0/a1 from sc[2ks], a2/a3 from sc[2ks+1]
        uint32_t pfrag[4][4];
        #pragma unroll
        for (int ks = 0; ks < 4; ks++) {
            half2 h00 = __floats2half2_rn(sc[2*ks][0] - m0, sc[2*ks][1] - m0);
            half2 h01 = __floats2half2_rn(sc[2*ks][2] - m1, sc[2*ks][3] - m1);
            half2 h10 = __floats2half2_rn(sc[2*ks+1][0] - m0, sc[2*ks+1][1] - m0);
            half2 h11 = __floats2half2_rn(sc[2*ks+1][2] - m1, sc[2*ks+1][3] - m1);
            pfrag[ks][0] = h2ex2(*(uint32_t*)&h00);
            pfrag[ks][1] = h2ex2(*(uint32_t*)&h01);
            pfrag[ks][2] = h2ex2(*(uint32_t*)&h10);
            pfrag[ks][3] = h2ex2(*(uint32_t*)&h11);
        }

        // O += P @ V  (tile nt=8 is the ones-column -> running row sum l)
        const uint32_t vb = v_base + buf * 11520;
        #pragma unroll
        for (int ks = 0; ks < 4; ks++) {
            uint32_t bv[10][2];
            #pragma unroll
            for (int p = 0; p < 5; p++)
                LDSM4(bv[2*p][0], bv[2*p][1], bv[2*p+1][0], bv[2*p+1][1],
                      vb + p * 16 * 144 + ks * 32);
            #pragma unroll
            for (int nt = 0; nt < 9; nt++)
                MMA_F16(acc[nt], pfrag[ks], bv[nt]);
        }
        __syncthreads();                  // all warps done reading buf before reuse
    }

    float l0 = __shfl_sync(0xffffffffu, acc[8][0], lane & 28);
    float l1 = __shfl_sync(0xffffffffu, acc[8][2], lane & 28);
    float inv0 = (l0 > 0.0f) ? (1.0f / l0) : 0.0f;
    float inv1 = (l1 > 0.0f) ? (1.0f / l1) : 0.0f;
    __half* o0 = ctx + (size_t)(b * NQ + qt * 128 + row0) * EMB + h * HD;
    __half* o1 = ctx + (size_t)(b * NQ + qt * 128 + row1) * EMB + h * HD;
    #pragma unroll
    for (int nt = 0; nt < 8; nt++) {
        int c0 = nt * 8 + 2 * t;
        *(half2*)(o0 + c0) = __floats2half2_rn(acc[nt][0] * inv0, acc[nt][1] * inv0);
        *(half2*)(o1 + c0) = __floats2half2_rn(acc[nt][2] * inv1, acc[nt][3] * inv1);
    }
}

// ---------------- mask dtype sniff ---------------------------------------------
__global__ void detect_mask_kernel(const unsigned char* kvm_raw,
                                   const unsigned char* spm_raw) {
    __shared__ int found[2];
    if (threadIdx.x == 0) { found[0] = 0; found[1] = 0; }
    __syncthreads();
    for (int i = threadIdx.x; i < 8192; i += blockDim.x) {
        if ((i & 3) != 0) {
            if (kvm_raw[i]) atomicOr(&found[0], 1);
            if (spm_raw[i]) atomicOr(&found[1], 1);
        }
    }
    __syncthreads();
    if (threadIdx.x == 0) { g_is_byte[0] = found[0]; g_is_byte[1] = found[1]; }
}

// ---------------- kv_mask stream compaction -------------------------------------
__global__ void compact_idx_kernel(const void* kvm_raw) {
    const int b = blockIdx.x;
    const int tid = threadIdx.x;
    const int lane = tid & 31, w = tid >> 5;
    __shared__ int base;
    __shared__ int wstart[8];
    __shared__ int wcnt[8];
    if (tid == 0) base = 0;
    __syncthreads();
    const bool kb = g_is_byte[0] != 0;
    for (int c0 = 0; c0 < NK; c0 += 256) {
        int kk = c0 + tid;
        bool v = kb ? (((const unsigned char*)kvm_raw)[b * NK + kk] != 0)
                    : (((const int*)kvm_raw)[b * NK + kk] != 0);
        unsigned bal = __ballot_sync(0xffffffffu, v);
        if (lane == 0) wcnt[w] = __popc(bal);
        __syncthreads();
        if (tid == 0) {
            int s = base;
            #pragma unroll
            for (int i = 0; i < 8; i++) { wstart[i] = s; s += wcnt[i]; }
            base = s;
        }
        __syncthreads();
        if (v)
            g_kidx[b * NK + wstart[w] + __popc(bal & ((1u << lane) - 1))] = kk;
        __syncthreads();
    }
    int nv = base;
    for (int c = nv + tid; c < NK; c += 256) g_kidx[b * NK + c] = 0;
    if (tid == 0) {
        g_nvalid[b] = nv;
        g_nkt[b] = (nv + 63) >> 6;
    }
}

// ---------------- sparse-mask bits (coalesced via smem) --------------------------
__global__ void __launch_bounds__(256) mask_bits_kernel(const void* spm_raw) {
    __shared__ unsigned char sp_sm[2048];
    __shared__ uint32_t wb[64];
    const int bq = blockIdx.x;
    const int b = bq >> 11;
    const int tid = threadIdx.x;

    if (g_is_byte[1]) {
        const uint32_t* sp = (const uint32_t*)
            ((const unsigned char*)spm_raw + (size_t)bq * NK);
        for (int i = tid; i < 512; i += 256) {
            uint32_t v = sp[i];
            sp_sm[i * 4 + 0] = (v & 0x000000ffu) ? 1 : 0;
            sp_sm[i * 4 + 1] = (v & 0x0000ff00u) ? 1 : 0;
            sp_sm[i * 4 + 2] = (v & 0x00ff0000u) ? 1 : 0;
            sp_sm[i * 4 + 3] = (v & 0xff000000u) ? 1 : 0;
        }
    } else {
        const int* sp = (const int*)spm_raw + (size_t)bq * NK;
        for (int i = tid; i < 2048; i += 256)
            sp_sm[i] = sp[i] ? 1 : 0;
    }
    __syncthreads();

    const int nv = g_nvalid[b];
    const int* kidx = g_kidx + b * NK;
    #pragma unroll
    for (int i = 0; i < 8; i++) {
        int c = i * 256 + tid;
        bool bit = (c < nv) && (sp_sm[kidx[c]] != 0);
        unsigned bal = __ballot_sync(0xffffffffu, bit);
        if ((tid & 31) == 0) wb[i * 8 + (tid >> 5)] = bal;
    }
    __syncthreads();
    if (tid < 32) {
        int i = tid >> 2, wp = (tid & 3) * 2;
        uint64_t wv = (uint64_t)wb[i * 8 + wp] |
                      ((uint64_t)wb[i * 8 + wp + 1] << 32);
        g_mbits[(size_t)bq * 32 + tid] = wv;
    }
}

// ---------------- LayerNorm ------------------------------------------------------
__global__ void lnorm_kernel(const float* __restrict__ xq,
                             const float* __restrict__ xkv,
                             const float* __restrict__ gq,
                             const float* __restrict__ bq,
                             const float* __restrict__ gkv,
                             const float* __restrict__ bkv,
                             __half* __restrict__ yq,
                             __half* __restrict__ ykv) {
    __shared__ float red[8];
    int row = blockIdx.x, t = threadIdx.x;
    const float* x = blockIdx.y ? xkv : xq;
    const float* g = blockIdx.y ? gkv : gq;
    const float* b = blockIdx.y ? bkv : bq;
    __half* y      = blockIdx.y ? ykv : yq;

    float4 v = ((const float4*)(x + (size_t)row * EMB))[t];
    float s  = v.x + v.y + v.z + v.w;
    float s2 = v.x*v.x + v.y*v.y + v.z*v.z + v.w*v.w;
    #pragma unroll
    for (int o = 16; o > 0; o >>= 1) {
        s  += __shfl_xor_sync(0xffffffffu, s,  o);
        s2 += __shfl_xor_sync(0xffffffffu, s2, o);
    }
    if ((t & 31) == 0) { red[t >> 5] = s; red[4 + (t >> 5)] = s2; }
    __syncthreads();
    float tot  = red[0] + red[1] + red[2] + red[3];
    float tot2 = red[4] + red[5] + red[6] + red[7];
    float mu  = tot * (1.0f / EMB);
    float var = tot2 * (1.0f / EMB) - mu * mu;
    float inv = rsqrtf(var + 1e-5f);
    float4 gg = ((const float4*)g)[t];
    float4 bb = ((const float4*)b)[t];
    float o0 = (v.x - mu) * inv * gg.x + bb.x;
    float o1 = (v.y - mu) * inv * gg.y + bb.y;
    float o2 = (v.z - mu) * inv * gg.z + bb.z;
    float o3 = (v.w - mu) * inv * gg.w + bb.w;
    __half* yr = y + (size_t)row * EMB + t * 4;
    *(half2*)(yr)     = __floats2half2_rn(o0, o1);
    *(half2*)(yr + 2) = __floats2half2_rn(o2, o3);
}

// ---------------- weight transpose ------------------------------------------------
__global__ void wt_kernel(const float* __restrict__ Wq,
                          const float* __restrict__ Wk,
                          const float* __restrict__ Wv,
                          const float* __restrict__ Wo,
                          __half* __restrict__ Wt) {
    __shared__ float tile[32][33];
    int z = blockIdx.z;
    const float* W = (z == 0) ? Wq : (z == 1) ? Wk : (z == 2) ? Wv : Wo;
    __half* dst = Wt + (size_t)z * EMB * EMB;
    int bx = blockIdx.x * 32, by = blockIdx.y * 32;
    int tx = threadIdx.x, ty = threadIdx.y;
    #pragma unroll
    for (int i = 0; i < 4; i++)
        tile[ty + i * 8][tx] = W[(size_t)(by + ty + i * 8) * EMB + bx + tx];
    __syncthreads();
    #pragma unroll
    for (int i = 0; i < 4; i++)
        dst[(size_t)(bx + ty + i * 8) * EMB + by + tx] =
            __float2half_rn(tile[tx][ty + i * 8]);
}

// ---------------- launch ----------------------------------------------------------
extern "C" void kernel_launch(void* const* d_in, const int* in_sizes, int n_in,
                              void* d_out, int out_size) {
    const float* query     = (const float*)d_in[0];
    const float* key_value = (const float*)d_in[1];
    const void*  kvm_raw   = d_in[2];
    const void*  spm_raw   = d_in[3];
    const float* ln_q_g  = (const float*)d_in[4];
    const float* ln_q_b  = (const float*)d_in[5];
    const float* ln_kv_g = (const float*)d_in[6];
    const float* ln_kv_b = (const float*)d_in[7];
    const float* Wq = (const float*)d_in[8];
    const float* bq = (const float*)d_in[9];
    const float* Wk = (const float*)d_in[10];
    const float* bk = (const float*)d_in[11];
    const float* Wv = (const float*)d_in[12];
    const float* bv = (const float*)d_in[13];
    const float* Wo = (const float*)d_in[14];
    const float* bo = (const float*)d_in[15];
    float* out = (float*)d_out;

    void *p_qn, *p_kvn, *p_q, *p_k, *p_vt, *p_ctx, *p_wt, *p_mb;
    cudaGetSymbolAddress(&p_qn,  g_qn);
    cudaGetSymbolAddress(&p_kvn, g_kvn);
    cudaGetSymbolAddress(&p_q,   g_q);
    cudaGetSymbolAddress(&p_k,   g_k);
    cudaGetSymbolAddress(&p_vt,  g_vt);
    cudaGetSymbolAddress(&p_ctx, g_ctx);
    cudaGetSymbolAddress(&p_wt,  g_wt);
    cudaGetSymbolAddress(&p_mb,  g_mbits);

    detect_mask_kernel<<<1, 256>>>((const unsigned char*)kvm_raw,
                                   (const unsigned char*)spm_raw);
    compact_idx_kernel<<<BATCH, 256>>>(kvm_raw);
    mask_bits_kernel<<<BATCH * NQ, 256>>>(spm_raw);

    dim3 lg(NTOK, 2);
    lnorm_kernel<<<lg, 128>>>(query, key_value, ln_q_g, ln_q_b,
                              ln_kv_g, ln_kv_b,
                              (__half*)p_qn, (__half*)p_kvn);

    dim3 tb(32, 8), tg(16, 16, 4);
    wt_kernel<<<tg, tb>>>(Wq, Wk, Wv, Wo, (__half*)p_wt);

    dim3 pg(EMB / 128, NTOK / 128, 3);
    proj_qkv_kernel<<<pg, 256>>>((const __half*)p_qn, (const __half*)p_kvn,
                                 (const __half*)p_wt, bq, bk, bv,
                                 (__half*)p_q, (__half*)p_k, (__half*)p_vt);

    cudaFuncSetAttribute(fattn_kernel,
        cudaFuncAttributeMaxDynamicSharedMemorySize, FATTN_SMEM);
    dim3 fg(NQ / 128, BHN);
    fattn_kernel<<<fg, 256, FATTN_SMEM>>>((const __half*)p_q, (const __half*)p_k,
                              (const __half*)p_vt,
                              (const unsigned long long*)p_mb,
                              (__half*)p_ctx);

    dim3 og(EMB / 128, NTOK / 128);
    proj_o_kernel<<<og, 256>>>((const __half*)p_ctx, (const __half*)p_wt,
                               bo, out);
}

// round 12
// speedup vs baseline: 2.1153x; 1.0646x over previous
#include <cuda_runtime.h>
#include <cuda_fp16.h>
#include <cstdint>
#include <cstddef>

#define BATCH 4
#define NQ    2048
#define NK    2048
#define EMB   512
#define NH    8
#define HD    64
#define NTOK  (BATCH * NQ)
#define BHN   (BATCH * NH)

// ---------------- device-global scratch ---------------------------------------
__device__ __half g_qn [NTOK * EMB];
__device__ __half g_kvn[NTOK * EMB];
__device__ __half g_q  [NTOK * EMB];          // pre-scaled by 0.125*log2(e)
__device__ __half g_k  [NTOK * EMB];          // COMPACTED rows per batch
__device__ __half g_vt [BHN * HD * NK];       // V^T per (b,h): [d][compacted key]
__device__ __half g_ctx[NTOK * EMB];
__device__ __half g_wt [4 * EMB * EMB];       // W^T, k-major rows
__device__ unsigned long long g_mbits[(size_t)BATCH * NQ * (NK / 64)];
__device__ int g_kidx[BATCH * NK];
__device__ int g_nvalid[BATCH];
__device__ int g_nkt[BATCH];
__device__ int g_is_byte[2];

// ---------------- streams/events for graph-parallel branches -------------------
struct StreamInit {
    cudaStream_t s2 = nullptr;
    cudaEvent_t eFork = nullptr, eCompact = nullptr, eMask = nullptr;
    bool ok = false;
    StreamInit() {
        if (cudaStreamCreateWithFlags(&s2, cudaStreamNonBlocking) != cudaSuccess) return;
        if (cudaEventCreateWithFlags(&eFork, cudaEventDisableTiming) != cudaSuccess) return;
        if (cudaEventCreateWithFlags(&eCompact, cudaEventDisableTiming) != cudaSuccess) return;
        if (cudaEventCreateWithFlags(&eMask, cudaEventDisableTiming) != cudaSuccess) return;
        ok = true;
    }
};
static StreamInit g_si;

// ---------------- PTX helpers --------------------------------------------------
__device__ __forceinline__ uint32_t sptr(const void* p) {
    uint32_t a;
    asm("{ .reg .u64 t; cvta.to.shared.u64 t, %1; cvt.u32.u64 %0, t; }"
        : "=r"(a) : "l"(p));
    return a;
}
__device__ __forceinline__ uint32_t h2ex2(uint32_t x) {
    uint32_t r;
    asm("ex2.approx.f16x2 %0, %1;" : "=r"(r) : "r"(x));
    return r;
}

#define MMA_F16(C, A, B) \
    asm volatile( \
        "mma.sync.aligned.m16n8k16.row.col.f32.f16.f16.f32 " \
        "{%0,%1,%2,%3}, {%4,%5,%6,%7}, {%8,%9}, {%0,%1,%2,%3};" \
        : "+f"((C)[0]), "+f"((C)[1]), "+f"((C)[2]), "+f"((C)[3]) \
        : "r"((A)[0]), "r"((A)[1]), "r"((A)[2]), "r"((A)[3]), \
          "r"((B)[0]), "r"((B)[1]))

#define LDSM4(R0, R1, R2, R3, ADDR) \
    asm volatile("ldmatrix.sync.aligned.m8n8.x4.shared.b16 {%0,%1,%2,%3}, [%4];" \
        : "=r"(R0), "=r"(R1), "=r"(R2), "=r"(R3) : "r"(ADDR))

#define CP16(DST, SRC) \
    asm volatile("cp.async.cg.shared.global [%0], [%1], 16;" \
        :: "r"(DST), "l"(SRC))
#define CP_COMMIT() asm volatile("cp.async.commit_group;" ::: "memory")
#define CP_WAIT0()  asm volatile("cp.async.wait_group 0;" ::: "memory")

// ---------------- fp16 GEMM mainloop (double-buffered, 1 sync/chunk) -----------
__device__ __forceinline__ void gemm16_mainloop(
        const __half* __restrict__ A, const int* __restrict__ ridx,
        const __half* __restrict__ B, float (&c)[2][8][4]) {
    __shared__ __align__(16) __half As[2][128][40];
    __shared__ __align__(16) __half Bs[2][128][40];
    const int tid = threadIdx.x;
    const int lane = tid & 31, wid = tid >> 5;
    const int wm = wid & 3, wn = wid >> 2;

    #pragma unroll
    for (int mt = 0; mt < 2; mt++)
        #pragma unroll
        for (int nt = 0; nt < 8; nt++)
            #pragma unroll
            for (int j = 0; j < 4; j++) c[mt][nt][j] = 0.0f;

    const uint32_t a_base = sptr(&As[0][wm * 32 + ((lane & 8) ? 8 : 0) + (lane & 7)]
                                      [(lane & 16) ? 8 : 0]);
    const uint32_t b_base = sptr(&Bs[0][wn * 64 + ((lane & 16) ? 8 : 0) + (lane & 7)]
                                      [(lane & 8) ? 8 : 0]);
    const uint32_t BUFB = 128 * 40 * 2;

    const int r0 = tid >> 2, r1 = r0 + 64;
    const int f0 = (tid & 3) * 8;
    const __half* A0 = A + (size_t)(ridx ? ridx[r0] : r0) * EMB + f0;
    const __half* A1 = A + (size_t)(ridx ? ridx[r1] : r1) * EMB + f0;
    const __half* B0 = B + (size_t)r0 * EMB + f0;
    const __half* B1 = B + (size_t)r1 * EMB + f0;

    uint4 pa0 = *(const uint4*)A0, pa1 = *(const uint4*)A1;
    uint4 pb0 = *(const uint4*)B0, pb1 = *(const uint4*)B1;

    for (int ch = 0; ch < 16; ch++) {
        const int buf = ch & 1;
        *(uint4*)&As[buf][r0][f0] = pa0;  *(uint4*)&As[buf][r1][f0] = pa1;
        *(uint4*)&Bs[buf][r0][f0] = pb0;  *(uint4*)&Bs[buf][r1][f0] = pb1;
        if (ch + 1 < 16) {
            int co = (ch + 1) * 32;
            pa0 = *(const uint4*)(A0 + co);
            pa1 = *(const uint4*)(A1 + co);
            pb0 = *(const uint4*)(B0 + co);
            pb1 = *(const uint4*)(B1 + co);
        }
        __syncthreads();
        const uint32_t ab = a_base + buf * BUFB;
        const uint32_t bb = b_base + buf * BUFB;
        #pragma unroll
        for (int ks = 0; ks < 2; ks++) {
            uint32_t a[2][4], b[8][2];
            #pragma unroll
            for (int mt = 0; mt < 2; mt++)
                LDSM4(a[mt][0], a[mt][1], a[mt][2], a[mt][3],
                      ab + mt * 1280 + ks * 32);
            #pragma unroll
            for (int p = 0; p < 4; p++)
                LDSM4(b[2*p][0], b[2*p][1], b[2*p+1][0], b[2*p+1][1],
                      bb + p * 1280 + ks * 32);
            #pragma unroll
            for (int mt = 0; mt < 2; mt++)
                #pragma unroll
                for (int nt = 0; nt < 8; nt++)
                    MMA_F16(c[mt][nt], a[mt], b[nt]);
        }
    }
}

// Q/K/V projections. z=0: Q (scaled 0.125*log2e), z=1: K (gathered), z=2: V^T.
__global__ void __launch_bounds__(256, 2) proj_qkv_kernel(
        const __half* __restrict__ qn, const __half* __restrict__ kvn,
        const __half* __restrict__ wt,
        const float* __restrict__ bq, const float* __restrict__ bk,
        const float* __restrict__ bv,
        __half* __restrict__ q, __half* __restrict__ k,
        __half* __restrict__ vt) {
    const int z = blockIdx.z;
    const size_t bm = (size_t)blockIdx.y * 128, bn = (size_t)blockIdx.x * 128;
    const int bb = (int)(bm >> 11);
    const int rloc = (int)(bm & 2047);

    const int* ridx = nullptr;
    const __half* A;
    if (z == 0) {
        A = qn + bm * EMB;
    } else {
        if (rloc >= g_nkt[bb] * 64) return;
        A = kvn + (size_t)bb * 2048 * EMB;
        ridx = g_kidx + bb * NK + rloc;
    }
    const __half* B = wt + (size_t)z * EMB * EMB + bn * EMB;
    float c[2][8][4];
    gemm16_mainloop(A, ridx, B, c);

    const int tid = threadIdx.x, lane = tid & 31, wid = tid >> 5;
    const int wm = wid & 3, wn = wid >> 2, g = lane >> 2, t = lane & 3;
    const float* bias = (z == 0) ? bq : (z == 1) ? bk : bv;
    const float scale = (z == 0) ? 0.1803368801111244f : 1.0f;  // 0.125*log2(e)

    #pragma unroll
    for (int mt = 0; mt < 2; mt++) {
        #pragma unroll
        for (int nt = 0; nt < 8; nt++) {
            int m   = (int)bm + wm * 32 + mt * 16 + g;
            int col = (int)bn + wn * 64 + nt * 8 + 2 * t;
            float b0 = bias[col], b1 = bias[col + 1];
            float v0 = (c[mt][nt][0] + b0) * scale;
            float v1 = (c[mt][nt][1] + b1) * scale;
            float v2 = (c[mt][nt][2] + b0) * scale;
            float v3 = (c[mt][nt][3] + b1) * scale;
            if (z < 2) {
                __half* dst = (z == 0) ? q : k;
                *(half2*)(dst + (size_t)m * EMB + col) = __floats2half2_rn(v0, v1);
                *(half2*)(dst + (size_t)(m + 8) * EMB + col) = __floats2half2_rn(v2, v3);
            } else {
                int h = col >> 6, d = col & 63;
                int b_ = m >> 11;
                size_t base = ((size_t)(b_ * NH + h) * HD);
                int tok = m & 2047;
                vt[(base + d) * NK + tok]         = __float2half_rn(v0);
                vt[(base + d + 1) * NK + tok]     = __float2half_rn(v1);
                vt[(base + d) * NK + tok + 8]     = __float2half_rn(v2);
                vt[(base + d + 1) * NK + tok + 8] = __float2half_rn(v3);
            }
        }
    }
}

__global__ void __launch_bounds__(256, 2) proj_o_kernel(
        const __half* __restrict__ ctx, const __half* __restrict__ wt,
        const float* __restrict__ bo, float* __restrict__ out) {
    const size_t bm = (size_t)blockIdx.y * 128, bn = (size_t)blockIdx.x * 128;
    float c[2][8][4];
    gemm16_mainloop(ctx + bm * EMB, nullptr,
                    wt + 3ull * EMB * EMB + bn * EMB, c);

    const int tid = threadIdx.x, lane = tid & 31, wid = tid >> 5;
    const int wm = wid & 3, wn = wid >> 2, g = lane >> 2, t = lane & 3;
    #pragma unroll
    for (int mt = 0; mt < 2; mt++) {
        #pragma unroll
        for (int nt = 0; nt < 8; nt++) {
            int m   = (int)bm + wm * 32 + mt * 16 + g;
            int col = (int)bn + wn * 64 + nt * 8 + 2 * t;
            float b0 = bo[col], b1 = bo[col + 1];
            *(float2*)(out + (size_t)m * EMB + col) =
                make_float2(c[mt][nt][0] + b0, c[mt][nt][1] + b1);
            *(float2*)(out + (size_t)(m + 8) * EMB + col) =
                make_float2(c[mt][nt][2] + b0, c[mt][nt][3] + b1);
        }
    }
}

// ---------------- fused flash attention (register-resident P) -------------------
// Dynamic smem layout (halves):
//   Ks : [2][64][72]  at 0        (buf byte-stride  9216)
//   Vst: [2][80][72]  at 9216h    (buf byte-stride 11520; rows 64..79 = ones/zeros)
#define FATTN_SMEM 41472
__global__ void __launch_bounds__(256, 2) fattn_kernel(
        const __half* __restrict__ Qp, const __half* __restrict__ Kp,
        const __half* __restrict__ Vtp,
        const unsigned long long* __restrict__ mbits,
        __half* __restrict__ ctx) {
    extern __shared__ __align__(16) __half smd[];
    __half* KsB = smd;
    __half* VsB = smd + 9216;

    const int tid = threadIdx.x;
    const int lane = tid & 31, w = tid >> 5;
    const int g = lane >> 2, t = lane & 3;
    const int qt = blockIdx.x, bh = blockIdx.y;
    const int b = bh >> 3, h = bh & 7;
    const int row0 = w * 16 + g, row1 = row0 + 8;
    const int nkt = g_nkt[b];

    const uint32_t ks_smem = sptr(KsB);
    const uint32_t vs_smem = sptr(VsB);
    const uint32_t lrow = ((lane & 16) ? 8 : 0) + (lane & 7);
    const uint32_t k_base = ks_smem + lrow * 144 + ((lane & 8) ? 16 : 0);
    const uint32_t v_base = vs_smem + lrow * 144 + ((lane & 8) ? 16 : 0);

    // init ones/zeros rows 64..79 of both V buffers (row 64 = 1, rest 0)
    for (int idx = tid; idx < 2 * 16 * 72; idx += 256) {
        int bufr = idx / 72, col = idx % 72;
        int buf = bufr >> 4, row = 64 + (bufr & 15);
        VsB[buf * 5760 + row * 72 + col] =
            (row == 64) ? __float2half(1.0f) : __float2half(0.0f);
    }

    // Q fragments (pre-scaled by 0.125*log2e, fp16)
    uint32_t qa[4][4];
    {
        const __half* q0 = Qp + (size_t)(b * NQ + qt * 128 + row0) * EMB + h * HD;
        const __half* q1 = Qp + (size_t)(b * NQ + qt * 128 + row1) * EMB + h * HD;
        #pragma unroll
        for (int ks = 0; ks < 4; ks++) {
            qa[ks][0] = *(const uint32_t*)(q0 + ks * 16 + 2 * t);
            qa[ks][1] = *(const uint32_t*)(q1 + ks * 16 + 2 * t);
            qa[ks][2] = *(const uint32_t*)(q0 + ks * 16 + 2 * t + 8);
            qa[ks][3] = *(const uint32_t*)(q1 + ks * 16 + 2 * t + 8);
        }
    }

    float m0 = -40.0f, m1 = -40.0f;          // log2-domain running max
    float acc[9][4];
    #pragma unroll
    for (int nt = 0; nt < 9; nt++)
        #pragma unroll
        for (int j = 0; j < 4; j++) acc[nt][j] = 0.0f;

    const unsigned long long* mb0 =
        mbits + ((size_t)b * NQ + qt * 128 + row0) * (NK / 64);
    const unsigned long long* mb1 =
        mbits + ((size_t)b * NQ + qt * 128 + row1) * (NK / 64);

    const __half* Kbase  = Kp + ((size_t)b * NK) * EMB + h * HD;
    const __half* Vtbase = Vtp + (size_t)bh * HD * NK;

    // prologue: stage tile 0 into buf 0
    if (nkt > 0) {
        #pragma unroll
        for (int i = 0; i < 2; i++) {
            int s = tid + i * 256;
            int r = s >> 3, f = s & 7;
            CP16(ks_smem + r * 144 + f * 16,
                 Kbase + (size_t)r * EMB + f * 8);
            CP16(vs_smem + r * 144 + f * 16,
                 Vtbase + (size_t)r * NK + f * 8);
        }
        CP_COMMIT();
    }

    for (int kt = 0; kt < nkt; kt++) {
        const int buf = kt & 1;
        // hoist mask words (hide gmem latency under staging + MMAs)
        unsigned long long w0 = mb0[kt], w1 = mb1[kt];
        CP_WAIT0();
        __syncthreads();   // all data ready; all warps done with prior tile reads

        if (kt + 1 < nkt) {
            int k0n = (kt + 1) * 64;
            int nbuf = buf ^ 1;
            #pragma unroll
            for (int i = 0; i < 2; i++) {
                int s = tid + i * 256;
                int r = s >> 3, f = s & 7;
                CP16(ks_smem + nbuf * 9216 + r * 144 + f * 16,
                     Kbase + (size_t)(k0n + r) * EMB + f * 8);
                CP16(vs_smem + nbuf * 11520 + r * 144 + f * 16,
                     Vtbase + (size_t)r * NK + k0n + f * 8);
            }
            CP_COMMIT();
        }

        // S = Q @ K^T  (scores already in log2 units)
        float sc[8][4];
        #pragma unroll
        for (int nt = 0; nt < 8; nt++)
            #pragma unroll
            for (int j = 0; j < 4; j++) sc[nt][j] = 0.0f;
        const uint32_t kb = k_base + buf * 9216;
        #pragma unroll
        for (int ks = 0; ks < 4; ks++) {
            uint32_t bf[8][2];
            #pragma unroll
            for (int p = 0; p < 4; p++)
                LDSM4(bf[2*p][0], bf[2*p][1], bf[2*p+1][0], bf[2*p+1][1],
                      kb + p * 16 * 144 + ks * 32);
            #pragma unroll
            for (int nt = 0; nt < 8; nt++)
                MMA_F16(sc[nt], qa[ks], bf[nt]);
        }

        // mask + tile max
        float tm0 = -1e30f, tm1 = -1e30f;
        #pragma unroll
        for (int nt = 0; nt < 8; nt++) {
            int c0 = nt * 8 + 2 * t;
            sc[nt][0] = ((w0 >> c0) & 1)       ? sc[nt][0] : -1e30f;
            sc[nt][1] = ((w0 >> (c0 + 1)) & 1) ? sc[nt][1] : -1e30f;
            sc[nt][2] = ((w1 >> c0) & 1)       ? sc[nt][2] : -1e30f;
            sc[nt][3] = ((w1 >> (c0 + 1)) & 1) ? sc[nt][3] : -1e30f;
            tm0 = fmaxf(tm0, fmaxf(sc[nt][0], sc[nt][1]));
            tm1 = fmaxf(tm1, fmaxf(sc[nt][2], sc[nt][3]));
        }
        tm0 = fmaxf(tm0, __shfl_xor_sync(0xffffffffu, tm0, 1));
        tm0 = fmaxf(tm0, __shfl_xor_sync(0xffffffffu, tm0, 2));
        tm1 = fmaxf(tm1, __shfl_xor_sync(0xffffffffu, tm1, 1));
        tm1 = fmaxf(tm1, __shfl_xor_sync(0xffffffffu, tm1, 2));

        float mn0 = fmaxf(m0, tm0), mn1 = fmaxf(m1, tm1);  // >= -40 always
        if (__any_sync(0xffffffffu, (mn0 > m0) | (mn1 > m1))) {
            float corr0 = exp2f(m0 - mn0);
            float corr1 = exp2f(m1 - mn1);
            #pragma unroll
            for (int nt = 0; nt < 9; nt++) {
                acc[nt][0] *= corr0; acc[nt][1] *= corr0;
                acc[nt][2] *= corr1; acc[nt][3] *= corr1;
            }
            m0 = mn0;  m1 = mn1;
        }

        // P in registers: S C-fragment == PV A-fragment (FA-2 layout identity)
        uint32_t pfrag[4][4];
        #pragma unroll
        for (int ks = 0; ks < 4; ks++) {
            half2 h00 = __floats2half2_rn(sc[2*ks][0] - m0, sc[2*ks][1] - m0);
            half2 h01 = __floats2half2_rn(sc[2*ks][2] - m1, sc[2*ks][3] - m1);
            half2 h10 = __floats2half2_rn(sc[2*ks+1][0] - m0, sc[2*ks+1][1] - m0);
            half2 h11 = __floats2half2_rn(sc[2*ks+1][2] - m1, sc[2*ks+1][3] - m1);
            pfrag[ks][0] = h2ex2(*(uint32_t*)&h00);
            pfrag[ks][1] = h2ex2(*(uint32_t*)&h01);
            pfrag[ks][2] = h2ex2(*(uint32_t*)&h10);
            pfrag[ks][3] = h2ex2(*(uint32_t*)&h11);
        }

        // O += P @ V  (tile nt=8 is the ones-column -> running row sum l)
        const uint32_t vb = v_base + buf * 11520;
        #pragma unroll
        for (int ks = 0; ks < 4; ks++) {
            uint32_t bv[10][2];
            #pragma unroll
            for (int p = 0; p < 5; p++)
                LDSM4(bv[2*p][0], bv[2*p][1], bv[2*p+1][0], bv[2*p+1][1],
                      vb + p * 16 * 144 + ks * 32);
            #pragma unroll
            for (int nt = 0; nt < 9; nt++)
                MMA_F16(acc[nt], pfrag[ks], bv[nt]);
        }
        // NOTE: no end-of-tile sync needed — the top-of-loop __syncthreads
        // guarantees all warps completed these reads before re-staging.
    }

    float l0 = __shfl_sync(0xffffffffu, acc[8][0], lane & 28);
    float l1 = __shfl_sync(0xffffffffu, acc[8][2], lane & 28);
    float inv0 = (l0 > 0.0f) ? (1.0f / l0) : 0.0f;
    float inv1 = (l1 > 0.0f) ? (1.0f / l1) : 0.0f;
    __half* o0 = ctx + (size_t)(b * NQ + qt * 128 + row0) * EMB + h * HD;
    __half* o1 = ctx + (size_t)(b * NQ + qt * 128 + row1) * EMB + h * HD;
    #pragma unroll
    for (int nt = 0; nt < 8; nt++) {
        int c0 = nt * 8 + 2 * t;
        *(half2*)(o0 + c0) = __floats2half2_rn(acc[nt][0] * inv0, acc[nt][1] * inv0);
        *(half2*)(o1 + c0) = __floats2half2_rn(acc[nt][2] * inv1, acc[nt][3] * inv1);
    }
}

// ---------------- mask dtype sniff ---------------------------------------------
__global__ void detect_mask_kernel(const unsigned char* kvm_raw,
                                   const unsigned char* spm_raw) {
    __shared__ int found[2];
    if (threadIdx.x == 0) { found[0] = 0; found[1] = 0; }
    __syncthreads();
    for (int i = threadIdx.x; i < 8192; i += blockDim.x) {
        if ((i & 3) != 0) {
            if (kvm_raw[i]) atomicOr(&found[0], 1);
            if (spm_raw[i]) atomicOr(&found[1], 1);
        }
    }
    __syncthreads();
    if (threadIdx.x == 0) { g_is_byte[0] = found[0]; g_is_byte[1] = found[1]; }
}

// ---------------- kv_mask stream compaction -------------------------------------
__global__ void compact_idx_kernel(const void* kvm_raw) {
    const int b = blockIdx.x;
    const int tid = threadIdx.x;
    const int lane = tid & 31, w = tid >> 5;
    __shared__ int base;
    __shared__ int wstart[8];
    __shared__ int wcnt[8];
    if (tid == 0) base = 0;
    __syncthreads();
    const bool kb = g_is_byte[0] != 0;
    for (int c0 = 0; c0 < NK; c0 += 256) {
        int kk = c0 + tid;
        bool v = kb ? (((const unsigned char*)kvm_raw)[b * NK + kk] != 0)
                    : (((const int*)kvm_raw)[b * NK + kk] != 0);
        unsigned bal = __ballot_sync(0xffffffffu, v);
        if (lane == 0) wcnt[w] = __popc(bal);
        __syncthreads();
        if (tid == 0) {
            int s = base;
            #pragma unroll
            for (int i = 0; i < 8; i++) { wstart[i] = s; s += wcnt[i]; }
            base = s;
        }
        __syncthreads();
        if (v)
            g_kidx[b * NK + wstart[w] + __popc(bal & ((1u << lane) - 1))] = kk;
        __syncthreads();
    }
    int nv = base;
    for (int c = nv + tid; c < NK; c += 256) g_kidx[b * NK + c] = 0;
    if (tid == 0) {
        g_nvalid[b] = nv;
        g_nkt[b] = (nv + 63) >> 6;
    }
}

// ---------------- sparse-mask bits (coalesced via smem) --------------------------
__global__ void __launch_bounds__(256) mask_bits_kernel(const void* spm_raw) {
    __shared__ unsigned char sp_sm[2048];
    __shared__ uint32_t wb[64];
    const int bq = blockIdx.x;
    const int b = bq >> 11;
    const int tid = threadIdx.x;

    if (g_is_byte[1]) {
        const uint32_t* sp = (const uint32_t*)
            ((const unsigned char*)spm_raw + (size_t)bq * NK);
        for (int i = tid; i < 512; i += 256) {
            uint32_t v = sp[i];
            sp_sm[i * 4 + 0] = (v & 0x000000ffu) ? 1 : 0;
            sp_sm[i * 4 + 1] = (v & 0x0000ff00u) ? 1 : 0;
            sp_sm[i * 4 + 2] = (v & 0x00ff0000u) ? 1 : 0;
            sp_sm[i * 4 + 3] = (v & 0xff000000u) ? 1 : 0;
        }
    } else {
        const int* sp = (const int*)spm_raw + (size_t)bq * NK;
        for (int i = tid; i < 2048; i += 256)
            sp_sm[i] = sp[i] ? 1 : 0;
    }
    __syncthreads();

    const int nv = g_nvalid[b];
    const int* kidx = g_kidx + b * NK;
    #pragma unroll
    for (int i = 0; i < 8; i++) {
        int c = i * 256 + tid;
        bool bit = (c < nv) && (sp_sm[kidx[c]] != 0);
        unsigned bal = __ballot_sync(0xffffffffu, bit);
        if ((tid & 31) == 0) wb[i * 8 + (tid >> 5)] = bal;
    }
    __syncthreads();
    if (tid < 32) {
        int i = tid >> 2, wp = (tid & 3) * 2;
        uint64_t wv = (uint64_t)wb[i * 8 + wp] |
                      ((uint64_t)wb[i * 8 + wp + 1] << 32);
        g_mbits[(size_t)bq * 32 + tid] = wv;
    }
}

// ---------------- LayerNorm ------------------------------------------------------
__global__ void lnorm_kernel(const float* __restrict__ xq,
                             const float* __restrict__ xkv,
                             const float* __restrict__ gq,
                             const float* __restrict__ bq,
                             const float* __restrict__ gkv,
                             const float* __restrict__ bkv,
                             __half* __restrict__ yq,
                             __half* __restrict__ ykv) {
    __shared__ float red[8];
    int row = blockIdx.x, t = threadIdx.x;
    const float* x = blockIdx.y ? xkv : xq;
    const float* g = blockIdx.y ? gkv : gq;
    const float* b = blockIdx.y ? bkv : bq;
    __half* y      = blockIdx.y ? ykv : yq;

    float4 v = ((const float4*)(x + (size_t)row * EMB))[t];
    float s  = v.x + v.y + v.z + v.w;
    float s2 = v.x*v.x + v.y*v.y + v.z*v.z + v.w*v.w;
    #pragma unroll
    for (int o = 16; o > 0; o >>= 1) {
        s  += __shfl_xor_sync(0xffffffffu, s,  o);
        s2 += __shfl_xor_sync(0xffffffffu, s2, o);
    }
    if ((t & 31) == 0) { red[t >> 5] = s; red[4 + (t >> 5)] = s2; }
    __syncthreads();
    float tot  = red[0] + red[1] + red[2] + red[3];
    float tot2 = red[4] + red[5] + red[6] + red[7];
    float mu  = tot * (1.0f / EMB);
    float var = tot2 * (1.0f / EMB) - mu * mu;
    float inv = rsqrtf(var + 1e-5f);
    float4 gg = ((const float4*)g)[t];
    float4 bb = ((const float4*)b)[t];
    float o0 = (v.x - mu) * inv * gg.x + bb.x;
    float o1 = (v.y - mu) * inv * gg.y + bb.y;
    float o2 = (v.z - mu) * inv * gg.z + bb.z;
    float o3 = (v.w - mu) * inv * gg.w + bb.w;
    __half* yr = y + (size_t)row * EMB + t * 4;
    *(half2*)(yr)     = __floats2half2_rn(o0, o1);
    *(half2*)(yr + 2) = __floats2half2_rn(o2, o3);
}

// ---------------- weight transpose ------------------------------------------------
__global__ void wt_kernel(const float* __restrict__ Wq,
                          const float* __restrict__ Wk,
                          const float* __restrict__ Wv,
                          const float* __restrict__ Wo,
                          __half* __restrict__ Wt) {
    __shared__ float tile[32][33];
    int z = blockIdx.z;
    const float* W = (z == 0) ? Wq : (z == 1) ? Wk : (z == 2) ? Wv : Wo;
    __half* dst = Wt + (size_t)z * EMB * EMB;
    int bx = blockIdx.x * 32, by = blockIdx.y * 32;
    int tx = threadIdx.x, ty = threadIdx.y;
    #pragma unroll
    for (int i = 0; i < 4; i++)
        tile[ty + i * 8][tx] = W[(size_t)(by + ty + i * 8) * EMB + bx + tx];
    __syncthreads();
    #pragma unroll
    for (int i = 0; i < 4; i++)
        dst[(size_t)(bx + ty + i * 8) * EMB + by + tx] =
            __float2half_rn(tile[tx][ty + i * 8]);
}

// ---------------- launch ----------------------------------------------------------
extern "C" void kernel_launch(void* const* d_in, const int* in_sizes, int n_in,
                              void* d_out, int out_size) {
    const float* query     = (const float*)d_in[0];
    const float* key_value = (const float*)d_in[1];
    const void*  kvm_raw   = d_in[2];
    const void*  spm_raw   = d_in[3];
    const float* ln_q_g  = (const float*)d_in[4];
    const float* ln_q_b  = (const float*)d_in[5];
    const float* ln_kv_g = (const float*)d_in[6];
    const float* ln_kv_b = (const float*)d_in[7];
    const float* Wq = (const float*)d_in[8];
    const float* bq = (const float*)d_in[9];
    const float* Wk = (const float*)d_in[10];
    const float* bk = (const float*)d_in[11];
    const float* Wv = (const float*)d_in[12];
    const float* bv = (const float*)d_in[13];
    const float* Wo = (const float*)d_in[14];
    const float* bo = (const float*)d_in[15];
    float* out = (float*)d_out;

    void *p_qn, *p_kvn, *p_q, *p_k, *p_vt, *p_ctx, *p_wt, *p_mb;
    cudaGetSymbolAddress(&p_qn,  g_qn);
    cudaGetSymbolAddress(&p_kvn, g_kvn);
    cudaGetSymbolAddress(&p_q,   g_q);
    cudaGetSymbolAddress(&p_k,   g_k);
    cudaGetSymbolAddress(&p_vt,  g_vt);
    cudaGetSymbolAddress(&p_ctx, g_ctx);
    cudaGetSymbolAddress(&p_wt,  g_wt);
    cudaGetSymbolAddress(&p_mb,  g_mbits);

    const bool fork = g_si.ok;
    cudaStream_t sm = fork ? g_si.s2 : (cudaStream_t)0;

    if (fork) {
        cudaEventRecord(g_si.eFork, 0);
        cudaStreamWaitEvent(g_si.s2, g_si.eFork, 0);
    }
    // mask branch (stream sm)
    detect_mask_kernel<<<1, 256, 0, sm>>>((const unsigned char*)kvm_raw,
                                          (const unsigned char*)spm_raw);
    compact_idx_kernel<<<BATCH, 256, 0, sm>>>(kvm_raw);
    if (fork) cudaEventRecord(g_si.eCompact, g_si.s2);
    mask_bits_kernel<<<BATCH * NQ, 256, 0, sm>>>(spm_raw);
    if (fork) cudaEventRecord(g_si.eMask, g_si.s2);

    // main branch (default stream)
    dim3 lg(NTOK, 2);
    lnorm_kernel<<<lg, 128>>>(query, key_value, ln_q_g, ln_q_b,
                              ln_kv_g, ln_kv_b,
                              (__half*)p_qn, (__half*)p_kvn);

    dim3 tb(32, 8), tg(16, 16, 4);
    wt_kernel<<<tg, tb>>>(Wq, Wk, Wv, Wo, (__half*)p_wt);

    if (fork) cudaStreamWaitEvent(0, g_si.eCompact, 0);   // proj needs kidx/nkt
    dim3 pg(EMB / 128, NTOK / 128, 3);
    proj_qkv_kernel<<<pg, 256>>>((const __half*)p_qn, (const __half*)p_kvn,
                                 (const __half*)p_wt, bq, bk, bv,
                                 (__half*)p_q, (__half*)p_k, (__half*)p_vt);

    if (fork) cudaStreamWaitEvent(0, g_si.eMask, 0);      // fattn needs mbits
    cudaFuncSetAttribute(fattn_kernel,
        cudaFuncAttributeMaxDynamicSharedMemorySize, FATTN_SMEM);
    dim3 fg(NQ / 128, BHN);
    fattn_kernel<<<fg, 256, FATTN_SMEM>>>((const __half*)p_q, (const __half*)p_k,
                              (const __half*)p_vt,
                              (const unsigned long long*)p_mb,
                              (__half*)p_ctx);

    dim3 og(EMB / 128, NTOK / 128);
    proj_o_kernel<<<og, 256>>>((const __half*)p_ctx, (const __half*)p_wt,
                               bo, out);
}

// round 13
// speedup vs baseline: 2.2137x; 1.0465x over previous
#include <cuda_runtime.h>
#include <cuda_fp16.h>
#include <cstdint>
#include <cstddef>

#define BATCH 4
#define NQ    2048
#define NK    2048
#define EMB   512
#define NH    8
#define HD    64
#define NTOK  (BATCH * NQ)
#define BHN   (BATCH * NH)

// ---------------- device-global scratch ---------------------------------------
__device__ __half g_qn [NTOK * EMB];
__device__ __half g_kvn[NTOK * EMB];
__device__ __half g_q  [NTOK * EMB];          // pre-scaled by 0.125*log2(e)
__device__ __half g_k  [NTOK * EMB];          // COMPACTED rows per batch
__device__ __half g_vt [BHN * HD * NK];       // V^T per (b,h): [d][compacted key]
__device__ __half g_ctx[NTOK * EMB];
__device__ __half g_wt [4 * EMB * EMB];       // W^T, k-major rows
__device__ unsigned long long g_mbits[(size_t)BATCH * NQ * (NK / 64)];
__device__ int g_kidx[BATCH * NK];
__device__ int g_nvalid[BATCH];
__device__ int g_nkt[BATCH];
__device__ int g_is_byte[2];

// ---------------- streams/events for graph-parallel branches -------------------
struct StreamInit {
    cudaStream_t s2 = nullptr, s3 = nullptr;
    cudaEvent_t eFork = nullptr, eCompact = nullptr, eMask = nullptr, eWt = nullptr;
    bool ok = false;
    StreamInit() {
        if (cudaStreamCreateWithFlags(&s2, cudaStreamNonBlocking) != cudaSuccess) return;
        if (cudaStreamCreateWithFlags(&s3, cudaStreamNonBlocking) != cudaSuccess) return;
        if (cudaEventCreateWithFlags(&eFork, cudaEventDisableTiming) != cudaSuccess) return;
        if (cudaEventCreateWithFlags(&eCompact, cudaEventDisableTiming) != cudaSuccess) return;
        if (cudaEventCreateWithFlags(&eMask, cudaEventDisableTiming) != cudaSuccess) return;
        if (cudaEventCreateWithFlags(&eWt, cudaEventDisableTiming) != cudaSuccess) return;
        ok = true;
    }
};
static StreamInit g_si;

// ---------------- PTX helpers --------------------------------------------------
__device__ __forceinline__ uint32_t sptr(const void* p) {
    uint32_t a;
    asm("{ .reg .u64 t; cvta.to.shared.u64 t, %1; cvt.u32.u64 %0, t; }"
        : "=r"(a) : "l"(p));
    return a;
}
__device__ __forceinline__ uint32_t h2ex2(uint32_t x) {
    uint32_t r;
    asm("ex2.approx.f16x2 %0, %1;" : "=r"(r) : "r"(x));
    return r;
}

#define MMA_F16(C, A, B) \
    asm volatile( \
        "mma.sync.aligned.m16n8k16.row.col.f32.f16.f16.f32 " \
        "{%0,%1,%2,%3}, {%4,%5,%6,%7}, {%8,%9}, {%0,%1,%2,%3};" \
        : "+f"((C)[0]), "+f"((C)[1]), "+f"((C)[2]), "+f"((C)[3]) \
        : "r"((A)[0]), "r"((A)[1]), "r"((A)[2]), "r"((A)[3]), \
          "r"((B)[0]), "r"((B)[1]))

#define LDSM4(R0, R1, R2, R3, ADDR) \
    asm volatile("ldmatrix.sync.aligned.m8n8.x4.shared.b16 {%0,%1,%2,%3}, [%4];" \
        : "=r"(R0), "=r"(R1), "=r"(R2), "=r"(R3) : "r"(ADDR))

#define CP16(DST, SRC) \
    asm volatile("cp.async.cg.shared.global [%0], [%1], 16;" \
        :: "r"(DST), "l"(SRC))
#define CP_COMMIT() asm volatile("cp.async.commit_group;" ::: "memory")
#define CP_WAIT0()  asm volatile("cp.async.wait_group 0;" ::: "memory")

// ---------------- fp16 GEMM mainloop: BK=64, cp.async double-buffered ----------
// Dynamic smem: A at buf*36864, B at buf*36864+18432; row stride 144 B.
#define GSMEM 73728
__device__ __forceinline__ void gemm16_mainloop(
        const __half* __restrict__ A, const int* __restrict__ ridx,
        const __half* __restrict__ B, float (&c)[2][8][4], char* sm) {
    const int tid = threadIdx.x;
    const int lane = tid & 31, wid = tid >> 5;
    const int wm = wid & 3, wn = wid >> 2;
    const uint32_t s0 = sptr(sm);

    #pragma unroll
    for (int mt = 0; mt < 2; mt++)
        #pragma unroll
        for (int nt = 0; nt < 8; nt++)
            #pragma unroll
            for (int j = 0; j < 4; j++) c[mt][nt][j] = 0.0f;

    const uint32_t a_base = s0 +
        (wm * 32 + ((lane & 8) ? 8 : 0) + (lane & 7)) * 144 + ((lane & 16) ? 16 : 0);
    const uint32_t b_base = s0 + 18432 +
        (wn * 64 + ((lane & 16) ? 8 : 0) + (lane & 7)) * 144 + ((lane & 8) ? 16 : 0);

    const int rbase = tid >> 3;             // staging row base (0..31)
    const int fh = (tid & 7) * 8;           // gmem half offset
    const uint32_t fB = (tid & 7) * 16;     // smem byte offset
    int ar[4];
    #pragma unroll
    for (int i = 0; i < 4; i++)
        ar[i] = ridx ? ridx[rbase + 32 * i] : (rbase + 32 * i);

    // prologue: stage chunk 0 -> buf 0
    #pragma unroll
    for (int i = 0; i < 4; i++) {
        int r = rbase + 32 * i;
        CP16(s0 + r * 144 + fB, A + (size_t)ar[i] * EMB + fh);
        CP16(s0 + 18432 + r * 144 + fB, B + (size_t)r * EMB + fh);
    }
    CP_COMMIT();

    for (int ch = 0; ch < 8; ch++) {
        const int buf = ch & 1;
        CP_WAIT0();
        __syncthreads();
        if (ch + 1 < 8) {
            const uint32_t nb = (uint32_t)((ch + 1) & 1) * 36864u;
            const int co = (ch + 1) * 64 + fh;
            #pragma unroll
            for (int i = 0; i < 4; i++) {
                int r = rbase + 32 * i;
                CP16(s0 + nb + r * 144 + fB, A + (size_t)ar[i] * EMB + co);
                CP16(s0 + nb + 18432 + r * 144 + fB, B + (size_t)r * EMB + co);
            }
            CP_COMMIT();
        }
        const uint32_t ab = a_base + buf * 36864u;
        const uint32_t bb = b_base + buf * 36864u;
        #pragma unroll
        for (int ks = 0; ks < 4; ks++) {
            uint32_t a[2][4], b[8][2];
            #pragma unroll
            for (int mt = 0; mt < 2; mt++)
                LDSM4(a[mt][0], a[mt][1], a[mt][2], a[mt][3],
                      ab + mt * 16 * 144 + ks * 32);
            #pragma unroll
            for (int p = 0; p < 4; p++)
                LDSM4(b[2*p][0], b[2*p][1], b[2*p+1][0], b[2*p+1][1],
                      bb + p * 16 * 144 + ks * 32);
            #pragma unroll
            for (int mt = 0; mt < 2; mt++)
                #pragma unroll
                for (int nt = 0; nt < 8; nt++)
                    MMA_F16(c[mt][nt], a[mt], b[nt]);
        }
        // top-of-loop __syncthreads covers buffer reuse
    }
}

// Q/K/V projections. z=0: Q (scaled 0.125*log2e), z=1: K (gathered), z=2: V^T.
__global__ void __launch_bounds__(256, 2) proj_qkv_kernel(
        const __half* __restrict__ qn, const __half* __restrict__ kvn,
        const __half* __restrict__ wt,
        const float* __restrict__ bq, const float* __restrict__ bk,
        const float* __restrict__ bv,
        __half* __restrict__ q, __half* __restrict__ k,
        __half* __restrict__ vt) {
    extern __shared__ __align__(16) char smqkv[];
    const int z = blockIdx.z;
    const size_t bm = (size_t)blockIdx.y * 128, bn = (size_t)blockIdx.x * 128;
    const int bb = (int)(bm >> 11);
    const int rloc = (int)(bm & 2047);

    const int* ridx = nullptr;
    const __half* A;
    if (z == 0) {
        A = qn + bm * EMB;
    } else {
        if (rloc >= g_nkt[bb] * 64) return;
        A = kvn + (size_t)bb * 2048 * EMB;
        ridx = g_kidx + bb * NK + rloc;
    }
    const __half* B = wt + (size_t)z * EMB * EMB + bn * EMB;
    float c[2][8][4];
    gemm16_mainloop(A, ridx, B, c, smqkv);

    const int tid = threadIdx.x, lane = tid & 31, wid = tid >> 5;
    const int wm = wid & 3, wn = wid >> 2, g = lane >> 2, t = lane & 3;
    const float* bias = (z == 0) ? bq : (z == 1) ? bk : bv;
    const float scale = (z == 0) ? 0.1803368801111244f : 1.0f;  // 0.125*log2(e)

    if (z < 2) {
        #pragma unroll
        for (int mt = 0; mt < 2; mt++) {
            #pragma unroll
            for (int nt = 0; nt < 8; nt++) {
                int m   = (int)bm + wm * 32 + mt * 16 + g;
                int col = (int)bn + wn * 64 + nt * 8 + 2 * t;
                float b0 = bias[col], b1 = bias[col + 1];
                float v0 = (c[mt][nt][0] + b0) * scale;
                float v1 = (c[mt][nt][1] + b1) * scale;
                float v2 = (c[mt][nt][2] + b0) * scale;
                float v3 = (c[mt][nt][3] + b1) * scale;
                __half* dst = (z == 0) ? q : k;
                *(half2*)(dst + (size_t)m * EMB + col) = __floats2half2_rn(v0, v1);
                *(half2*)(dst + (size_t)(m + 8) * EMB + col) = __floats2half2_rn(v2, v3);
            }
        }
    } else {
        // V^T: transpose through smem [col][m], stride 136 halves (16B-aligned rows)
        __half* smT = (__half*)smqkv;
        __syncthreads();   // done with GEMM smem
        #pragma unroll
        for (int mt = 0; mt < 2; mt++) {
            #pragma unroll
            for (int nt = 0; nt < 8; nt++) {
                int m   = wm * 32 + mt * 16 + g;           // block-local token
                int col = wn * 64 + nt * 8 + 2 * t;        // block-local channel
                float b0 = bias[(int)bn + col], b1 = bias[(int)bn + col + 1];
                smT[col * 136 + m]           = __float2half_rn(c[mt][nt][0] + b0);
                smT[(col + 1) * 136 + m]     = __float2half_rn(c[mt][nt][1] + b1);
                smT[col * 136 + m + 8]       = __float2half_rn(c[mt][nt][2] + b0);
                smT[(col + 1) * 136 + m + 8] = __float2half_rn(c[mt][nt][3] + b1);
            }
        }
        __syncthreads();
        // coalesced writes: thread -> (col = tid/2, 64-half chunk = tid&1)
        int col = tid >> 1;
        int mo  = (tid & 1) * 64;
        int gc  = (int)bn + col;                 // global channel
        int h = gc >> 6, d = gc & 63;
        size_t orow = ((size_t)(bb * NH + h) * HD + d) * NK + (size_t)rloc + mo;
        const uint4* srcp = (const uint4*)(smT + col * 136 + mo);
        uint4* dstp = (uint4*)(vt + orow);
        #pragma unroll
        for (int j = 0; j < 8; j++) dstp[j] = srcp[j];
    }
}

__global__ void __launch_bounds__(256, 2) proj_o_kernel(
        const __half* __restrict__ ctx, const __half* __restrict__ wt,
        const float* __restrict__ bo, float* __restrict__ out) {
    extern __shared__ __align__(16) char smo[];
    const size_t bm = (size_t)blockIdx.y * 128, bn = (size_t)blockIdx.x * 128;
    float c[2][8][4];
    gemm16_mainloop(ctx + bm * EMB, nullptr,
                    wt + 3ull * EMB * EMB + bn * EMB, c, smo);

    const int tid = threadIdx.x, lane = tid & 31, wid = tid >> 5;
    const int wm = wid & 3, wn = wid >> 2, g = lane >> 2, t = lane & 3;
    #pragma unroll
    for (int mt = 0; mt < 2; mt++) {
        #pragma unroll
        for (int nt = 0; nt < 8; nt++) {
            int m   = (int)bm + wm * 32 + mt * 16 + g;
            int col = (int)bn + wn * 64 + nt * 8 + 2 * t;
            float b0 = bo[col], b1 = bo[col + 1];
            *(float2*)(out + (size_t)m * EMB + col) =
                make_float2(c[mt][nt][0] + b0, c[mt][nt][1] + b1);
            *(float2*)(out + (size_t)(m + 8) * EMB + col) =
                make_float2(c[mt][nt][2] + b0, c[mt][nt][3] + b1);
        }
    }
}

// ---------------- fused flash attention (register-resident P) -------------------
#define FATTN_SMEM 41472
__global__ void __launch_bounds__(256, 2) fattn_kernel(
        const __half* __restrict__ Qp, const __half* __restrict__ Kp,
        const __half* __restrict__ Vtp,
        const unsigned long long* __restrict__ mbits,
        __half* __restrict__ ctx) {
    extern __shared__ __align__(16) __half smd[];
    __half* KsB = smd;
    __half* VsB = smd + 9216;

    const int tid = threadIdx.x;
    const int lane = tid & 31, w = tid >> 5;
    const int g = lane >> 2, t = lane & 3;
    const int qt = blockIdx.x, bh = blockIdx.y;
    const int b = bh >> 3, h = bh & 7;
    const int row0 = w * 16 + g, row1 = row0 + 8;
    const int nkt = g_nkt[b];

    const uint32_t ks_smem = sptr(KsB);
    const uint32_t vs_smem = sptr(VsB);
    const uint32_t lrow = ((lane & 16) ? 8 : 0) + (lane & 7);
    const uint32_t k_base = ks_smem + lrow * 144 + ((lane & 8) ? 16 : 0);
    const uint32_t v_base = vs_smem + lrow * 144 + ((lane & 8) ? 16 : 0);

    for (int idx = tid; idx < 2 * 16 * 72; idx += 256) {
        int bufr = idx / 72, col = idx % 72;
        int buf = bufr >> 4, row = 64 + (bufr & 15);
        VsB[buf * 5760 + row * 72 + col] =
            (row == 64) ? __float2half(1.0f) : __float2half(0.0f);
    }

    uint32_t qa[4][4];
    {
        const __half* q0 = Qp + (size_t)(b * NQ + qt * 128 + row0) * EMB + h * HD;
        const __half* q1 = Qp + (size_t)(b * NQ + qt * 128 + row1) * EMB + h * HD;
        #pragma unroll
        for (int ks = 0; ks < 4; ks++) {
            qa[ks][0] = *(const uint32_t*)(q0 + ks * 16 + 2 * t);
            qa[ks][1] = *(const uint32_t*)(q1 + ks * 16 + 2 * t);
            qa[ks][2] = *(const uint32_t*)(q0 + ks * 16 + 2 * t + 8);
            qa[ks][3] = *(const uint32_t*)(q1 + ks * 16 + 2 * t + 8);
        }
    }

    float m0 = -40.0f, m1 = -40.0f;
    float acc[9][4];
    #pragma unroll
    for (int nt = 0; nt < 9; nt++)
        #pragma unroll
        for (int j = 0; j < 4; j++) acc[nt][j] = 0.0f;

    const unsigned long long* mb0 =
        mbits + ((size_t)b * NQ + qt * 128 + row0) * (NK / 64);
    const unsigned long long* mb1 =
        mbits + ((size_t)b * NQ + qt * 128 + row1) * (NK / 64);

    const __half* Kbase  = Kp + ((size_t)b * NK) * EMB + h * HD;
    const __half* Vtbase = Vtp + (size_t)bh * HD * NK;

    if (nkt > 0) {
        #pragma unroll
        for (int i = 0; i < 2; i++) {
            int s = tid + i * 256;
            int r = s >> 3, f = s & 7;
            CP16(ks_smem + r * 144 + f * 16, Kbase + (size_t)r * EMB + f * 8);
            CP16(vs_smem + r * 144 + f * 16, Vtbase + (size_t)r * NK + f * 8);
        }
        CP_COMMIT();
    }

    for (int kt = 0; kt < nkt; kt++) {
        const int buf = kt & 1;
        unsigned long long w0 = mb0[kt], w1 = mb1[kt];
        CP_WAIT0();
        __syncthreads();

        if (kt + 1 < nkt) {
            int k0n = (kt + 1) * 64;
            int nbuf = buf ^ 1;
            #pragma unroll
            for (int i = 0; i < 2; i++) {
                int s = tid + i * 256;
                int r = s >> 3, f = s & 7;
                CP16(ks_smem + nbuf * 9216 + r * 144 + f * 16,
                     Kbase + (size_t)(k0n + r) * EMB + f * 8);
                CP16(vs_smem + nbuf * 11520 + r * 144 + f * 16,
                     Vtbase + (size_t)r * NK + k0n + f * 8);
            }
            CP_COMMIT();
        }

        float sc[8][4];
        #pragma unroll
        for (int nt = 0; nt < 8; nt++)
            #pragma unroll
            for (int j = 0; j < 4; j++) sc[nt][j] = 0.0f;
        const uint32_t kb = k_base + buf * 9216;
        #pragma unroll
        for (int ks = 0; ks < 4; ks++) {
            uint32_t bf[8][2];
            #pragma unroll
            for (int p = 0; p < 4; p++)
                LDSM4(bf[2*p][0], bf[2*p][1], bf[2*p+1][0], bf[2*p+1][1],
                      kb + p * 16 * 144 + ks * 32);
            #pragma unroll
            for (int nt = 0; nt < 8; nt++)
                MMA_F16(sc[nt], qa[ks], bf[nt]);
        }

        float tm0 = -1e30f, tm1 = -1e30f;
        #pragma unroll
        for (int nt = 0; nt < 8; nt++) {
            int c0 = nt * 8 + 2 * t;
            sc[nt][0] = ((w0 >> c0) & 1)       ? sc[nt][0] : -1e30f;
            sc[nt][1] = ((w0 >> (c0 + 1)) & 1) ? sc[nt][1] : -1e30f;
            sc[nt][2] = ((w1 >> c0) & 1)       ? sc[nt][2] : -1e30f;
            sc[nt][3] = ((w1 >> (c0 + 1)) & 1) ? sc[nt][3] : -1e30f;
            tm0 = fmaxf(tm0, fmaxf(sc[nt][0], sc[nt][1]));
            tm1 = fmaxf(tm1, fmaxf(sc[nt][2], sc[nt][3]));
        }
        tm0 = fmaxf(tm0, __shfl_xor_sync(0xffffffffu, tm0, 1));
        tm0 = fmaxf(tm0, __shfl_xor_sync(0xffffffffu, tm0, 2));
        tm1 = fmaxf(tm1, __shfl_xor_sync(0xffffffffu, tm1, 1));
        tm1 = fmaxf(tm1, __shfl_xor_sync(0xffffffffu, tm1, 2));

        float mn0 = fmaxf(m0, tm0), mn1 = fmaxf(m1, tm1);
        if (__any_sync(0xffffffffu, (mn0 > m0) | (mn1 > m1))) {
            float corr0 = exp2f(m0 - mn0);
            float corr1 = exp2f(m1 - mn1);
            #pragma unroll
            for (int nt = 0; nt < 9; nt++) {
                acc[nt][0] *= corr0; acc[nt][1] *= corr0;
                acc[nt][2] *= corr1; acc[nt][3] *= corr1;
            }
            m0 = mn0;  m1 = mn1;
        }

        uint32_t pfrag[4][4];
        #pragma unroll
        for (int ks = 0; ks < 4; ks++) {
            half2 h00 = __floats2half2_rn(sc[2*ks][0] - m0, sc[2*ks][1] - m0);
            half2 h01 = __floats2half2_rn(sc[2*ks][2] - m1, sc[2*ks][3] - m1);
            half2 h10 = __floats2half2_rn(sc[2*ks+1][0] - m0, sc[2*ks+1][1] - m0);
            half2 h11 = __floats2half2_rn(sc[2*ks+1][2] - m1, sc[2*ks+1][3] - m1);
            pfrag[ks][0] = h2ex2(*(uint32_t*)&h00);
            pfrag[ks][1] = h2ex2(*(uint32_t*)&h01);
            pfrag[ks][2] = h2ex2(*(uint32_t*)&h10);
            pfrag[ks][3] = h2ex2(*(uint32_t*)&h11);
        }

        const uint32_t vb = v_base + buf * 11520;
        #pragma unroll
        for (int ks = 0; ks < 4; ks++) {
            uint32_t bv[10][2];
            #pragma unroll
            for (int p = 0; p < 5; p++)
                LDSM4(bv[2*p][0], bv[2*p][1], bv[2*p+1][0], bv[2*p+1][1],
                      vb + p * 16 * 144 + ks * 32);
            #pragma unroll
            for (int nt = 0; nt < 9; nt++)
                MMA_F16(acc[nt], pfrag[ks], bv[nt]);
        }
    }

    float l0 = __shfl_sync(0xffffffffu, acc[8][0], lane & 28);
    float l1 = __shfl_sync(0xffffffffu, acc[8][2], lane & 28);
    float inv0 = (l0 > 0.0f) ? (1.0f / l0) : 0.0f;
    float inv1 = (l1 > 0.0f) ? (1.0f / l1) : 0.0f;
    __half* o0 = ctx + (size_t)(b * NQ + qt * 128 + row0) * EMB + h * HD;
    __half* o1 = ctx + (size_t)(b * NQ + qt * 128 + row1) * EMB + h * HD;
    #pragma unroll
    for (int nt = 0; nt < 8; nt++) {
        int c0 = nt * 8 + 2 * t;
        *(half2*)(o0 + c0) = __floats2half2_rn(acc[nt][0] * inv0, acc[nt][1] * inv0);
        *(half2*)(o1 + c0) = __floats2half2_rn(acc[nt][2] * inv1, acc[nt][3] * inv1);
    }
}

// ---------------- mask dtype sniff ---------------------------------------------
__global__ void detect_mask_kernel(const unsigned char* kvm_raw,
                                   const unsigned char* spm_raw) {
    __shared__ int found[2];
    if (threadIdx.x == 0) { found[0] = 0; found[1] = 0; }
    __syncthreads();
    for (int i = threadIdx.x; i < 8192; i += blockDim.x) {
        if ((i & 3) != 0) {
            if (kvm_raw[i]) atomicOr(&found[0], 1);
            if (spm_raw[i]) atomicOr(&found[1], 1);
        }
    }
    __syncthreads();
    if (threadIdx.x == 0) { g_is_byte[0] = found[0]; g_is_byte[1] = found[1]; }
}

// ---------------- kv_mask stream compaction -------------------------------------
__global__ void compact_idx_kernel(const void* kvm_raw) {
    const int b = blockIdx.x;
    const int tid = threadIdx.x;
    const int lane = tid & 31, w = tid >> 5;
    __shared__ int base;
    __shared__ int wstart[8];
    __shared__ int wcnt[8];
    if (tid == 0) base = 0;
    __syncthreads();
    const bool kb = g_is_byte[0] != 0;
    for (int c0 = 0; c0 < NK; c0 += 256) {
        int kk = c0 + tid;
        bool v = kb ? (((const unsigned char*)kvm_raw)[b * NK + kk] != 0)
                    : (((const int*)kvm_raw)[b * NK + kk] != 0);
        unsigned bal = __ballot_sync(0xffffffffu, v);
        if (lane == 0) wcnt[w] = __popc(bal);
        __syncthreads();
        if (tid == 0) {
            int s = base;
            #pragma unroll
            for (int i = 0; i < 8; i++) { wstart[i] = s; s += wcnt[i]; }
            base = s;
        }
        __syncthreads();
        if (v)
            g_kidx[b * NK + wstart[w] + __popc(bal & ((1u << lane) - 1))] = kk;
        __syncthreads();
    }
    int nv = base;
    for (int c = nv + tid; c < NK; c += 256) g_kidx[b * NK + c] = 0;
    if (tid == 0) {
        g_nvalid[b] = nv;
        g_nkt[b] = (nv + 63) >> 6;
    }
}

// ---------------- sparse-mask bits (coalesced via smem) --------------------------
__global__ void __launch_bounds__(256) mask_bits_kernel(const void* spm_raw) {
    __shared__ unsigned char sp_sm[2048];
    __shared__ uint32_t wb[64];
    const int bq = blockIdx.x;
    const int b = bq >> 11;
    const int tid = threadIdx.x;

    if (g_is_byte[1]) {
        const uint32_t* sp = (const uint32_t*)
            ((const unsigned char*)spm_raw + (size_t)bq * NK);
        for (int i = tid; i < 512; i += 256) {
            uint32_t v = sp[i];
            sp_sm[i * 4 + 0] = (v & 0x000000ffu) ? 1 : 0;
            sp_sm[i * 4 + 1] = (v & 0x0000ff00u) ? 1 : 0;
            sp_sm[i * 4 + 2] = (v & 0x00ff0000u) ? 1 : 0;
            sp_sm[i * 4 + 3] = (v & 0xff000000u) ? 1 : 0;
        }
    } else {
        const int* sp = (const int*)spm_raw + (size_t)bq * NK;
        for (int i = tid; i < 2048; i += 256)
            sp_sm[i] = sp[i] ? 1 : 0;
    }
    __syncthreads();

    const int nv = g_nvalid[b];
    const int* kidx = g_kidx + b * NK;
    #pragma unroll
    for (int i = 0; i < 8; i++) {
        int c = i * 256 + tid;
        bool bit = (c < nv) && (sp_sm[kidx[c]] != 0);
        unsigned bal = __ballot_sync(0xffffffffu, bit);
        if ((tid & 31) == 0) wb[i * 8 + (tid >> 5)] = bal;
    }
    __syncthreads();
    if (tid < 32) {
        int i = tid >> 2, wp = (tid & 3) * 2;
        uint64_t wv = (uint64_t)wb[i * 8 + wp] |
                      ((uint64_t)wb[i * 8 + wp + 1] << 32);
        g_mbits[(size_t)bq * 32 + tid] = wv;
    }
}

// ---------------- LayerNorm (warp-per-row, shuffle-only) ------------------------
__global__ void __launch_bounds__(256) lnorm_kernel(
        const float* __restrict__ xq, const float* __restrict__ xkv,
        const float* __restrict__ gq, const float* __restrict__ bq,
        const float* __restrict__ gkv, const float* __restrict__ bkv,
        __half* __restrict__ yq, __half* __restrict__ ykv) {
    const int row = blockIdx.x * 8 + (threadIdx.x >> 5);
    const int lane = threadIdx.x & 31;
    const float* x = blockIdx.y ? xkv : xq;
    const float* g = blockIdx.y ? gkv : gq;
    const float* b = blockIdx.y ? bkv : bq;
    __half* y      = blockIdx.y ? ykv : yq;

    const float4* xr = (const float4*)(x + (size_t)row * EMB);
    float4 v[4];
    float s = 0.0f, s2 = 0.0f;
    #pragma unroll
    for (int j = 0; j < 4; j++) {
        v[j] = xr[lane + 32 * j];
        s  += v[j].x + v[j].y + v[j].z + v[j].w;
        s2 += v[j].x*v[j].x + v[j].y*v[j].y + v[j].z*v[j].z + v[j].w*v[j].w;
    }
    #pragma unroll
    for (int o = 16; o > 0; o >>= 1) {
        s  += __shfl_xor_sync(0xffffffffu, s,  o);
        s2 += __shfl_xor_sync(0xffffffffu, s2, o);
    }
    float mu  = s * (1.0f / EMB);
    float var = s2 * (1.0f / EMB) - mu * mu;
    float inv = rsqrtf(var + 1e-5f);
    #pragma unroll
    for (int j = 0; j < 4; j++) {
        float4 gg = ((const float4*)g)[lane + 32 * j];
        float4 bb = ((const float4*)b)[lane + 32 * j];
        half2 h0 = __floats2half2_rn((v[j].x - mu) * inv * gg.x + bb.x,
                                     (v[j].y - mu) * inv * gg.y + bb.y);
        half2 h1 = __floats2half2_rn((v[j].z - mu) * inv * gg.z + bb.z,
                                     (v[j].w - mu) * inv * gg.w + bb.w);
        uint2 o2 = make_uint2(*(uint32_t*)&h0, *(uint32_t*)&h1);
        *(uint2*)(y + (size_t)row * EMB + (lane + 32 * j) * 4) = o2;
    }
}

// ---------------- weight transpose ------------------------------------------------
__global__ void wt_kernel(const float* __restrict__ Wq,
                          const float* __restrict__ Wk,
                          const float* __restrict__ Wv,
                          const float* __restrict__ Wo,
                          __half* __restrict__ Wt) {
    __shared__ float tile[32][33];
    int z = blockIdx.z;
    const float* W = (z == 0) ? Wq : (z == 1) ? Wk : (z == 2) ? Wv : Wo;
    __half* dst = Wt + (size_t)z * EMB * EMB;
    int bx = blockIdx.x * 32, by = blockIdx.y * 32;
    int tx = threadIdx.x, ty = threadIdx.y;
    #pragma unroll
    for (int i = 0; i < 4; i++)
        tile[ty + i * 8][tx] = W[(size_t)(by + ty + i * 8) * EMB + bx + tx];
    __syncthreads();
    #pragma unroll
    for (int i = 0; i < 4; i++)
        dst[(size_t)(bx + ty + i * 8) * EMB + by + tx] =
            __float2half_rn(tile[tx][ty + i * 8]);
}

// ---------------- launch ----------------------------------------------------------
extern "C" void kernel_launch(void* const* d_in, const int* in_sizes, int n_in,
                              void* d_out, int out_size) {
    const float* query     = (const float*)d_in[0];
    const float* key_value = (const float*)d_in[1];
    const void*  kvm_raw   = d_in[2];
    const void*  spm_raw   = d_in[3];
    const float* ln_q_g  = (const float*)d_in[4];
    const float* ln_q_b  = (const float*)d_in[5];
    const float* ln_kv_g = (const float*)d_in[6];
    const float* ln_kv_b = (const float*)d_in[7];
    const float* Wq = (const float*)d_in[8];
    const float* bq = (const float*)d_in[9];
    const float* Wk = (const float*)d_in[10];
    const float* bk = (const float*)d_in[11];
    const float* Wv = (const float*)d_in[12];
    const float* bv = (const float*)d_in[13];
    const float* Wo = (const float*)d_in[14];
    const float* bo = (const float*)d_in[15];
    float* out = (float*)d_out;

    void *p_qn, *p_kvn, *p_q, *p_k, *p_vt, *p_ctx, *p_wt, *p_mb;
    cudaGetSymbolAddress(&p_qn,  g_qn);
    cudaGetSymbolAddress(&p_kvn, g_kvn);
    cudaGetSymbolAddress(&p_q,   g_q);
    cudaGetSymbolAddress(&p_k,   g_k);
    cudaGetSymbolAddress(&p_vt,  g_vt);
    cudaGetSymbolAddress(&p_ctx, g_ctx);
    cudaGetSymbolAddress(&p_wt,  g_wt);
    cudaGetSymbolAddress(&p_mb,  g_mbits);

    cudaFuncSetAttribute(proj_qkv_kernel,
        cudaFuncAttributeMaxDynamicSharedMemorySize, GSMEM);
    cudaFuncSetAttribute(proj_o_kernel,
        cudaFuncAttributeMaxDynamicSharedMemorySize, GSMEM);
    cudaFuncSetAttribute(fattn_kernel,
        cudaFuncAttributeMaxDynamicSharedMemorySize, FATTN_SMEM);

    const bool fork = g_si.ok;
    cudaStream_t sm = fork ? g_si.s2 : (cudaStream_t)0;
    cudaStream_t sw = fork ? g_si.s3 : (cudaStream_t)0;

    if (fork) {
        cudaEventRecord(g_si.eFork, 0);
        cudaStreamWaitEvent(g_si.s2, g_si.eFork, 0);
        cudaStreamWaitEvent(g_si.s3, g_si.eFork, 0);
    }
    // mask branch (s2)
    detect_mask_kernel<<<1, 256, 0, sm>>>((const unsigned char*)kvm_raw,
                                          (const unsigned char*)spm_raw);
    compact_idx_kernel<<<BATCH, 256, 0, sm>>>(kvm_raw);
    if (fork) cudaEventRecord(g_si.eCompact, g_si.s2);
    mask_bits_kernel<<<BATCH * NQ, 256, 0, sm>>>(spm_raw);
    if (fork) cudaEventRecord(g_si.eMask, g_si.s2);

    // weight branch (s3)
    dim3 tb(32, 8), tg(16, 16, 4);
    wt_kernel<<<tg, tb, 0, sw>>>(Wq, Wk, Wv, Wo, (__half*)p_wt);
    if (fork) cudaEventRecord(g_si.eWt, g_si.s3);

    // main branch (default stream)
    dim3 lg(NTOK / 8, 2);
    lnorm_kernel<<<lg, 256>>>(query, key_value, ln_q_g, ln_q_b,
                              ln_kv_g, ln_kv_b,
                              (__half*)p_qn, (__half*)p_kvn);

    if (fork) {
        cudaStreamWaitEvent(0, g_si.eCompact, 0);   // proj needs kidx/nkt
        cudaStreamWaitEvent(0, g_si.eWt, 0);        // proj needs W^T
    }
    dim3 pg(EMB / 128, NTOK / 128, 3);
    proj_qkv_kernel<<<pg, 256, GSMEM>>>((const __half*)p_qn, (const __half*)p_kvn,
                                 (const __half*)p_wt, bq, bk, bv,
                                 (__half*)p_q, (__half*)p_k, (__half*)p_vt);

    if (fork) cudaStreamWaitEvent(0, g_si.eMask, 0);  // fattn needs mbits
    dim3 fg(NQ / 128, BHN);
    fattn_kernel<<<fg, 256, FATTN_SMEM>>>((const __half*)p_q, (const __half*)p_k,
                              (const __half*)p_vt,
                              (const unsigned long long*)p_mb,
                              (__half*)p_ctx);

    dim3 og(EMB / 128, NTOK / 128);
    proj_o_kernel<<<og, 256, GSMEM>>>((const __half*)p_ctx, (const __half*)p_wt,
                               bo, out);
}